// round 1
// baseline (speedup 1.0000x reference)
#include <cuda_runtime.h>
#include <math.h>

#define NROWS 8192
#define DIM   1024
#define THR   0.85f

// Scratch (allocation-free: __device__ globals)
__device__ float g_h[(size_t)NROWS * DIM];    // 32 MB
__device__ float g_enc[(size_t)NROWS * DIM];  // 32 MB

// ---------------------------------------------------------------------------
// Tiled fp32 GEMM: 128x128 block tile, BK=16, 256 threads, 8x8 per thread.
// BT=false: C[M,Nc] = A[M,K] @ B[K,Nc] (+bias per column)
// BT=true : C[M,Nc] = A[M,K] @ B[Nc,K]^T  (both operands row-major [rows,K])
// All dims assumed multiples of 128 (K multiple of 16). True here.
// ---------------------------------------------------------------------------
template <bool BT>
__global__ __launch_bounds__(256) void gemm128(const float* __restrict__ A,
                                               const float* __restrict__ B,
                                               const float* __restrict__ bias,
                                               float* __restrict__ C,
                                               int M, int Nc, int K) {
    __shared__ float As[16][128];
    __shared__ float Bs[16][128];

    const int tid = threadIdx.x;
    const int tx = tid & 15;        // 0..15 -> columns
    const int ty = tid >> 4;        // 0..15 -> rows
    const int rowBase = blockIdx.y * 128;
    const int colBase = blockIdx.x * 128;

    // Loader mapping for transposed-store tiles (A always; B when BT)
    const int lrow = tid >> 2;          // 0..63
    const int lcol = (tid & 3) * 4;     // 0,4,8,12

    float acc[8][8];
#pragma unroll
    for (int i = 0; i < 8; i++)
#pragma unroll
        for (int j = 0; j < 8; j++) acc[i][j] = 0.f;

    for (int k0 = 0; k0 < K; k0 += 16) {
        // --- load A tile (transposed into As[k][row]) ---
        float4 a0 = *(const float4*)&A[(size_t)(rowBase + lrow) * K + k0 + lcol];
        float4 a1 = *(const float4*)&A[(size_t)(rowBase + lrow + 64) * K + k0 + lcol];
        As[lcol + 0][lrow] = a0.x; As[lcol + 1][lrow] = a0.y;
        As[lcol + 2][lrow] = a0.z; As[lcol + 3][lrow] = a0.w;
        As[lcol + 0][lrow + 64] = a1.x; As[lcol + 1][lrow + 64] = a1.y;
        As[lcol + 2][lrow + 64] = a1.z; As[lcol + 3][lrow + 64] = a1.w;

        if (BT) {
            // B rows are "columns" of C: load like A, transposed store
            float4 b0 = *(const float4*)&B[(size_t)(colBase + lrow) * K + k0 + lcol];
            float4 b1 = *(const float4*)&B[(size_t)(colBase + lrow + 64) * K + k0 + lcol];
            Bs[lcol + 0][lrow] = b0.x; Bs[lcol + 1][lrow] = b0.y;
            Bs[lcol + 2][lrow] = b0.z; Bs[lcol + 3][lrow] = b0.w;
            Bs[lcol + 0][lrow + 64] = b1.x; Bs[lcol + 1][lrow + 64] = b1.y;
            Bs[lcol + 2][lrow + 64] = b1.z; Bs[lcol + 3][lrow + 64] = b1.w;
        } else {
            // B is [K, Nc]: natural layout, vector store
            const int brow = tid >> 5;          // 0..7
            const int bcol = (tid & 31) * 4;    // 0..124
            float4 b0 = *(const float4*)&B[(size_t)(k0 + brow) * Nc + colBase + bcol];
            float4 b1 = *(const float4*)&B[(size_t)(k0 + brow + 8) * Nc + colBase + bcol];
            *(float4*)&Bs[brow][bcol] = b0;
            *(float4*)&Bs[brow + 8][bcol] = b1;
        }
        __syncthreads();

#pragma unroll
        for (int k = 0; k < 16; k++) {
            float a[8], b[8];
            *(float4*)&a[0] = *(const float4*)&As[k][ty * 4];
            *(float4*)&a[4] = *(const float4*)&As[k][64 + ty * 4];
            *(float4*)&b[0] = *(const float4*)&Bs[k][tx * 4];
            *(float4*)&b[4] = *(const float4*)&Bs[k][64 + tx * 4];
#pragma unroll
            for (int i = 0; i < 8; i++)
#pragma unroll
                for (int j = 0; j < 8; j++) acc[i][j] += a[i] * b[j];
        }
        __syncthreads();
    }

    // --- epilogue: coalesced float4 stores (+ optional bias) ---
#pragma unroll
    for (int i = 0; i < 8; i++) {
        const int r = rowBase + ((i < 4) ? (ty * 4 + i) : (64 + ty * 4 + i - 4));
#pragma unroll
        for (int jv = 0; jv < 2; jv++) {
            const int c = colBase + ((jv == 0) ? (tx * 4) : (64 + tx * 4));
            float4 v;
            v.x = acc[i][jv * 4 + 0];
            v.y = acc[i][jv * 4 + 1];
            v.z = acc[i][jv * 4 + 2];
            v.w = acc[i][jv * 4 + 3];
            if (bias) {
                v.x += bias[c + 0]; v.y += bias[c + 1];
                v.z += bias[c + 2]; v.w += bias[c + 3];
            }
            *(float4*)&C[(size_t)r * Nc + c] = v;
        }
    }
}

// ---------------------------------------------------------------------------
// LayerNorm + exact GELU, one block per row (DIM=1024, 256 threads x 4 elems)
// ---------------------------------------------------------------------------
__global__ __launch_bounds__(256) void ln_gelu_kernel(float* __restrict__ h,
                                                      const float* __restrict__ gamma,
                                                      const float* __restrict__ beta) {
    const int row = blockIdx.x;
    float* p = h + (size_t)row * DIM;
    const int t = threadIdx.x;

    float4 x = *(const float4*)&p[t * 4];
    float s1 = x.x + x.y + x.z + x.w;
    float s2 = x.x * x.x + x.y * x.y + x.z * x.z + x.w * x.w;

    // warp reduce
#pragma unroll
    for (int o = 16; o > 0; o >>= 1) {
        s1 += __shfl_xor_sync(0xffffffffu, s1, o);
        s2 += __shfl_xor_sync(0xffffffffu, s2, o);
    }
    __shared__ float r1[8], r2[8];
    if ((t & 31) == 0) { r1[t >> 5] = s1; r2[t >> 5] = s2; }
    __syncthreads();
    if (t < 8) { s1 = r1[t]; s2 = r2[t]; }
    else { s1 = 0.f; s2 = 0.f; }
    if (t < 32) {
#pragma unroll
        for (int o = 4; o > 0; o >>= 1) {
            s1 += __shfl_xor_sync(0xffffffffu, s1, o);
            s2 += __shfl_xor_sync(0xffffffffu, s2, o);
        }
        if (t == 0) { r1[0] = s1; r2[0] = s2; }
    }
    __syncthreads();
    const float mu = r1[0] * (1.f / DIM);
    const float var = r2[0] * (1.f / DIM) - mu * mu;
    const float rstd = rsqrtf(var + 1e-5f);

    const float4 g = *(const float4*)&gamma[t * 4];
    const float4 b = *(const float4*)&beta[t * 4];
    float y[4] = { (x.x - mu) * rstd * g.x + b.x,
                   (x.y - mu) * rstd * g.y + b.y,
                   (x.z - mu) * rstd * g.z + b.z,
                   (x.w - mu) * rstd * g.w + b.w };
    float4 o;
    o.x = 0.5f * y[0] * (1.f + erff(y[0] * 0.70710678118654752f));
    o.y = 0.5f * y[1] * (1.f + erff(y[1] * 0.70710678118654752f));
    o.z = 0.5f * y[2] * (1.f + erff(y[2] * 0.70710678118654752f));
    o.w = 0.5f * y[3] * (1.f + erff(y[3] * 0.70710678118654752f));
    *(float4*)&p[t * 4] = o;
}

// ---------------------------------------------------------------------------
// Row L2 normalize (one block per row)
// ---------------------------------------------------------------------------
__global__ __launch_bounds__(256) void l2norm_kernel(float* __restrict__ e) {
    const int row = blockIdx.x;
    float* p = e + (size_t)row * DIM;
    const int t = threadIdx.x;

    float4 x = *(const float4*)&p[t * 4];
    float s2 = x.x * x.x + x.y * x.y + x.z * x.z + x.w * x.w;
#pragma unroll
    for (int o = 16; o > 0; o >>= 1) s2 += __shfl_xor_sync(0xffffffffu, s2, o);
    __shared__ float r2[8];
    if ((t & 31) == 0) r2[t >> 5] = s2;
    __syncthreads();
    if (t < 32) {
        s2 = (t < 8) ? r2[t] : 0.f;
#pragma unroll
        for (int o = 4; o > 0; o >>= 1) s2 += __shfl_xor_sync(0xffffffffu, s2, o);
        if (t == 0) r2[0] = s2;
    }
    __syncthreads();
    const float nrm = sqrtf(r2[0]);
    const float inv = 1.f / fmaxf(nrm, 1e-12f);
    x.x *= inv; x.y *= inv; x.z *= inv; x.w *= inv;
    *(float4*)&p[t * 4] = x;
}

// ---------------------------------------------------------------------------
// is_duplicate[j] = any_{i<j} sim[i][j] > THR.
// sim is bitwise symmetric (identical k-order in both tiles), so read row j
// coalesced: any_{i<j} sim[j][i] > THR.
// ---------------------------------------------------------------------------
__global__ __launch_bounds__(256) void dup_kernel(const float* __restrict__ sim,
                                                  float* __restrict__ out) {
    const int j = blockIdx.x;
    const float* row = sim + (size_t)j * NROWS;
    int found = 0;
    for (int i = threadIdx.x; i < j; i += blockDim.x) {
        if (row[i] > THR) { found = 1; break; }
    }
    found = __syncthreads_or(found);
    if (threadIdx.x == 0) out[j] = found ? 1.0f : 0.0f;
}

// ---------------------------------------------------------------------------
extern "C" void kernel_launch(void* const* d_in, const int* in_sizes, int n_in,
                              void* d_out, int out_size) {
    const float* S     = (const float*)d_in[0];  // summaries [N, D]
    const float* W1    = (const float*)d_in[1];  // [D, D]
    const float* b1    = (const float*)d_in[2];  // [D]
    const float* gamma = (const float*)d_in[3];  // [D]
    const float* beta  = (const float*)d_in[4];  // [D]
    const float* W2    = (const float*)d_in[5];  // [D, D]
    const float* b2    = (const float*)d_in[6];  // [D]
    float* out = (float*)d_out;

    float *h, *enc;
    cudaGetSymbolAddress((void**)&h, g_h);
    cudaGetSymbolAddress((void**)&enc, g_enc);

    // 1) h = S @ W1 + b1
    gemm128<false><<<dim3(DIM / 128, NROWS / 128), 256>>>(S, W1, b1, h, NROWS, DIM, DIM);
    // 2) LayerNorm + GELU (in place)
    ln_gelu_kernel<<<NROWS, 256>>>(h, gamma, beta);
    // 3) enc = h @ W2 + b2
    gemm128<false><<<dim3(DIM / 128, NROWS / 128), 256>>>(h, W2, b2, enc, NROWS, DIM, DIM);
    // 4) L2 normalize rows (in place)
    l2norm_kernel<<<NROWS, 256>>>(enc);
    // 5) sim = enc @ enc^T -> d_out[0 : N*N)
    gemm128<true><<<dim3(NROWS / 128, NROWS / 128), 256>>>(enc, enc, nullptr, out,
                                                           NROWS, NROWS, DIM);
    // 6) is_duplicate -> d_out[N*N : N*N+N) as 0.0/1.0 (if the harness expects it)
    if (out_size >= NROWS * NROWS + NROWS) {
        dup_kernel<<<NROWS, 256>>>(out, out + (size_t)NROWS * NROWS);
    }
}

// round 3
// speedup vs baseline: 2.2025x; 2.2025x over previous
#include <cuda_runtime.h>
#include <cuda_bf16.h>
#include <math.h>
#include <stdint.h>

#define NROWS 8192
#define DIM   1024
#define THR   0.85f

// Scratch (allocation-free: __device__ globals)
__device__ float g_h[(size_t)NROWS * DIM];              // 32 MB
__device__ float g_enc[(size_t)NROWS * DIM];            // 32 MB
__device__ __nv_bfloat16 g_hi[(size_t)NROWS * DIM];     // 16 MB
__device__ __nv_bfloat16 g_lo[(size_t)NROWS * DIM];     // 16 MB

// ===========================================================================
// sm_80-generic PTX helpers (NO tcgen05 — harness compiles for base sm_103)
// ===========================================================================
__device__ __forceinline__ uint32_t smem_u32(const void* p) {
    uint32_t a;
    asm("{ .reg .u64 t; cvta.to.shared.u64 t, %1; cvt.u32.u64 %0, t; }"
        : "=r"(a) : "l"(p));
    return a;
}
__device__ __forceinline__ void cp16(uint32_t dst, const void* src) {
    asm volatile("cp.async.cg.shared.global [%0], [%1], 16;"
                 :: "r"(dst), "l"(src));
}
__device__ __forceinline__ void ldsm_x4(uint32_t* r, uint32_t addr) {
    asm volatile("ldmatrix.sync.aligned.m8n8.x4.shared.b16 {%0,%1,%2,%3}, [%4];"
                 : "=r"(r[0]), "=r"(r[1]), "=r"(r[2]), "=r"(r[3]) : "r"(addr));
}
__device__ __forceinline__ void ldsm_x2(uint32_t* r, uint32_t addr) {
    asm volatile("ldmatrix.sync.aligned.m8n8.x2.shared.b16 {%0,%1}, [%2];"
                 : "=r"(r[0]), "=r"(r[1]) : "r"(addr));
}
__device__ __forceinline__ void mma16816(float* c, const uint32_t* a,
                                         const uint32_t* b) {
    asm volatile("mma.sync.aligned.m16n8k16.row.col.f32.bf16.bf16.f32 "
                 "{%0,%1,%2,%3}, {%4,%5,%6,%7}, {%8,%9}, {%0,%1,%2,%3};"
                 : "+f"(c[0]), "+f"(c[1]), "+f"(c[2]), "+f"(c[3])
                 : "r"(a[0]), "r"(a[1]), "r"(a[2]), "r"(a[3]),
                   "r"(b[0]), "r"(b[1]));
}

// smem tile: 128 rows x 64B (32 bf16). 16B chunk swizzle — conflict-free for
// LDSM phases (any 8 consecutive rows hit all 8 bank-groups).
__device__ __forceinline__ uint32_t swz(uint32_t row, uint32_t chunk) {
    uint32_t c = chunk ^ (row & 3u) ^ ((row >> 2) & 1u);
    return row * 64u + c * 16u;
}

// ===========================================================================
// sim = enc @ enc^T, lower-triangular 128x128 tiles only, bf16 hi/lo 3-pass.
// 256 threads = 8 warps (2m x 4n), warp tile 64x32, BK=32, double-buffered
// cp.async. SMEM/stage: Ahi,Alo,Bhi,Blo @ 8KB = 32KB; 2 stages = 64KB.
// ===========================================================================
__global__ __launch_bounds__(256) void sim_mma_kernel(
    const __nv_bfloat16* __restrict__ hi,
    const __nv_bfloat16* __restrict__ lo,
    float* __restrict__ out) {
    extern __shared__ char sm[];
    const uint32_t sb = smem_u32(sm);

    // block -> lower-tri (bi, bj), bi >= bj
    const int b = blockIdx.x;
    int bi = (int)((sqrtf(8.f * b + 1.f) - 1.f) * 0.5f);
    while ((bi + 1) * (bi + 2) / 2 <= b) bi++;
    while (bi * (bi + 1) / 2 > b) bi--;
    const int bj = b - bi * (bi + 1) / 2;
    const int rowBase = bi * 128;
    const int colBase = bj * 128;

    const int tid = threadIdx.x;
    const int wid = tid >> 5;
    const int lane = tid & 31;
    const int wm = (wid & 1) * 64;   // warp m offset
    const int wn = (wid >> 1) * 32;  // warp n offset

    const char* gAh = (const char*)hi + (size_t)rowBase * 2048;
    const char* gAl = (const char*)lo + (size_t)rowBase * 2048;
    const char* gBh = (const char*)hi + (size_t)colBase * 2048;
    const char* gBl = (const char*)lo + (size_t)colBase * 2048;

    // stage loader: 4 tiles x 512 chunks(16B); 2 chunks/thread/tile
    auto load_stage = [&](int st, int kc) {
        const char* bases[4] = {gAh, gAl, gBh, gBl};
#pragma unroll
        for (int t = 0; t < 4; t++) {
#pragma unroll
            for (int h = 0; h < 2; h++) {
                const int c = tid + h * 256;
                const uint32_t row = c >> 2, kch = c & 3;
                const uint32_t dst = sb + st * 32768u + t * 8192u + swz(row, kch);
                cp16(dst, bases[t] + (size_t)row * 2048 + (size_t)kc * 64 + kch * 16);
            }
        }
    };

    float acc[4][4][4];
#pragma unroll
    for (int i = 0; i < 4; i++)
#pragma unroll
        for (int j = 0; j < 4; j++)
#pragma unroll
            for (int k = 0; k < 4; k++) acc[i][j][k] = 0.f;

    load_stage(0, 0);
    asm volatile("cp.async.commit_group;");
    load_stage(1, 1);
    asm volatile("cp.async.commit_group;");

    for (int kc = 0; kc < 32; kc++) {
        asm volatile("cp.async.wait_group 1;");
        __syncthreads();
        const int st = kc & 1;
        const uint32_t uAh = sb + st * 32768u;
        const uint32_t uAl = uAh + 8192u;
        const uint32_t uBh = uAh + 16384u;
        const uint32_t uBl = uAh + 24576u;

        uint32_t ah[4][4], al[4][4], bh[4][2], bl[4][2];

        // ---- ks = 0: load frags, mma ----
#pragma unroll
        for (int mt = 0; mt < 4; mt++) {
            const uint32_t row = wm + mt * 16 + (lane & 15);
            const uint32_t ch = (uint32_t)(lane >> 4);
            ldsm_x4(ah[mt], uAh + swz(row, ch));
            ldsm_x4(al[mt], uAl + swz(row, ch));
        }
#pragma unroll
        for (int nt = 0; nt < 4; nt++) {
            const uint32_t row = wn + nt * 8 + (lane & 7);
            const uint32_t ch = (uint32_t)((lane >> 3) & 1);
            ldsm_x2(bh[nt], uBh + swz(row, ch));
            ldsm_x2(bl[nt], uBl + swz(row, ch));
        }
#pragma unroll
        for (int mt = 0; mt < 4; mt++)
#pragma unroll
            for (int nt = 0; nt < 4; nt++) {
                mma16816(acc[mt][nt], ah[mt], bh[nt]);
                mma16816(acc[mt][nt], ah[mt], bl[nt]);
                mma16816(acc[mt][nt], al[mt], bh[nt]);
            }

        // ---- ks = 1: load frags (smem reads done after this) ----
#pragma unroll
        for (int mt = 0; mt < 4; mt++) {
            const uint32_t row = wm + mt * 16 + (lane & 15);
            const uint32_t ch = 2u + (uint32_t)(lane >> 4);
            ldsm_x4(ah[mt], uAh + swz(row, ch));
            ldsm_x4(al[mt], uAl + swz(row, ch));
        }
#pragma unroll
        for (int nt = 0; nt < 4; nt++) {
            const uint32_t row = wn + nt * 8 + (lane & 7);
            const uint32_t ch = 2u + (uint32_t)((lane >> 3) & 1);
            ldsm_x2(bh[nt], uBh + swz(row, ch));
            ldsm_x2(bl[nt], uBl + swz(row, ch));
        }
        __syncthreads();  // all smem reads of stage st complete
        if (kc + 2 < 32) load_stage(st, kc + 2);
        asm volatile("cp.async.commit_group;");

#pragma unroll
        for (int mt = 0; mt < 4; mt++)
#pragma unroll
            for (int nt = 0; nt < 4; nt++) {
                mma16816(acc[mt][nt], ah[mt], bh[nt]);
                mma16816(acc[mt][nt], ah[mt], bl[nt]);
                mma16816(acc[mt][nt], al[mt], bh[nt]);
            }
    }

    // epilogue: fragment -> global (float2 stores)
    const int g = lane >> 2, tg = lane & 3;
#pragma unroll
    for (int mt = 0; mt < 4; mt++)
#pragma unroll
        for (int nt = 0; nt < 4; nt++) {
            const int r0 = rowBase + wm + mt * 16 + g;
            const int c0 = colBase + wn + nt * 8 + tg * 2;
            float2 v0, v1;
            v0.x = acc[mt][nt][0]; v0.y = acc[mt][nt][1];
            v1.x = acc[mt][nt][2]; v1.y = acc[mt][nt][3];
            *(float2*)&out[(size_t)r0 * NROWS + c0] = v0;
            *(float2*)&out[(size_t)(r0 + 8) * NROWS + c0] = v1;
        }
}

// ===========================================================================
// Mirror strict-lower 32x32 tiles to upper: out[tj,ti] = out[ti,tj]^T
// ===========================================================================
__global__ __launch_bounds__(256) void mirror_kernel(float* __restrict__ out) {
    const long b = blockIdx.x;
    int ti = (int)((sqrt(8.0 * (double)b + 1.0) + 1.0) * 0.5);
    while ((long)ti * (ti - 1) / 2 > b) ti--;
    while ((long)(ti + 1) * ti / 2 <= b) ti++;
    const int tj = (int)(b - (long)ti * (ti - 1) / 2);

    __shared__ float t[32][33];
    const int x = threadIdx.x;     // 0..31
    const int y0 = threadIdx.y;    // 0..7
    const float* src = out + (size_t)(ti * 32) * NROWS + tj * 32;
#pragma unroll
    for (int yy = y0; yy < 32; yy += 8) t[yy][x] = src[(size_t)yy * NROWS + x];
    __syncthreads();
    float* dst = out + (size_t)(tj * 32) * NROWS + ti * 32;
#pragma unroll
    for (int yy = y0; yy < 32; yy += 8) dst[(size_t)yy * NROWS + x] = t[x][yy];
}

// ===========================================================================
// fp32 SIMT GEMM for the two encoder GEMMs (128x128, BK=16)
// ===========================================================================
__global__ __launch_bounds__(256) void gemm128(const float* __restrict__ A,
                                               const float* __restrict__ B,
                                               const float* __restrict__ bias,
                                               float* __restrict__ C,
                                               int M, int Nc, int K) {
    __shared__ float As[16][128];
    __shared__ float Bs[16][128];

    const int tid = threadIdx.x;
    const int tx = tid & 15;
    const int ty = tid >> 4;
    const int rowBase = blockIdx.y * 128;
    const int colBase = blockIdx.x * 128;
    const int lrow = tid >> 2;
    const int lcol = (tid & 3) * 4;

    float acc[8][8];
#pragma unroll
    for (int i = 0; i < 8; i++)
#pragma unroll
        for (int j = 0; j < 8; j++) acc[i][j] = 0.f;

    for (int k0 = 0; k0 < K; k0 += 16) {
        float4 a0 = *(const float4*)&A[(size_t)(rowBase + lrow) * K + k0 + lcol];
        float4 a1 = *(const float4*)&A[(size_t)(rowBase + lrow + 64) * K + k0 + lcol];
        As[lcol + 0][lrow] = a0.x; As[lcol + 1][lrow] = a0.y;
        As[lcol + 2][lrow] = a0.z; As[lcol + 3][lrow] = a0.w;
        As[lcol + 0][lrow + 64] = a1.x; As[lcol + 1][lrow + 64] = a1.y;
        As[lcol + 2][lrow + 64] = a1.z; As[lcol + 3][lrow + 64] = a1.w;

        const int brow = tid >> 5;
        const int bcol = (tid & 31) * 4;
        float4 b0 = *(const float4*)&B[(size_t)(k0 + brow) * Nc + colBase + bcol];
        float4 b1 = *(const float4*)&B[(size_t)(k0 + brow + 8) * Nc + colBase + bcol];
        *(float4*)&Bs[brow][bcol] = b0;
        *(float4*)&Bs[brow + 8][bcol] = b1;
        __syncthreads();

#pragma unroll
        for (int k = 0; k < 16; k++) {
            float a[8], bb[8];
            *(float4*)&a[0] = *(const float4*)&As[k][ty * 4];
            *(float4*)&a[4] = *(const float4*)&As[k][64 + ty * 4];
            *(float4*)&bb[0] = *(const float4*)&Bs[k][tx * 4];
            *(float4*)&bb[4] = *(const float4*)&Bs[k][64 + tx * 4];
#pragma unroll
            for (int i = 0; i < 8; i++)
#pragma unroll
                for (int j = 0; j < 8; j++) acc[i][j] += a[i] * bb[j];
        }
        __syncthreads();
    }

#pragma unroll
    for (int i = 0; i < 8; i++) {
        const int r = rowBase + ((i < 4) ? (ty * 4 + i) : (64 + ty * 4 + i - 4));
#pragma unroll
        for (int jv = 0; jv < 2; jv++) {
            const int c = colBase + ((jv == 0) ? (tx * 4) : (64 + tx * 4));
            float4 v;
            v.x = acc[i][jv * 4 + 0];
            v.y = acc[i][jv * 4 + 1];
            v.z = acc[i][jv * 4 + 2];
            v.w = acc[i][jv * 4 + 3];
            if (bias) {
                v.x += bias[c + 0]; v.y += bias[c + 1];
                v.z += bias[c + 2]; v.w += bias[c + 3];
            }
            *(float4*)&C[(size_t)r * Nc + c] = v;
        }
    }
}

// ===========================================================================
// LayerNorm + exact GELU (one block per row)
// ===========================================================================
__global__ __launch_bounds__(256) void ln_gelu_kernel(float* __restrict__ h,
                                                      const float* __restrict__ gamma,
                                                      const float* __restrict__ beta) {
    const int row = blockIdx.x;
    float* p = h + (size_t)row * DIM;
    const int t = threadIdx.x;

    float4 x = *(const float4*)&p[t * 4];
    float s1 = x.x + x.y + x.z + x.w;
    float s2 = x.x * x.x + x.y * x.y + x.z * x.z + x.w * x.w;
#pragma unroll
    for (int o = 16; o > 0; o >>= 1) {
        s1 += __shfl_xor_sync(0xffffffffu, s1, o);
        s2 += __shfl_xor_sync(0xffffffffu, s2, o);
    }
    __shared__ float r1[8], r2[8];
    if ((t & 31) == 0) { r1[t >> 5] = s1; r2[t >> 5] = s2; }
    __syncthreads();
    if (t < 32) {
        s1 = (t < 8) ? r1[t] : 0.f;
        s2 = (t < 8) ? r2[t] : 0.f;
#pragma unroll
        for (int o = 4; o > 0; o >>= 1) {
            s1 += __shfl_xor_sync(0xffffffffu, s1, o);
            s2 += __shfl_xor_sync(0xffffffffu, s2, o);
        }
        if (t == 0) { r1[0] = s1; r2[0] = s2; }
    }
    __syncthreads();
    const float mu = r1[0] * (1.f / DIM);
    const float var = r2[0] * (1.f / DIM) - mu * mu;
    const float rstd = rsqrtf(var + 1e-5f);

    const float4 g = *(const float4*)&gamma[t * 4];
    const float4 bb = *(const float4*)&beta[t * 4];
    float y[4] = { (x.x - mu) * rstd * g.x + bb.x,
                   (x.y - mu) * rstd * g.y + bb.y,
                   (x.z - mu) * rstd * g.z + bb.z,
                   (x.w - mu) * rstd * g.w + bb.w };
    float4 o;
    o.x = 0.5f * y[0] * (1.f + erff(y[0] * 0.70710678118654752f));
    o.y = 0.5f * y[1] * (1.f + erff(y[1] * 0.70710678118654752f));
    o.z = 0.5f * y[2] * (1.f + erff(y[2] * 0.70710678118654752f));
    o.w = 0.5f * y[3] * (1.f + erff(y[3] * 0.70710678118654752f));
    *(float4*)&p[t * 4] = o;
}

// ===========================================================================
// Row L2 normalize + bf16 hi/lo split fused (one block per row)
// ===========================================================================
__global__ __launch_bounds__(256) void l2norm_split_kernel(
    const float* __restrict__ e,
    __nv_bfloat16* __restrict__ hi,
    __nv_bfloat16* __restrict__ lo) {
    const int row = blockIdx.x;
    const float* p = e + (size_t)row * DIM;
    const int t = threadIdx.x;

    float4 x = *(const float4*)&p[t * 4];
    float s2 = x.x * x.x + x.y * x.y + x.z * x.z + x.w * x.w;
#pragma unroll
    for (int o = 16; o > 0; o >>= 1) s2 += __shfl_xor_sync(0xffffffffu, s2, o);
    __shared__ float r2[8];
    if ((t & 31) == 0) r2[t >> 5] = s2;
    __syncthreads();
    if (t < 32) {
        s2 = (t < 8) ? r2[t] : 0.f;
#pragma unroll
        for (int o = 4; o > 0; o >>= 1) s2 += __shfl_xor_sync(0xffffffffu, s2, o);
        if (t == 0) r2[0] = s2;
    }
    __syncthreads();
    const float inv = 1.f / fmaxf(sqrtf(r2[0]), 1e-12f);
    float v[4] = { x.x * inv, x.y * inv, x.z * inv, x.w * inv };

    __nv_bfloat16 hh[4], ll[4];
#pragma unroll
    for (int i = 0; i < 4; i++) {
        hh[i] = __float2bfloat16(v[i]);
        ll[i] = __float2bfloat16(v[i] - __bfloat162float(hh[i]));
    }
    const size_t idx = (size_t)row * (DIM / 4) + t;
    uint2 hv, lv;
    __nv_bfloat162 hp0, hp1, lp0, lp1;
    hp0.x = hh[0]; hp0.y = hh[1]; hp1.x = hh[2]; hp1.y = hh[3];
    lp0.x = ll[0]; lp0.y = ll[1]; lp1.x = ll[2]; lp1.y = ll[3];
    hv.x = *(uint32_t*)&hp0; hv.y = *(uint32_t*)&hp1;
    lv.x = *(uint32_t*)&lp0; lv.y = *(uint32_t*)&lp1;
    ((uint2*)hi)[idx] = hv;
    ((uint2*)lo)[idx] = lv;
}

// ===========================================================================
// is_duplicate[j] = any_{i<j} sim[j][i] > THR (row read via symmetry)
// ===========================================================================
__global__ __launch_bounds__(256) void dup_kernel(const float* __restrict__ sim,
                                                  float* __restrict__ out) {
    const int j = blockIdx.x;
    const float* row = sim + (size_t)j * NROWS;
    int found = 0;
    for (int i = threadIdx.x; i < j; i += blockDim.x) {
        if (row[i] > THR) { found = 1; break; }
    }
    found = __syncthreads_or(found);
    if (threadIdx.x == 0) out[j] = found ? 1.0f : 0.0f;
}

// ===========================================================================
extern "C" void kernel_launch(void* const* d_in, const int* in_sizes, int n_in,
                              void* d_out, int out_size) {
    const float* S     = (const float*)d_in[0];
    const float* W1    = (const float*)d_in[1];
    const float* b1    = (const float*)d_in[2];
    const float* gamma = (const float*)d_in[3];
    const float* beta  = (const float*)d_in[4];
    const float* W2    = (const float*)d_in[5];
    const float* b2    = (const float*)d_in[6];
    float* out = (float*)d_out;

    float *h, *enc;
    __nv_bfloat16 *hi, *lo;
    cudaGetSymbolAddress((void**)&h, g_h);
    cudaGetSymbolAddress((void**)&enc, g_enc);
    cudaGetSymbolAddress((void**)&hi, g_hi);
    cudaGetSymbolAddress((void**)&lo, g_lo);

    const int SIM_SMEM = 2 * 32768;  // 64 KB dynamic
    cudaFuncSetAttribute(sim_mma_kernel, cudaFuncAttributeMaxDynamicSharedMemorySize,
                         SIM_SMEM);

    // 1) h = S @ W1 + b1
    gemm128<<<dim3(DIM / 128, NROWS / 128), 256>>>(S, W1, b1, h, NROWS, DIM, DIM);
    // 2) LayerNorm + GELU
    ln_gelu_kernel<<<NROWS, 256>>>(h, gamma, beta);
    // 3) enc = h @ W2 + b2
    gemm128<<<dim3(DIM / 128, NROWS / 128), 256>>>(h, W2, b2, enc, NROWS, DIM, DIM);
    // 4) L2 normalize + bf16 hi/lo split (fused)
    l2norm_split_kernel<<<NROWS, 256>>>(enc, hi, lo);
    // 5) sim lower-triangular tiles via mma.sync bf16 3-pass
    const int NT = NROWS / 128;                 // 64
    sim_mma_kernel<<<NT * (NT + 1) / 2, 256, SIM_SMEM>>>(hi, lo, out);
    // 6) mirror strict-lower 32x32 tiles to upper
    const int T32 = NROWS / 32;                 // 256
    mirror_kernel<<<T32 * (T32 - 1) / 2, dim3(32, 8)>>>(out);
    // 7) is_duplicate
    if (out_size >= NROWS * NROWS + NROWS) {
        dup_kernel<<<NROWS, 256>>>(out, out + (size_t)NROWS * NROWS);
    }
}

// round 4
// speedup vs baseline: 3.3454x; 1.5189x over previous
#include <cuda_runtime.h>
#include <cuda_bf16.h>
#include <math.h>
#include <stdint.h>

#define NROWS 8192
#define DIM   1024
#define THR   0.85f

// Scratch (allocation-free: __device__ globals)
__device__ float g_h[(size_t)NROWS * DIM];              // 32 MB
__device__ float g_enc[(size_t)NROWS * DIM];            // 32 MB
__device__ __nv_bfloat16 g_hi[(size_t)NROWS * DIM];     // 16 MB
__device__ __nv_bfloat16 g_lo[(size_t)NROWS * DIM];     // 16 MB
__device__ __nv_bfloat16 g_wt_hi[(size_t)DIM * DIM];    // 2 MB
__device__ __nv_bfloat16 g_wt_lo[(size_t)DIM * DIM];    // 2 MB

// ===========================================================================
// sm_80-generic PTX helpers (base sm_103 target: no tcgen05)
// ===========================================================================
__device__ __forceinline__ uint32_t smem_u32(const void* p) {
    uint32_t a;
    asm("{ .reg .u64 t; cvta.to.shared.u64 t, %1; cvt.u32.u64 %0, t; }"
        : "=r"(a) : "l"(p));
    return a;
}
__device__ __forceinline__ void cp16(uint32_t dst, const void* src) {
    asm volatile("cp.async.cg.shared.global [%0], [%1], 16;"
                 :: "r"(dst), "l"(src));
}
__device__ __forceinline__ void ldsm_x4(uint32_t* r, uint32_t addr) {
    asm volatile("ldmatrix.sync.aligned.m8n8.x4.shared.b16 {%0,%1,%2,%3}, [%4];"
                 : "=r"(r[0]), "=r"(r[1]), "=r"(r[2]), "=r"(r[3]) : "r"(addr));
}
__device__ __forceinline__ void mma16816(float* c, const uint32_t* a,
                                         const uint32_t* b) {
    asm volatile("mma.sync.aligned.m16n8k16.row.col.f32.bf16.bf16.f32 "
                 "{%0,%1,%2,%3}, {%4,%5,%6,%7}, {%8,%9}, {%0,%1,%2,%3};"
                 : "+f"(c[0]), "+f"(c[1]), "+f"(c[2]), "+f"(c[3])
                 : "r"(a[0]), "r"(a[1]), "r"(a[2]), "r"(a[3]),
                   "r"(b[0]), "r"(b[1]));
}

// smem tile: 128 rows x 64B (32 bf16). 16B-chunk swizzle, conflict-free LDSM.
__device__ __forceinline__ uint32_t swz(uint32_t row, uint32_t chunk) {
    uint32_t c = chunk ^ (row & 3u) ^ ((row >> 2) & 1u);
    return row * 64u + c * 16u;
}

// ===========================================================================
// Unified bf16 hi/lo 3-pass tensor-core GEMM.
//   C[m,n] (+bias[n]) = sum_k A[m,k]*B[n,k]   (both row-major, K contiguous)
// TRI=true : lower-triangular 128x128 tile grid over blockIdx.x (sim).
// TRI=false: rectangular grid (x = n tiles, y = m tiles) (encoder).
// 256 threads = 8 warps (2m x 4n), warp tile 64x32, BK=32, 2-stage cp.async.
// ===========================================================================
template <bool TRI>
__global__ __launch_bounds__(256) void gemm_tc(
    const __nv_bfloat16* __restrict__ Ah, const __nv_bfloat16* __restrict__ Al,
    const __nv_bfloat16* __restrict__ Bh, const __nv_bfloat16* __restrict__ Bl,
    float* __restrict__ C, int ldc, const float* __restrict__ bias, int K) {
    extern __shared__ char sm[];
    const uint32_t sb = smem_u32(sm);

    int rowBase, colBase;
    if (TRI) {
        const int b = blockIdx.x;
        int bi = (int)((sqrtf(8.f * b + 1.f) - 1.f) * 0.5f);
        while ((bi + 1) * (bi + 2) / 2 <= b) bi++;
        while (bi * (bi + 1) / 2 > b) bi--;
        rowBase = bi * 128;
        colBase = (b - bi * (bi + 1) / 2) * 128;
    } else {
        rowBase = blockIdx.y * 128;
        colBase = blockIdx.x * 128;
    }

    const int tid = threadIdx.x;
    const int wid = tid >> 5;
    const int lane = tid & 31;
    const int wm = (wid & 1) * 64;
    const int wn = (wid >> 1) * 32;

    const size_t rowB = (size_t)K * 2;  // bytes per row
    const char* gAh = (const char*)Ah + (size_t)rowBase * rowB;
    const char* gAl = (const char*)Al + (size_t)rowBase * rowB;
    const char* gBh = (const char*)Bh + (size_t)colBase * rowB;
    const char* gBl = (const char*)Bl + (size_t)colBase * rowB;

    auto load_stage = [&](int st, int kc) {
        const char* bases[4] = {gAh, gAl, gBh, gBl};
#pragma unroll
        for (int t = 0; t < 4; t++) {
#pragma unroll
            for (int h = 0; h < 2; h++) {
                const int c = tid + h * 256;
                const uint32_t row = c >> 2, kch = c & 3;
                const uint32_t dst = sb + st * 32768u + t * 8192u + swz(row, kch);
                cp16(dst, bases[t] + (size_t)row * rowB + (size_t)kc * 64 + kch * 16);
            }
        }
    };

    float acc[4][4][4];
#pragma unroll
    for (int i = 0; i < 4; i++)
#pragma unroll
        for (int j = 0; j < 4; j++)
#pragma unroll
            for (int k = 0; k < 4; k++) acc[i][j][k] = 0.f;

    load_stage(0, 0);
    asm volatile("cp.async.commit_group;");
    load_stage(1, 1);
    asm volatile("cp.async.commit_group;");

    const int kcN = K / 32;
    for (int kc = 0; kc < kcN; kc++) {
        asm volatile("cp.async.wait_group 1;");
        __syncthreads();
        const int st = kc & 1;
        const uint32_t uAh = sb + st * 32768u;
        const uint32_t uAl = uAh + 8192u;
        const uint32_t uBh = uAh + 16384u;
        const uint32_t uBl = uAh + 24576u;

        uint32_t ah[4][4], al[4][4], bh[4][2], bl[4][2];

        // A-frag addr pieces (ks-dependent chunk added below)
        const uint32_t arow0 = (uint32_t)(wm + (lane & 15));
        const uint32_t achb = (uint32_t)(lane >> 4);
        // B-frag x4 addr: two nt per ldsm
        const uint32_t brow0 = (uint32_t)(wn + (lane & 7) + ((lane & 16) >> 1));
        const uint32_t bchb = (uint32_t)((lane >> 3) & 1);

        // ---- ks = 0 ----
#pragma unroll
        for (int mt = 0; mt < 4; mt++) {
            ldsm_x4(ah[mt], uAh + swz(arow0 + mt * 16, achb));
            ldsm_x4(al[mt], uAl + swz(arow0 + mt * 16, achb));
        }
#pragma unroll
        for (int p = 0; p < 2; p++) {
            uint32_t r[4];
            ldsm_x4(r, uBh + swz(brow0 + p * 16, bchb));
            bh[p * 2][0] = r[0]; bh[p * 2][1] = r[1];
            bh[p * 2 + 1][0] = r[2]; bh[p * 2 + 1][1] = r[3];
            ldsm_x4(r, uBl + swz(brow0 + p * 16, bchb));
            bl[p * 2][0] = r[0]; bl[p * 2][1] = r[1];
            bl[p * 2 + 1][0] = r[2]; bl[p * 2 + 1][1] = r[3];
        }
#pragma unroll
        for (int mt = 0; mt < 4; mt++)
#pragma unroll
            for (int nt = 0; nt < 4; nt++) {
                mma16816(acc[mt][nt], ah[mt], bh[nt]);
                mma16816(acc[mt][nt], ah[mt], bl[nt]);
                mma16816(acc[mt][nt], al[mt], bh[nt]);
            }

        // ---- ks = 1 ----
#pragma unroll
        for (int mt = 0; mt < 4; mt++) {
            ldsm_x4(ah[mt], uAh + swz(arow0 + mt * 16, 2u + achb));
            ldsm_x4(al[mt], uAl + swz(arow0 + mt * 16, 2u + achb));
        }
#pragma unroll
        for (int p = 0; p < 2; p++) {
            uint32_t r[4];
            ldsm_x4(r, uBh + swz(brow0 + p * 16, 2u + bchb));
            bh[p * 2][0] = r[0]; bh[p * 2][1] = r[1];
            bh[p * 2 + 1][0] = r[2]; bh[p * 2 + 1][1] = r[3];
            ldsm_x4(r, uBl + swz(brow0 + p * 16, 2u + bchb));
            bl[p * 2][0] = r[0]; bl[p * 2][1] = r[1];
            bl[p * 2 + 1][0] = r[2]; bl[p * 2 + 1][1] = r[3];
        }
        __syncthreads();  // all smem reads of stage st done
        if (kc + 2 < kcN) load_stage(st, kc + 2);
        asm volatile("cp.async.commit_group;");

#pragma unroll
        for (int mt = 0; mt < 4; mt++)
#pragma unroll
            for (int nt = 0; nt < 4; nt++) {
                mma16816(acc[mt][nt], ah[mt], bh[nt]);
                mma16816(acc[mt][nt], ah[mt], bl[nt]);
                mma16816(acc[mt][nt], al[mt], bh[nt]);
            }
    }

    // epilogue
    const int g = lane >> 2, tg = lane & 3;
#pragma unroll
    for (int mt = 0; mt < 4; mt++)
#pragma unroll
        for (int nt = 0; nt < 4; nt++) {
            const int r0 = rowBase + wm + mt * 16 + g;
            const int c0 = colBase + wn + nt * 8 + tg * 2;
            float2 v0, v1;
            v0.x = acc[mt][nt][0]; v0.y = acc[mt][nt][1];
            v1.x = acc[mt][nt][2]; v1.y = acc[mt][nt][3];
            if (bias) {
                const float bx = bias[c0], by = bias[c0 + 1];
                v0.x += bx; v0.y += by; v1.x += bx; v1.y += by;
            }
            *(float2*)&C[(size_t)r0 * ldc + c0] = v0;
            *(float2*)&C[(size_t)(r0 + 8) * ldc + c0] = v1;
        }
}

// ===========================================================================
// Transpose + hi/lo split: Wt_hi/lo[n,k] = split(W[k,n]), 32x32 tiles
// ===========================================================================
__global__ __launch_bounds__(256) void transpose_split_kernel(
    const float* __restrict__ W,
    __nv_bfloat16* __restrict__ Wth, __nv_bfloat16* __restrict__ Wtl) {
    __shared__ float t[32][33];
    const int n0 = blockIdx.x * 32, k0 = blockIdx.y * 32;
    const int x = threadIdx.x, ty = threadIdx.y;
#pragma unroll
    for (int yy = ty; yy < 32; yy += 8)
        t[yy][x] = W[(size_t)(k0 + yy) * DIM + n0 + x];
    __syncthreads();
#pragma unroll
    for (int yy = ty; yy < 32; yy += 8) {
        const float v = t[x][yy];
        const __nv_bfloat16 h = __float2bfloat16(v);
        const __nv_bfloat16 l = __float2bfloat16(v - __bfloat162float(h));
        const size_t o = (size_t)(n0 + yy) * DIM + k0 + x;
        Wth[o] = h;
        Wtl[o] = l;
    }
}

// ===========================================================================
// Elementwise hi/lo split (fp32 -> 2x bf16), float4 granularity
// ===========================================================================
__global__ __launch_bounds__(256) void split_kernel(const float* __restrict__ e,
                                                    __nv_bfloat16* __restrict__ hi,
                                                    __nv_bfloat16* __restrict__ lo) {
    const size_t i = (size_t)blockIdx.x * blockDim.x + threadIdx.x;
    float4 x = ((const float4*)e)[i];
    float v[4] = {x.x, x.y, x.z, x.w};
    __nv_bfloat16 hh[4], ll[4];
#pragma unroll
    for (int k = 0; k < 4; k++) {
        hh[k] = __float2bfloat16(v[k]);
        ll[k] = __float2bfloat16(v[k] - __bfloat162float(hh[k]));
    }
    __nv_bfloat162 hp0, hp1, lp0, lp1;
    hp0.x = hh[0]; hp0.y = hh[1]; hp1.x = hh[2]; hp1.y = hh[3];
    lp0.x = ll[0]; lp0.y = ll[1]; lp1.x = ll[2]; lp1.y = ll[3];
    uint2 hv, lv;
    hv.x = *(uint32_t*)&hp0; hv.y = *(uint32_t*)&hp1;
    lv.x = *(uint32_t*)&lp0; lv.y = *(uint32_t*)&lp1;
    ((uint2*)hi)[i] = hv;
    ((uint2*)lo)[i] = lv;
}

// ===========================================================================
// LayerNorm + exact GELU (one block per row)
// ===========================================================================
__global__ __launch_bounds__(256) void ln_gelu_kernel(float* __restrict__ h,
                                                      const float* __restrict__ gamma,
                                                      const float* __restrict__ beta) {
    const int row = blockIdx.x;
    float* p = h + (size_t)row * DIM;
    const int t = threadIdx.x;

    float4 x = *(const float4*)&p[t * 4];
    float s1 = x.x + x.y + x.z + x.w;
    float s2 = x.x * x.x + x.y * x.y + x.z * x.z + x.w * x.w;
#pragma unroll
    for (int o = 16; o > 0; o >>= 1) {
        s1 += __shfl_xor_sync(0xffffffffu, s1, o);
        s2 += __shfl_xor_sync(0xffffffffu, s2, o);
    }
    __shared__ float r1[8], r2[8];
    if ((t & 31) == 0) { r1[t >> 5] = s1; r2[t >> 5] = s2; }
    __syncthreads();
    if (t < 32) {
        s1 = (t < 8) ? r1[t] : 0.f;
        s2 = (t < 8) ? r2[t] : 0.f;
#pragma unroll
        for (int o = 4; o > 0; o >>= 1) {
            s1 += __shfl_xor_sync(0xffffffffu, s1, o);
            s2 += __shfl_xor_sync(0xffffffffu, s2, o);
        }
        if (t == 0) { r1[0] = s1; r2[0] = s2; }
    }
    __syncthreads();
    const float mu = r1[0] * (1.f / DIM);
    const float var = r2[0] * (1.f / DIM) - mu * mu;
    const float rstd = rsqrtf(var + 1e-5f);

    const float4 g = *(const float4*)&gamma[t * 4];
    const float4 bb = *(const float4*)&beta[t * 4];
    float y[4] = { (x.x - mu) * rstd * g.x + bb.x,
                   (x.y - mu) * rstd * g.y + bb.y,
                   (x.z - mu) * rstd * g.z + bb.z,
                   (x.w - mu) * rstd * g.w + bb.w };
    float4 o;
    o.x = 0.5f * y[0] * (1.f + erff(y[0] * 0.70710678118654752f));
    o.y = 0.5f * y[1] * (1.f + erff(y[1] * 0.70710678118654752f));
    o.z = 0.5f * y[2] * (1.f + erff(y[2] * 0.70710678118654752f));
    o.w = 0.5f * y[3] * (1.f + erff(y[3] * 0.70710678118654752f));
    *(float4*)&p[t * 4] = o;
}

// ===========================================================================
// Row L2 normalize + hi/lo split fused (one block per row)
// ===========================================================================
__global__ __launch_bounds__(256) void l2norm_split_kernel(
    const float* __restrict__ e,
    __nv_bfloat16* __restrict__ hi,
    __nv_bfloat16* __restrict__ lo) {
    const int row = blockIdx.x;
    const float* p = e + (size_t)row * DIM;
    const int t = threadIdx.x;

    float4 x = *(const float4*)&p[t * 4];
    float s2 = x.x * x.x + x.y * x.y + x.z * x.z + x.w * x.w;
#pragma unroll
    for (int o = 16; o > 0; o >>= 1) s2 += __shfl_xor_sync(0xffffffffu, s2, o);
    __shared__ float r2[8];
    if ((t & 31) == 0) r2[t >> 5] = s2;
    __syncthreads();
    if (t < 32) {
        s2 = (t < 8) ? r2[t] : 0.f;
#pragma unroll
        for (int o = 4; o > 0; o >>= 1) s2 += __shfl_xor_sync(0xffffffffu, s2, o);
        if (t == 0) r2[0] = s2;
    }
    __syncthreads();
    const float inv = 1.f / fmaxf(sqrtf(r2[0]), 1e-12f);
    float v[4] = { x.x * inv, x.y * inv, x.z * inv, x.w * inv };

    __nv_bfloat16 hh[4], ll[4];
#pragma unroll
    for (int i = 0; i < 4; i++) {
        hh[i] = __float2bfloat16(v[i]);
        ll[i] = __float2bfloat16(v[i] - __bfloat162float(hh[i]));
    }
    const size_t idx = (size_t)row * (DIM / 4) + t;
    __nv_bfloat162 hp0, hp1, lp0, lp1;
    hp0.x = hh[0]; hp0.y = hh[1]; hp1.x = hh[2]; hp1.y = hh[3];
    lp0.x = ll[0]; lp0.y = ll[1]; lp1.x = ll[2]; lp1.y = ll[3];
    uint2 hv, lv;
    hv.x = *(uint32_t*)&hp0; hv.y = *(uint32_t*)&hp1;
    lv.x = *(uint32_t*)&lp0; lv.y = *(uint32_t*)&lp1;
    ((uint2*)hi)[idx] = hv;
    ((uint2*)lo)[idx] = lv;
}

// ===========================================================================
// Mirror strict-lower 32x32 tiles to upper
// ===========================================================================
__global__ __launch_bounds__(256) void mirror_kernel(float* __restrict__ out) {
    const long b = blockIdx.x;
    int ti = (int)((sqrt(8.0 * (double)b + 1.0) + 1.0) * 0.5);
    while ((long)ti * (ti - 1) / 2 > b) ti--;
    while ((long)(ti + 1) * ti / 2 <= b) ti++;
    const int tj = (int)(b - (long)ti * (ti - 1) / 2);

    __shared__ float t[32][33];
    const int x = threadIdx.x;
    const int y0 = threadIdx.y;
    const float* src = out + (size_t)(ti * 32) * NROWS + tj * 32;
#pragma unroll
    for (int yy = y0; yy < 32; yy += 8) t[yy][x] = src[(size_t)yy * NROWS + x];
    __syncthreads();
    float* dst = out + (size_t)(tj * 32) * NROWS + ti * 32;
#pragma unroll
    for (int yy = y0; yy < 32; yy += 8) dst[(size_t)yy * NROWS + x] = t[x][yy];
}

// ===========================================================================
// is_duplicate[j] = any_{i<j} sim[j][i] > THR (row read via exact symmetry)
// ===========================================================================
__global__ __launch_bounds__(256) void dup_kernel(const float* __restrict__ sim,
                                                  float* __restrict__ out) {
    const int j = blockIdx.x;
    const float* row = sim + (size_t)j * NROWS;
    int found = 0;
    for (int i = threadIdx.x; i < j; i += blockDim.x) {
        if (row[i] > THR) { found = 1; break; }
    }
    found = __syncthreads_or(found);
    if (threadIdx.x == 0) out[j] = found ? 1.0f : 0.0f;
}

// ===========================================================================
extern "C" void kernel_launch(void* const* d_in, const int* in_sizes, int n_in,
                              void* d_out, int out_size) {
    const float* S     = (const float*)d_in[0];
    const float* W1    = (const float*)d_in[1];
    const float* b1    = (const float*)d_in[2];
    const float* gamma = (const float*)d_in[3];
    const float* beta  = (const float*)d_in[4];
    const float* W2    = (const float*)d_in[5];
    const float* b2    = (const float*)d_in[6];
    float* out = (float*)d_out;

    float *h, *enc;
    __nv_bfloat16 *hi, *lo, *wth, *wtl;
    cudaGetSymbolAddress((void**)&h, g_h);
    cudaGetSymbolAddress((void**)&enc, g_enc);
    cudaGetSymbolAddress((void**)&hi, g_hi);
    cudaGetSymbolAddress((void**)&lo, g_lo);
    cudaGetSymbolAddress((void**)&wth, g_wt_hi);
    cudaGetSymbolAddress((void**)&wtl, g_wt_lo);

    const int TC_SMEM = 2 * 32768;  // 64 KB dynamic
    cudaFuncSetAttribute(gemm_tc<true>, cudaFuncAttributeMaxDynamicSharedMemorySize,
                         TC_SMEM);
    cudaFuncSetAttribute(gemm_tc<false>, cudaFuncAttributeMaxDynamicSharedMemorySize,
                         TC_SMEM);

    const int SPLIT_BLK = (NROWS * (DIM / 4)) / 256;

    // 1) split S; transpose+split W1
    split_kernel<<<SPLIT_BLK, 256>>>(S, hi, lo);
    transpose_split_kernel<<<dim3(32, 32), dim3(32, 8)>>>(W1, wth, wtl);
    // 2) h = S @ W1 + b1  (tensor cores)
    gemm_tc<false><<<dim3(DIM / 128, NROWS / 128), 256, TC_SMEM>>>(
        hi, lo, wth, wtl, h, DIM, b1, DIM);
    // 3) LayerNorm + GELU
    ln_gelu_kernel<<<NROWS, 256>>>(h, gamma, beta);
    // 4) split h; transpose+split W2
    split_kernel<<<SPLIT_BLK, 256>>>(h, hi, lo);
    transpose_split_kernel<<<dim3(32, 32), dim3(32, 8)>>>(W2, wth, wtl);
    // 5) enc = h @ W2 + b2  (tensor cores)
    gemm_tc<false><<<dim3(DIM / 128, NROWS / 128), 256, TC_SMEM>>>(
        hi, lo, wth, wtl, enc, DIM, b2, DIM);
    // 6) L2 normalize + split
    l2norm_split_kernel<<<NROWS, 256>>>(enc, hi, lo);
    // 7) sim lower-triangular tiles
    const int NT = NROWS / 128;
    gemm_tc<true><<<NT * (NT + 1) / 2, 256, TC_SMEM>>>(
        hi, lo, hi, lo, out, NROWS, nullptr, DIM);
    // 8) mirror to upper triangle
    const int T32 = NROWS / 32;
    mirror_kernel<<<T32 * (T32 - 1) / 2, dim3(32, 8)>>>(out);
    // 9) is_duplicate
    if (out_size >= NROWS * NROWS + NROWS) {
        dup_kernel<<<NROWS, 256>>>(out, out + (size_t)NROWS * NROWS);
    }
}

// round 5
// speedup vs baseline: 5.6257x; 1.6816x over previous
#include <cuda_runtime.h>
#include <cuda_bf16.h>
#include <cuda_fp16.h>
#include <math.h>
#include <stdint.h>

#define NROWS 8192
#define DIM   1024
#define THR   0.85f

// Scratch (allocation-free: __device__ globals)
__device__ float g_h[(size_t)NROWS * DIM];              // 32 MB (later: fp16 enc hi/lo)
__device__ float g_enc[(size_t)NROWS * DIM];            // 32 MB
__device__ __nv_bfloat16 g_hi[(size_t)NROWS * DIM];     // 16 MB
__device__ __nv_bfloat16 g_lo[(size_t)NROWS * DIM];     // 16 MB
__device__ __nv_bfloat16 g_wt_hi[(size_t)DIM * DIM];    // 2 MB
__device__ __nv_bfloat16 g_wt_lo[(size_t)DIM * DIM];    // 2 MB

// ===========================================================================
// sm_80-generic PTX helpers (base sm_103 target: no tcgen05)
// ===========================================================================
__device__ __forceinline__ uint32_t smem_u32(const void* p) {
    uint32_t a;
    asm("{ .reg .u64 t; cvta.to.shared.u64 t, %1; cvt.u32.u64 %0, t; }"
        : "=r"(a) : "l"(p));
    return a;
}
__device__ __forceinline__ void cp16(uint32_t dst, const void* src) {
    asm volatile("cp.async.cg.shared.global [%0], [%1], 16;"
                 :: "r"(dst), "l"(src));
}
__device__ __forceinline__ void ldsm_x4(uint32_t* r, uint32_t addr) {
    asm volatile("ldmatrix.sync.aligned.m8n8.x4.shared.b16 {%0,%1,%2,%3}, [%4];"
                 : "=r"(r[0]), "=r"(r[1]), "=r"(r[2]), "=r"(r[3]) : "r"(addr));
}
__device__ __forceinline__ void mma_bf16(float* c, const uint32_t* a,
                                         const uint32_t* b) {
    asm volatile("mma.sync.aligned.m16n8k16.row.col.f32.bf16.bf16.f32 "
                 "{%0,%1,%2,%3}, {%4,%5,%6,%7}, {%8,%9}, {%0,%1,%2,%3};"
                 : "+f"(c[0]), "+f"(c[1]), "+f"(c[2]), "+f"(c[3])
                 : "r"(a[0]), "r"(a[1]), "r"(a[2]), "r"(a[3]),
                   "r"(b[0]), "r"(b[1]));
}
__device__ __forceinline__ void mma_f16(float* c, const uint32_t* a,
                                        const uint32_t* b) {
    asm volatile("mma.sync.aligned.m16n8k16.row.col.f32.f16.f16.f32 "
                 "{%0,%1,%2,%3}, {%4,%5,%6,%7}, {%8,%9}, {%0,%1,%2,%3};"
                 : "+f"(c[0]), "+f"(c[1]), "+f"(c[2]), "+f"(c[3])
                 : "r"(a[0]), "r"(a[1]), "r"(a[2]), "r"(a[3]),
                   "r"(b[0]), "r"(b[1]));
}

// smem tile: 128 rows x 64B (32 x16-bit). 16B-chunk swizzle, conflict-free LDSM.
__device__ __forceinline__ uint32_t swz(uint32_t row, uint32_t chunk) {
    uint32_t c = chunk ^ (row & 3u) ^ ((row >> 2) & 1u);
    return row * 64u + c * 16u;
}

// ===========================================================================
// Encoder GEMM: bf16 hi/lo 3-pass. C[m,n]+bias = sum_k A[m,k]*B[n,k].
// 256 thr = 8 warps (2m x 4n), warp 64x32, BK=32, 2-stage cp.async. (proven)
// ===========================================================================
__global__ __launch_bounds__(256) void gemm_rect(
    const __nv_bfloat16* __restrict__ Ah, const __nv_bfloat16* __restrict__ Al,
    const __nv_bfloat16* __restrict__ Bh, const __nv_bfloat16* __restrict__ Bl,
    float* __restrict__ C, int ldc, const float* __restrict__ bias, int K) {
    extern __shared__ char sm[];
    const uint32_t sb = smem_u32(sm);

    const int rowBase = blockIdx.y * 128;
    const int colBase = blockIdx.x * 128;

    const int tid = threadIdx.x;
    const int wid = tid >> 5;
    const int lane = tid & 31;
    const int wm = (wid & 1) * 64;
    const int wn = (wid >> 1) * 32;

    const size_t rowB = (size_t)K * 2;
    const char* gAh = (const char*)Ah + (size_t)rowBase * rowB;
    const char* gAl = (const char*)Al + (size_t)rowBase * rowB;
    const char* gBh = (const char*)Bh + (size_t)colBase * rowB;
    const char* gBl = (const char*)Bl + (size_t)colBase * rowB;

    auto load_stage = [&](int st, int kc) {
        const char* bases[4] = {gAh, gAl, gBh, gBl};
#pragma unroll
        for (int t = 0; t < 4; t++) {
#pragma unroll
            for (int h = 0; h < 2; h++) {
                const int c = tid + h * 256;
                const uint32_t row = c >> 2, kch = c & 3;
                const uint32_t dst = sb + st * 32768u + t * 8192u + swz(row, kch);
                cp16(dst, bases[t] + (size_t)row * rowB + (size_t)kc * 64 + kch * 16);
            }
        }
    };

    float acc[4][4][4];
#pragma unroll
    for (int i = 0; i < 4; i++)
#pragma unroll
        for (int j = 0; j < 4; j++)
#pragma unroll
            for (int k = 0; k < 4; k++) acc[i][j][k] = 0.f;

    load_stage(0, 0);
    asm volatile("cp.async.commit_group;");
    load_stage(1, 1);
    asm volatile("cp.async.commit_group;");

    const int kcN = K / 32;
    for (int kc = 0; kc < kcN; kc++) {
        asm volatile("cp.async.wait_group 1;");
        __syncthreads();
        const int st = kc & 1;
        const uint32_t uAh = sb + st * 32768u;
        const uint32_t uAl = uAh + 8192u;
        const uint32_t uBh = uAh + 16384u;
        const uint32_t uBl = uAh + 24576u;

        uint32_t ah[4][4], al[4][4], bh[4][2], bl[4][2];
        const uint32_t arow0 = (uint32_t)(wm + (lane & 15));
        const uint32_t achb = (uint32_t)(lane >> 4);
        const uint32_t brow0 = (uint32_t)(wn + (lane & 7) + ((lane & 16) >> 1));
        const uint32_t bchb = (uint32_t)((lane >> 3) & 1);

        // ---- ks = 0 ----
#pragma unroll
        for (int mt = 0; mt < 4; mt++) {
            ldsm_x4(ah[mt], uAh + swz(arow0 + mt * 16, achb));
            ldsm_x4(al[mt], uAl + swz(arow0 + mt * 16, achb));
        }
#pragma unroll
        for (int p = 0; p < 2; p++) {
            uint32_t r[4];
            ldsm_x4(r, uBh + swz(brow0 + p * 16, bchb));
            bh[p * 2][0] = r[0]; bh[p * 2][1] = r[1];
            bh[p * 2 + 1][0] = r[2]; bh[p * 2 + 1][1] = r[3];
            ldsm_x4(r, uBl + swz(brow0 + p * 16, bchb));
            bl[p * 2][0] = r[0]; bl[p * 2][1] = r[1];
            bl[p * 2 + 1][0] = r[2]; bl[p * 2 + 1][1] = r[3];
        }
#pragma unroll
        for (int mt = 0; mt < 4; mt++)
#pragma unroll
            for (int nt = 0; nt < 4; nt++) {
                mma_bf16(acc[mt][nt], ah[mt], bh[nt]);
                mma_bf16(acc[mt][nt], ah[mt], bl[nt]);
                mma_bf16(acc[mt][nt], al[mt], bh[nt]);
            }

        // ---- ks = 1 ----
#pragma unroll
        for (int mt = 0; mt < 4; mt++) {
            ldsm_x4(ah[mt], uAh + swz(arow0 + mt * 16, 2u + achb));
            ldsm_x4(al[mt], uAl + swz(arow0 + mt * 16, 2u + achb));
        }
#pragma unroll
        for (int p = 0; p < 2; p++) {
            uint32_t r[4];
            ldsm_x4(r, uBh + swz(brow0 + p * 16, 2u + bchb));
            bh[p * 2][0] = r[0]; bh[p * 2][1] = r[1];
            bh[p * 2 + 1][0] = r[2]; bh[p * 2 + 1][1] = r[3];
            ldsm_x4(r, uBl + swz(brow0 + p * 16, 2u + bchb));
            bl[p * 2][0] = r[0]; bl[p * 2][1] = r[1];
            bl[p * 2 + 1][0] = r[2]; bl[p * 2 + 1][1] = r[3];
        }
        __syncthreads();
        if (kc + 2 < kcN) load_stage(st, kc + 2);
        asm volatile("cp.async.commit_group;");

#pragma unroll
        for (int mt = 0; mt < 4; mt++)
#pragma unroll
            for (int nt = 0; nt < 4; nt++) {
                mma_bf16(acc[mt][nt], ah[mt], bh[nt]);
                mma_bf16(acc[mt][nt], ah[mt], bl[nt]);
                mma_bf16(acc[mt][nt], al[mt], bh[nt]);
            }
    }

    const int g = lane >> 2, tg = lane & 3;
#pragma unroll
    for (int mt = 0; mt < 4; mt++)
#pragma unroll
        for (int nt = 0; nt < 4; nt++) {
            const int r0 = rowBase + wm + mt * 16 + g;
            const int c0 = colBase + wn + nt * 8 + tg * 2;
            float2 v0, v1;
            v0.x = acc[mt][nt][0]; v0.y = acc[mt][nt][1];
            v1.x = acc[mt][nt][2]; v1.y = acc[mt][nt][3];
            const float bx = bias[c0], by = bias[c0 + 1];
            v0.x += bx; v0.y += by; v1.x += bx; v1.y += by;
            *(float2*)&C[(size_t)r0 * ldc + c0] = v0;
            *(float2*)&C[(size_t)(r0 + 8) * ldc + c0] = v1;
        }
}

// ===========================================================================
// Sim GEMM: fp16 2-pass (hiA*hiB + hiA*loB), lower-tri 128x128 tiles,
// 3-stage pipeline (A-hi, B-hi, B-lo = 24KB/stage). Fused epilogue:
// writes out[r][c], mirrors out[c][r] (r>c), sets dup[r] on v>THR.
// ===========================================================================
__global__ __launch_bounds__(256) void sim_tc_kernel(
    const __half* __restrict__ Eh, const __half* __restrict__ El,
    float* __restrict__ out, float* __restrict__ dup) {
    extern __shared__ char sm[];
    const uint32_t sb = smem_u32(sm);

    const int b = blockIdx.x;
    int bi = (int)((sqrtf(8.f * b + 1.f) - 1.f) * 0.5f);
    while ((bi + 1) * (bi + 2) / 2 <= b) bi++;
    while (bi * (bi + 1) / 2 > b) bi--;
    const int bj = b - bi * (bi + 1) / 2;
    const int rowBase = bi * 128;
    const int colBase = bj * 128;

    const int tid = threadIdx.x;
    const int wid = tid >> 5;
    const int lane = tid & 31;
    const int wm = (wid & 1) * 64;
    const int wn = (wid >> 1) * 32;

    const char* gA  = (const char*)Eh + (size_t)rowBase * 2048;
    const char* gBh = (const char*)Eh + (size_t)colBase * 2048;
    const char* gBl = (const char*)El + (size_t)colBase * 2048;

    auto load_stage = [&](int st, int kc) {
        const char* bases[3] = {gA, gBh, gBl};
#pragma unroll
        for (int t = 0; t < 3; t++) {
#pragma unroll
            for (int h = 0; h < 2; h++) {
                const int c = tid + h * 256;
                const uint32_t row = c >> 2, kch = c & 3;
                const uint32_t dst = sb + st * 24576u + t * 8192u + swz(row, kch);
                cp16(dst, bases[t] + (size_t)row * 2048 + (size_t)kc * 64 + kch * 16);
            }
        }
    };

    float acc[4][4][4];
#pragma unroll
    for (int i = 0; i < 4; i++)
#pragma unroll
        for (int j = 0; j < 4; j++)
#pragma unroll
            for (int k = 0; k < 4; k++) acc[i][j][k] = 0.f;

    load_stage(0, 0);
    asm volatile("cp.async.commit_group;");
    load_stage(1, 1);
    asm volatile("cp.async.commit_group;");
    load_stage(2, 2);
    asm volatile("cp.async.commit_group;");

    int st = 0;
    for (int kc = 0; kc < 32; kc++) {
        asm volatile("cp.async.wait_group 2;");
        __syncthreads();
        const uint32_t uA  = sb + st * 24576u;
        const uint32_t uBh = uA + 8192u;
        const uint32_t uBl = uA + 16384u;

        uint32_t ah[4][4], bh[4][2], bl[4][2];
        const uint32_t arow0 = (uint32_t)(wm + (lane & 15));
        const uint32_t achb = (uint32_t)(lane >> 4);
        const uint32_t brow0 = (uint32_t)(wn + (lane & 7) + ((lane & 16) >> 1));
        const uint32_t bchb = (uint32_t)((lane >> 3) & 1);

        // ---- ks = 0 ----
#pragma unroll
        for (int mt = 0; mt < 4; mt++)
            ldsm_x4(ah[mt], uA + swz(arow0 + mt * 16, achb));
#pragma unroll
        for (int p = 0; p < 2; p++) {
            uint32_t r[4];
            ldsm_x4(r, uBh + swz(brow0 + p * 16, bchb));
            bh[p * 2][0] = r[0]; bh[p * 2][1] = r[1];
            bh[p * 2 + 1][0] = r[2]; bh[p * 2 + 1][1] = r[3];
            ldsm_x4(r, uBl + swz(brow0 + p * 16, bchb));
            bl[p * 2][0] = r[0]; bl[p * 2][1] = r[1];
            bl[p * 2 + 1][0] = r[2]; bl[p * 2 + 1][1] = r[3];
        }
#pragma unroll
        for (int mt = 0; mt < 4; mt++)
#pragma unroll
            for (int nt = 0; nt < 4; nt++) {
                mma_f16(acc[mt][nt], ah[mt], bh[nt]);
                mma_f16(acc[mt][nt], ah[mt], bl[nt]);
            }

        // ---- ks = 1 ----
#pragma unroll
        for (int mt = 0; mt < 4; mt++)
            ldsm_x4(ah[mt], uA + swz(arow0 + mt * 16, 2u + achb));
#pragma unroll
        for (int p = 0; p < 2; p++) {
            uint32_t r[4];
            ldsm_x4(r, uBh + swz(brow0 + p * 16, 2u + bchb));
            bh[p * 2][0] = r[0]; bh[p * 2][1] = r[1];
            bh[p * 2 + 1][0] = r[2]; bh[p * 2 + 1][1] = r[3];
            ldsm_x4(r, uBl + swz(brow0 + p * 16, 2u + bchb));
            bl[p * 2][0] = r[0]; bl[p * 2][1] = r[1];
            bl[p * 2 + 1][0] = r[2]; bl[p * 2 + 1][1] = r[3];
        }
        __syncthreads();
        if (kc + 3 < 32) load_stage(st, kc + 3);
        asm volatile("cp.async.commit_group;");

#pragma unroll
        for (int mt = 0; mt < 4; mt++)
#pragma unroll
            for (int nt = 0; nt < 4; nt++) {
                mma_f16(acc[mt][nt], ah[mt], bh[nt]);
                mma_f16(acc[mt][nt], ah[mt], bl[nt]);
            }
        st = (st == 2) ? 0 : st + 1;
    }

    // fused epilogue: normal store + mirror + dup flag
    const int g = lane >> 2, tg = lane & 3;
    const bool offdiag = (rowBase != colBase);
#pragma unroll
    for (int mt = 0; mt < 4; mt++)
#pragma unroll
        for (int nt = 0; nt < 4; nt++) {
            const int c0 = colBase + wn + nt * 8 + tg * 2;
#pragma unroll
            for (int hf = 0; hf < 2; hf++) {
                const int r = rowBase + wm + mt * 16 + g + hf * 8;
                const float vx = acc[mt][nt][hf * 2 + 0];
                const float vy = acc[mt][nt][hf * 2 + 1];
                if (offdiag) {
                    float2 v; v.x = vx; v.y = vy;
                    *(float2*)&out[(size_t)r * NROWS + c0] = v;
                    out[(size_t)c0 * NROWS + r] = vx;
                    out[(size_t)(c0 + 1) * NROWS + r] = vy;
                    if (dup) {
                        if (vx > THR) dup[r] = 1.0f;
                        if (vy > THR) dup[r] = 1.0f;
                    }
                } else {
                    if (r >= c0) {
                        out[(size_t)r * NROWS + c0] = vx;
                        if (r > c0) {
                            out[(size_t)c0 * NROWS + r] = vx;
                            if (dup && vx > THR) dup[r] = 1.0f;
                        }
                    }
                    if (r >= c0 + 1) {
                        out[(size_t)r * NROWS + c0 + 1] = vy;
                        if (r > c0 + 1) {
                            out[(size_t)(c0 + 1) * NROWS + r] = vy;
                            if (dup && vy > THR) dup[r] = 1.0f;
                        }
                    }
                }
            }
        }
}

// ===========================================================================
// Transpose + bf16 hi/lo split: Wt[n,k] = split(W[k,n])
// ===========================================================================
__global__ __launch_bounds__(256) void transpose_split_kernel(
    const float* __restrict__ W,
    __nv_bfloat16* __restrict__ Wth, __nv_bfloat16* __restrict__ Wtl) {
    __shared__ float t[32][33];
    const int n0 = blockIdx.x * 32, k0 = blockIdx.y * 32;
    const int x = threadIdx.x, ty = threadIdx.y;
#pragma unroll
    for (int yy = ty; yy < 32; yy += 8)
        t[yy][x] = W[(size_t)(k0 + yy) * DIM + n0 + x];
    __syncthreads();
#pragma unroll
    for (int yy = ty; yy < 32; yy += 8) {
        const float v = t[x][yy];
        const __nv_bfloat16 h = __float2bfloat16(v);
        const __nv_bfloat16 l = __float2bfloat16(v - __bfloat162float(h));
        const size_t o = (size_t)(n0 + yy) * DIM + k0 + x;
        Wth[o] = h;
        Wtl[o] = l;
    }
}

// ===========================================================================
// Elementwise bf16 hi/lo split
// ===========================================================================
__global__ __launch_bounds__(256) void split_kernel(const float* __restrict__ e,
                                                    __nv_bfloat16* __restrict__ hi,
                                                    __nv_bfloat16* __restrict__ lo) {
    const size_t i = (size_t)blockIdx.x * blockDim.x + threadIdx.x;
    float4 x = ((const float4*)e)[i];
    float v[4] = {x.x, x.y, x.z, x.w};
    __nv_bfloat16 hh[4], ll[4];
#pragma unroll
    for (int k = 0; k < 4; k++) {
        hh[k] = __float2bfloat16(v[k]);
        ll[k] = __float2bfloat16(v[k] - __bfloat162float(hh[k]));
    }
    __nv_bfloat162 hp0, hp1, lp0, lp1;
    hp0.x = hh[0]; hp0.y = hh[1]; hp1.x = hh[2]; hp1.y = hh[3];
    lp0.x = ll[0]; lp0.y = ll[1]; lp1.x = ll[2]; lp1.y = ll[3];
    uint2 hv, lv;
    hv.x = *(uint32_t*)&hp0; hv.y = *(uint32_t*)&hp1;
    lv.x = *(uint32_t*)&lp0; lv.y = *(uint32_t*)&lp1;
    ((uint2*)hi)[i] = hv;
    ((uint2*)lo)[i] = lv;
}

// ===========================================================================
// LayerNorm + exact GELU + bf16 hi/lo split (fused, one block per row)
// ===========================================================================
__global__ __launch_bounds__(256) void ln_gelu_split_kernel(
    const float* __restrict__ h, const float* __restrict__ gamma,
    const float* __restrict__ beta,
    __nv_bfloat16* __restrict__ hi, __nv_bfloat16* __restrict__ lo) {
    const int row = blockIdx.x;
    const float* p = h + (size_t)row * DIM;
    const int t = threadIdx.x;

    float4 x = *(const float4*)&p[t * 4];
    float s1 = x.x + x.y + x.z + x.w;
    float s2 = x.x * x.x + x.y * x.y + x.z * x.z + x.w * x.w;
#pragma unroll
    for (int o = 16; o > 0; o >>= 1) {
        s1 += __shfl_xor_sync(0xffffffffu, s1, o);
        s2 += __shfl_xor_sync(0xffffffffu, s2, o);
    }
    __shared__ float r1[8], r2[8];
    if ((t & 31) == 0) { r1[t >> 5] = s1; r2[t >> 5] = s2; }
    __syncthreads();
    if (t < 32) {
        s1 = (t < 8) ? r1[t] : 0.f;
        s2 = (t < 8) ? r2[t] : 0.f;
#pragma unroll
        for (int o = 4; o > 0; o >>= 1) {
            s1 += __shfl_xor_sync(0xffffffffu, s1, o);
            s2 += __shfl_xor_sync(0xffffffffu, s2, o);
        }
        if (t == 0) { r1[0] = s1; r2[0] = s2; }
    }
    __syncthreads();
    const float mu = r1[0] * (1.f / DIM);
    const float var = r2[0] * (1.f / DIM) - mu * mu;
    const float rstd = rsqrtf(var + 1e-5f);

    const float4 g = *(const float4*)&gamma[t * 4];
    const float4 bb = *(const float4*)&beta[t * 4];
    float y[4] = { (x.x - mu) * rstd * g.x + bb.x,
                   (x.y - mu) * rstd * g.y + bb.y,
                   (x.z - mu) * rstd * g.z + bb.z,
                   (x.w - mu) * rstd * g.w + bb.w };
    float v[4];
#pragma unroll
    for (int i = 0; i < 4; i++)
        v[i] = 0.5f * y[i] * (1.f + erff(y[i] * 0.70710678118654752f));

    __nv_bfloat16 hh[4], ll[4];
#pragma unroll
    for (int i = 0; i < 4; i++) {
        hh[i] = __float2bfloat16(v[i]);
        ll[i] = __float2bfloat16(v[i] - __bfloat162float(hh[i]));
    }
    const size_t idx = (size_t)row * (DIM / 4) + t;
    __nv_bfloat162 hp0, hp1, lp0, lp1;
    hp0.x = hh[0]; hp0.y = hh[1]; hp1.x = hh[2]; hp1.y = hh[3];
    lp0.x = ll[0]; lp0.y = ll[1]; lp1.x = ll[2]; lp1.y = ll[3];
    uint2 hv, lv;
    hv.x = *(uint32_t*)&hp0; hv.y = *(uint32_t*)&hp1;
    lv.x = *(uint32_t*)&lp0; lv.y = *(uint32_t*)&lp1;
    ((uint2*)hi)[idx] = hv;
    ((uint2*)lo)[idx] = lv;
}

// ===========================================================================
// Row L2 normalize + fp16 hi/lo split (for the sim GEMM)
// ===========================================================================
__global__ __launch_bounds__(256) void l2norm_split_f16_kernel(
    const float* __restrict__ e,
    __half* __restrict__ hi, __half* __restrict__ lo) {
    const int row = blockIdx.x;
    const float* p = e + (size_t)row * DIM;
    const int t = threadIdx.x;

    float4 x = *(const float4*)&p[t * 4];
    float s2 = x.x * x.x + x.y * x.y + x.z * x.z + x.w * x.w;
#pragma unroll
    for (int o = 16; o > 0; o >>= 1) s2 += __shfl_xor_sync(0xffffffffu, s2, o);
    __shared__ float r2[8];
    if ((t & 31) == 0) r2[t >> 5] = s2;
    __syncthreads();
    if (t < 32) {
        s2 = (t < 8) ? r2[t] : 0.f;
#pragma unroll
        for (int o = 4; o > 0; o >>= 1) s2 += __shfl_xor_sync(0xffffffffu, s2, o);
        if (t == 0) r2[0] = s2;
    }
    __syncthreads();
    const float inv = 1.f / fmaxf(sqrtf(r2[0]), 1e-12f);
    float v[4] = { x.x * inv, x.y * inv, x.z * inv, x.w * inv };

    __half hh[4], ll[4];
#pragma unroll
    for (int i = 0; i < 4; i++) {
        hh[i] = __float2half(v[i]);
        ll[i] = __float2half(v[i] - __half2float(hh[i]));
    }
    const size_t idx = (size_t)row * (DIM / 4) + t;
    __half2 hp0, hp1, lp0, lp1;
    hp0.x = hh[0]; hp0.y = hh[1]; hp1.x = hh[2]; hp1.y = hh[3];
    lp0.x = ll[0]; lp0.y = ll[1]; lp1.x = ll[2]; lp1.y = ll[3];
    uint2 hv, lv;
    hv.x = *(uint32_t*)&hp0; hv.y = *(uint32_t*)&hp1;
    lv.x = *(uint32_t*)&lp0; lv.y = *(uint32_t*)&lp1;
    ((uint2*)hi)[idx] = hv;
    ((uint2*)lo)[idx] = lv;
}

// ===========================================================================
__global__ void zero_kernel(float* __restrict__ p, int n) {
    const int i = blockIdx.x * blockDim.x + threadIdx.x;
    if (i < n) p[i] = 0.0f;
}

// ===========================================================================
extern "C" void kernel_launch(void* const* d_in, const int* in_sizes, int n_in,
                              void* d_out, int out_size) {
    const float* S     = (const float*)d_in[0];
    const float* W1    = (const float*)d_in[1];
    const float* b1    = (const float*)d_in[2];
    const float* gamma = (const float*)d_in[3];
    const float* beta  = (const float*)d_in[4];
    const float* W2    = (const float*)d_in[5];
    const float* b2    = (const float*)d_in[6];
    float* out = (float*)d_out;

    float *h, *enc;
    __nv_bfloat16 *hi, *lo, *wth, *wtl;
    cudaGetSymbolAddress((void**)&h, g_h);
    cudaGetSymbolAddress((void**)&enc, g_enc);
    cudaGetSymbolAddress((void**)&hi, g_hi);
    cudaGetSymbolAddress((void**)&lo, g_lo);
    cudaGetSymbolAddress((void**)&wth, g_wt_hi);
    cudaGetSymbolAddress((void**)&wtl, g_wt_lo);
    // fp16 enc halves overlay the (dead-after-LN) h buffer: 2 x 16 MB in 32 MB
    __half* eh = (__half*)h;
    __half* el = eh + (size_t)NROWS * DIM;

    const int ENC_SMEM = 2 * 32768;   // 64 KB
    const int SIM_SMEM = 3 * 24576;   // 72 KB
    cudaFuncSetAttribute(gemm_rect, cudaFuncAttributeMaxDynamicSharedMemorySize,
                         ENC_SMEM);
    cudaFuncSetAttribute(sim_tc_kernel, cudaFuncAttributeMaxDynamicSharedMemorySize,
                         SIM_SMEM);

    const int SPLIT_BLK = (NROWS * (DIM / 4)) / 256;

    // 1) split S (bf16); transpose+split W1
    split_kernel<<<SPLIT_BLK, 256>>>(S, hi, lo);
    transpose_split_kernel<<<dim3(32, 32), dim3(32, 8)>>>(W1, wth, wtl);
    // 2) h = S @ W1 + b1
    gemm_rect<<<dim3(DIM / 128, NROWS / 128), 256, ENC_SMEM>>>(
        hi, lo, wth, wtl, h, DIM, b1, DIM);
    // 3) LayerNorm + GELU + split (fused)
    ln_gelu_split_kernel<<<NROWS, 256>>>(h, gamma, beta, hi, lo);
    // 4) transpose+split W2
    transpose_split_kernel<<<dim3(32, 32), dim3(32, 8)>>>(W2, wth, wtl);
    // 5) enc = gelu(ln(h)) @ W2 + b2
    gemm_rect<<<dim3(DIM / 128, NROWS / 128), 256, ENC_SMEM>>>(
        hi, lo, wth, wtl, enc, DIM, b2, DIM);
    // 6) L2 normalize + fp16 split (h buffer now dead -> reuse for eh/el)
    l2norm_split_f16_kernel<<<NROWS, 256>>>(enc, eh, el);
    // 7) dup output init (if present)
    float* dup = nullptr;
    if (out_size >= NROWS * NROWS + NROWS) {
        dup = out + (size_t)NROWS * NROWS;
        zero_kernel<<<NROWS / 256, 256>>>(dup, NROWS);
    }
    // 8) sim lower-tri via fp16 2-pass; fused mirror + dup epilogue
    const int NT = NROWS / 128;
    sim_tc_kernel<<<NT * (NT + 1) / 2, 256, SIM_SMEM>>>(eh, el, out, dup);
}

// round 6
// speedup vs baseline: 6.6774x; 1.1869x over previous
#include <cuda_runtime.h>
#include <cuda_bf16.h>
#include <cuda_fp16.h>
#include <math.h>
#include <stdint.h>

#define NROWS 8192
#define DIM   1024
#define THR   0.85f

// Scratch (allocation-free: __device__ globals)
__device__ float g_h[(size_t)NROWS * DIM];              // 32 MB (reused: fp16 enc-hi)
__device__ float g_enc[(size_t)NROWS * DIM];            // 32 MB
__device__ __nv_bfloat16 g_hi[(size_t)NROWS * DIM];     // 16 MB
__device__ __nv_bfloat16 g_lo[(size_t)NROWS * DIM];     // 16 MB
__device__ __nv_bfloat16 g_wt_hi[(size_t)DIM * DIM];    // 2 MB
__device__ __nv_bfloat16 g_wt_lo[(size_t)DIM * DIM];    // 2 MB

// ===========================================================================
// sm_80-generic PTX helpers (base sm_103 target: no tcgen05)
// ===========================================================================
__device__ __forceinline__ uint32_t smem_u32(const void* p) {
    uint32_t a;
    asm("{ .reg .u64 t; cvta.to.shared.u64 t, %1; cvt.u32.u64 %0, t; }"
        : "=r"(a) : "l"(p));
    return a;
}
__device__ __forceinline__ void cp16(uint32_t dst, const void* src) {
    asm volatile("cp.async.cg.shared.global [%0], [%1], 16;"
                 :: "r"(dst), "l"(src));
}
__device__ __forceinline__ void ldsm_x4(uint32_t* r, uint32_t addr) {
    asm volatile("ldmatrix.sync.aligned.m8n8.x4.shared.b16 {%0,%1,%2,%3}, [%4];"
                 : "=r"(r[0]), "=r"(r[1]), "=r"(r[2]), "=r"(r[3]) : "r"(addr));
}
__device__ __forceinline__ void mma_bf16(float* c, const uint32_t* a,
                                         const uint32_t* b) {
    asm volatile("mma.sync.aligned.m16n8k16.row.col.f32.bf16.bf16.f32 "
                 "{%0,%1,%2,%3}, {%4,%5,%6,%7}, {%8,%9}, {%0,%1,%2,%3};"
                 : "+f"(c[0]), "+f"(c[1]), "+f"(c[2]), "+f"(c[3])
                 : "r"(a[0]), "r"(a[1]), "r"(a[2]), "r"(a[3]),
                   "r"(b[0]), "r"(b[1]));
}
__device__ __forceinline__ void mma_f16(float* c, const uint32_t* a,
                                        const uint32_t* b) {
    asm volatile("mma.sync.aligned.m16n8k16.row.col.f32.f16.f16.f32 "
                 "{%0,%1,%2,%3}, {%4,%5,%6,%7}, {%8,%9}, {%0,%1,%2,%3};"
                 : "+f"(c[0]), "+f"(c[1]), "+f"(c[2]), "+f"(c[3])
                 : "r"(a[0]), "r"(a[1]), "r"(a[2]), "r"(a[3]),
                   "r"(b[0]), "r"(b[1]));
}

// smem tile: 128 rows x 64B. 16B-chunk swizzle, conflict-free LDSM phases.
__device__ __forceinline__ uint32_t swz(uint32_t row, uint32_t chunk) {
    uint32_t c = chunk ^ (row & 3u) ^ ((row >> 2) & 1u);
    return row * 64u + c * 16u;
}

// ===========================================================================
// Encoder GEMM: bf16 hi/lo 3-pass (precision-locked). 2-stage cp.async.
// ===========================================================================
__global__ __launch_bounds__(256) void gemm_rect(
    const __nv_bfloat16* __restrict__ Ah, const __nv_bfloat16* __restrict__ Al,
    const __nv_bfloat16* __restrict__ Bh, const __nv_bfloat16* __restrict__ Bl,
    float* __restrict__ C, int ldc, const float* __restrict__ bias, int K) {
    extern __shared__ char sm[];
    const uint32_t sb = smem_u32(sm);

    const int rowBase = blockIdx.y * 128;
    const int colBase = blockIdx.x * 128;

    const int tid = threadIdx.x;
    const int wid = tid >> 5;
    const int lane = tid & 31;
    const int wm = (wid & 1) * 64;
    const int wn = (wid >> 1) * 32;

    const size_t rowB = (size_t)K * 2;
    const char* gAh = (const char*)Ah + (size_t)rowBase * rowB;
    const char* gAl = (const char*)Al + (size_t)rowBase * rowB;
    const char* gBh = (const char*)Bh + (size_t)colBase * rowB;
    const char* gBl = (const char*)Bl + (size_t)colBase * rowB;

    auto load_stage = [&](int st, int kc) {
        const char* bases[4] = {gAh, gAl, gBh, gBl};
#pragma unroll
        for (int t = 0; t < 4; t++) {
#pragma unroll
            for (int h = 0; h < 2; h++) {
                const int c = tid + h * 256;
                const uint32_t row = c >> 2, kch = c & 3;
                const uint32_t dst = sb + st * 32768u + t * 8192u + swz(row, kch);
                cp16(dst, bases[t] + (size_t)row * rowB + (size_t)kc * 64 + kch * 16);
            }
        }
    };

    float acc[4][4][4];
#pragma unroll
    for (int i = 0; i < 4; i++)
#pragma unroll
        for (int j = 0; j < 4; j++)
#pragma unroll
            for (int k = 0; k < 4; k++) acc[i][j][k] = 0.f;

    load_stage(0, 0);
    asm volatile("cp.async.commit_group;");
    load_stage(1, 1);
    asm volatile("cp.async.commit_group;");

    const int kcN = K / 32;
    for (int kc = 0; kc < kcN; kc++) {
        asm volatile("cp.async.wait_group 1;");
        __syncthreads();
        const int st = kc & 1;
        const uint32_t uAh = sb + st * 32768u;
        const uint32_t uAl = uAh + 8192u;
        const uint32_t uBh = uAh + 16384u;
        const uint32_t uBl = uAh + 24576u;

        uint32_t ah[4][4], al[4][4], bh[4][2], bl[4][2];
        const uint32_t arow0 = (uint32_t)(wm + (lane & 15));
        const uint32_t achb = (uint32_t)(lane >> 4);
        const uint32_t brow0 = (uint32_t)(wn + (lane & 7) + ((lane & 16) >> 1));
        const uint32_t bchb = (uint32_t)((lane >> 3) & 1);

#pragma unroll
        for (int ks = 0; ks < 2; ks++) {
#pragma unroll
            for (int mt = 0; mt < 4; mt++) {
                ldsm_x4(ah[mt], uAh + swz(arow0 + mt * 16, ks * 2u + achb));
                ldsm_x4(al[mt], uAl + swz(arow0 + mt * 16, ks * 2u + achb));
            }
#pragma unroll
            for (int p = 0; p < 2; p++) {
                uint32_t r[4];
                ldsm_x4(r, uBh + swz(brow0 + p * 16, ks * 2u + bchb));
                bh[p * 2][0] = r[0]; bh[p * 2][1] = r[1];
                bh[p * 2 + 1][0] = r[2]; bh[p * 2 + 1][1] = r[3];
                ldsm_x4(r, uBl + swz(brow0 + p * 16, ks * 2u + bchb));
                bl[p * 2][0] = r[0]; bl[p * 2][1] = r[1];
                bl[p * 2 + 1][0] = r[2]; bl[p * 2 + 1][1] = r[3];
            }
            if (ks == 1) {
                __syncthreads();
                if (kc + 2 < kcN) load_stage(st, kc + 2);
                asm volatile("cp.async.commit_group;");
            }
#pragma unroll
            for (int mt = 0; mt < 4; mt++)
#pragma unroll
                for (int nt = 0; nt < 4; nt++) {
                    mma_bf16(acc[mt][nt], ah[mt], bh[nt]);
                    mma_bf16(acc[mt][nt], ah[mt], bl[nt]);
                    mma_bf16(acc[mt][nt], al[mt], bh[nt]);
                }
        }
    }

    const int g = lane >> 2, tg = lane & 3;
#pragma unroll
    for (int mt = 0; mt < 4; mt++)
#pragma unroll
        for (int nt = 0; nt < 4; nt++) {
            const int r0 = rowBase + wm + mt * 16 + g;
            const int c0 = colBase + wn + nt * 8 + tg * 2;
            float2 v0, v1;
            v0.x = acc[mt][nt][0]; v0.y = acc[mt][nt][1];
            v1.x = acc[mt][nt][2]; v1.y = acc[mt][nt][3];
            const float bx = bias[c0], by = bias[c0 + 1];
            v0.x += bx; v0.y += by; v1.x += bx; v1.y += by;
            *(float2*)&C[(size_t)r0 * ldc + c0] = v0;
            *(float2*)&C[(size_t)(r0 + 8) * ldc + c0] = v1;
        }
}

// ===========================================================================
// Sim GEMM: fp16 1-pass (hi x hi), lower-tri 128x128 tiles, 3-stage pipeline
// (A,B hi = 16KB/stage). Epilogue stages tile in smem (stride 129) and writes
// BOTH out[r][c] and mirrored out[c][r] fully coalesced; sets dup[r] on >THR.
// ===========================================================================
__global__ __launch_bounds__(256) void sim_tc_kernel(
    const __half* __restrict__ E,
    float* __restrict__ out, float* __restrict__ dup) {
    extern __shared__ char sm[];
    const uint32_t sb = smem_u32(sm);

    const int b = blockIdx.x;
    int bi = (int)((sqrtf(8.f * b + 1.f) - 1.f) * 0.5f);
    while ((bi + 1) * (bi + 2) / 2 <= b) bi++;
    while (bi * (bi + 1) / 2 > b) bi--;
    const int bj = b - bi * (bi + 1) / 2;
    const int rowBase = bi * 128;
    const int colBase = bj * 128;
    const bool diag = (rowBase == colBase);

    const int tid = threadIdx.x;
    const int wid = tid >> 5;
    const int lane = tid & 31;
    const int wm = (wid & 1) * 64;
    const int wn = (wid >> 1) * 32;

    const char* gA = (const char*)E + (size_t)rowBase * 2048;
    const char* gB = (const char*)E + (size_t)colBase * 2048;

    auto load_stage = [&](int st, int kc) {
        const char* bases[2] = {gA, gB};
#pragma unroll
        for (int t = 0; t < 2; t++) {
#pragma unroll
            for (int h = 0; h < 2; h++) {
                const int c = tid + h * 256;
                const uint32_t row = c >> 2, kch = c & 3;
                const uint32_t dst = sb + st * 16384u + t * 8192u + swz(row, kch);
                cp16(dst, bases[t] + (size_t)row * 2048 + (size_t)kc * 64 + kch * 16);
            }
        }
    };

    float acc[4][4][4];
#pragma unroll
    for (int i = 0; i < 4; i++)
#pragma unroll
        for (int j = 0; j < 4; j++)
#pragma unroll
            for (int k = 0; k < 4; k++) acc[i][j][k] = 0.f;

    load_stage(0, 0);
    asm volatile("cp.async.commit_group;");
    load_stage(1, 1);
    asm volatile("cp.async.commit_group;");
    load_stage(2, 2);
    asm volatile("cp.async.commit_group;");

    int st = 0;
    for (int kc = 0; kc < 32; kc++) {
        asm volatile("cp.async.wait_group 2;");
        __syncthreads();
        const uint32_t uA = sb + st * 16384u;
        const uint32_t uB = uA + 8192u;

        uint32_t ah[4][4], bh[4][2];
        const uint32_t arow0 = (uint32_t)(wm + (lane & 15));
        const uint32_t achb = (uint32_t)(lane >> 4);
        const uint32_t brow0 = (uint32_t)(wn + (lane & 7) + ((lane & 16) >> 1));
        const uint32_t bchb = (uint32_t)((lane >> 3) & 1);

#pragma unroll
        for (int ks = 0; ks < 2; ks++) {
#pragma unroll
            for (int mt = 0; mt < 4; mt++)
                ldsm_x4(ah[mt], uA + swz(arow0 + mt * 16, ks * 2u + achb));
#pragma unroll
            for (int p = 0; p < 2; p++) {
                uint32_t r[4];
                ldsm_x4(r, uB + swz(brow0 + p * 16, ks * 2u + bchb));
                bh[p * 2][0] = r[0]; bh[p * 2][1] = r[1];
                bh[p * 2 + 1][0] = r[2]; bh[p * 2 + 1][1] = r[3];
            }
            if (ks == 1) {
                __syncthreads();
                if (kc + 3 < 32) load_stage(st, kc + 3);
                asm volatile("cp.async.commit_group;");
            }
#pragma unroll
            for (int mt = 0; mt < 4; mt++)
#pragma unroll
                for (int nt = 0; nt < 4; nt++)
                    mma_f16(acc[mt][nt], ah[mt], bh[nt]);
        }
        st = (st == 2) ? 0 : st + 1;
    }

    // ---- epilogue: stage fp32 tile in smem, coalesced dual-store ----
    asm volatile("cp.async.wait_group 0;");
    __syncthreads();
    float* tile = (float*)sm;  // [128][stride 129] = 66048 B

    const int g = lane >> 2, tg = lane & 3;
#pragma unroll
    for (int mt = 0; mt < 4; mt++)
#pragma unroll
        for (int nt = 0; nt < 4; nt++) {
            const int cl = wn + nt * 8 + tg * 2;
#pragma unroll
            for (int hf = 0; hf < 2; hf++) {
                const int rl = wm + mt * 16 + g + hf * 8;
                tile[rl * 129 + cl] = acc[mt][nt][hf * 2 + 0];
                tile[rl * 129 + cl + 1] = acc[mt][nt][hf * 2 + 1];
            }
        }
    __syncthreads();

    // normal store: lanes sweep columns (coalesced); bank = (r+c)%32 clean
    for (int it = tid; it < 16384; it += 256) {
        const int r = it >> 7, c = it & 127;
        const float v = tile[r * 129 + c];
        if (!diag || r >= c) {
            out[(size_t)(rowBase + r) * NROWS + colBase + c] = v;
            if (dup && v > THR && (!diag || r > c)) dup[rowBase + r] = 1.0f;
        }
    }
    // mirror store: lanes sweep rows of the transpose (coalesced)
    for (int it = tid; it < 16384; it += 256) {
        const int c = it >> 7, r = it & 127;
        if (!diag || r > c)
            out[(size_t)(colBase + c) * NROWS + rowBase + r] = tile[r * 129 + c];
    }
}

// ===========================================================================
// Transpose + bf16 hi/lo split: Wt[n,k] = split(W[k,n])
// ===========================================================================
__global__ __launch_bounds__(256) void transpose_split_kernel(
    const float* __restrict__ W,
    __nv_bfloat16* __restrict__ Wth, __nv_bfloat16* __restrict__ Wtl) {
    __shared__ float t[32][33];
    const int n0 = blockIdx.x * 32, k0 = blockIdx.y * 32;
    const int x = threadIdx.x, ty = threadIdx.y;
#pragma unroll
    for (int yy = ty; yy < 32; yy += 8)
        t[yy][x] = W[(size_t)(k0 + yy) * DIM + n0 + x];
    __syncthreads();
#pragma unroll
    for (int yy = ty; yy < 32; yy += 8) {
        const float v = t[x][yy];
        const __nv_bfloat16 h = __float2bfloat16(v);
        const __nv_bfloat16 l = __float2bfloat16(v - __bfloat162float(h));
        const size_t o = (size_t)(n0 + yy) * DIM + k0 + x;
        Wth[o] = h;
        Wtl[o] = l;
    }
}

// ===========================================================================
// Elementwise bf16 hi/lo split
// ===========================================================================
__global__ __launch_bounds__(256) void split_kernel(const float* __restrict__ e,
                                                    __nv_bfloat16* __restrict__ hi,
                                                    __nv_bfloat16* __restrict__ lo) {
    const size_t i = (size_t)blockIdx.x * blockDim.x + threadIdx.x;
    float4 x = ((const float4*)e)[i];
    float v[4] = {x.x, x.y, x.z, x.w};
    __nv_bfloat16 hh[4], ll[4];
#pragma unroll
    for (int k = 0; k < 4; k++) {
        hh[k] = __float2bfloat16(v[k]);
        ll[k] = __float2bfloat16(v[k] - __bfloat162float(hh[k]));
    }
    __nv_bfloat162 hp0, hp1, lp0, lp1;
    hp0.x = hh[0]; hp0.y = hh[1]; hp1.x = hh[2]; hp1.y = hh[3];
    lp0.x = ll[0]; lp0.y = ll[1]; lp1.x = ll[2]; lp1.y = ll[3];
    uint2 hv, lv;
    hv.x = *(uint32_t*)&hp0; hv.y = *(uint32_t*)&hp1;
    lv.x = *(uint32_t*)&lp0; lv.y = *(uint32_t*)&lp1;
    ((uint2*)hi)[i] = hv;
    ((uint2*)lo)[i] = lv;
}

// ===========================================================================
// LayerNorm + exact GELU + bf16 hi/lo split (fused, one block per row)
// ===========================================================================
__global__ __launch_bounds__(256) void ln_gelu_split_kernel(
    const float* __restrict__ h, const float* __restrict__ gamma,
    const float* __restrict__ beta,
    __nv_bfloat16* __restrict__ hi, __nv_bfloat16* __restrict__ lo) {
    const int row = blockIdx.x;
    const float* p = h + (size_t)row * DIM;
    const int t = threadIdx.x;

    float4 x = *(const float4*)&p[t * 4];
    float s1 = x.x + x.y + x.z + x.w;
    float s2 = x.x * x.x + x.y * x.y + x.z * x.z + x.w * x.w;
#pragma unroll
    for (int o = 16; o > 0; o >>= 1) {
        s1 += __shfl_xor_sync(0xffffffffu, s1, o);
        s2 += __shfl_xor_sync(0xffffffffu, s2, o);
    }
    __shared__ float r1[8], r2[8];
    if ((t & 31) == 0) { r1[t >> 5] = s1; r2[t >> 5] = s2; }
    __syncthreads();
    if (t < 32) {
        s1 = (t < 8) ? r1[t] : 0.f;
        s2 = (t < 8) ? r2[t] : 0.f;
#pragma unroll
        for (int o = 4; o > 0; o >>= 1) {
            s1 += __shfl_xor_sync(0xffffffffu, s1, o);
            s2 += __shfl_xor_sync(0xffffffffu, s2, o);
        }
        if (t == 0) { r1[0] = s1; r2[0] = s2; }
    }
    __syncthreads();
    const float mu = r1[0] * (1.f / DIM);
    const float var = r2[0] * (1.f / DIM) - mu * mu;
    const float rstd = rsqrtf(var + 1e-5f);

    const float4 g = *(const float4*)&gamma[t * 4];
    const float4 bb = *(const float4*)&beta[t * 4];
    float y[4] = { (x.x - mu) * rstd * g.x + bb.x,
                   (x.y - mu) * rstd * g.y + bb.y,
                   (x.z - mu) * rstd * g.z + bb.z,
                   (x.w - mu) * rstd * g.w + bb.w };
    float v[4];
#pragma unroll
    for (int i = 0; i < 4; i++)
        v[i] = 0.5f * y[i] * (1.f + erff(y[i] * 0.70710678118654752f));

    __nv_bfloat16 hh[4], ll[4];
#pragma unroll
    for (int i = 0; i < 4; i++) {
        hh[i] = __float2bfloat16(v[i]);
        ll[i] = __float2bfloat16(v[i] - __bfloat162float(hh[i]));
    }
    const size_t idx = (size_t)row * (DIM / 4) + t;
    __nv_bfloat162 hp0, hp1, lp0, lp1;
    hp0.x = hh[0]; hp0.y = hh[1]; hp1.x = hh[2]; hp1.y = hh[3];
    lp0.x = ll[0]; lp0.y = ll[1]; lp1.x = ll[2]; lp1.y = ll[3];
    uint2 hv, lv;
    hv.x = *(uint32_t*)&hp0; hv.y = *(uint32_t*)&hp1;
    lv.x = *(uint32_t*)&lp0; lv.y = *(uint32_t*)&lp1;
    ((uint2*)hi)[idx] = hv;
    ((uint2*)lo)[idx] = lv;
}

// ===========================================================================
// Row L2 normalize + fp16 (hi only) for the 1-pass sim GEMM
// ===========================================================================
__global__ __launch_bounds__(256) void l2norm_f16_kernel(
    const float* __restrict__ e, __half* __restrict__ hi) {
    const int row = blockIdx.x;
    const float* p = e + (size_t)row * DIM;
    const int t = threadIdx.x;

    float4 x = *(const float4*)&p[t * 4];
    float s2 = x.x * x.x + x.y * x.y + x.z * x.z + x.w * x.w;
#pragma unroll
    for (int o = 16; o > 0; o >>= 1) s2 += __shfl_xor_sync(0xffffffffu, s2, o);
    __shared__ float r2[8];
    if ((t & 31) == 0) r2[t >> 5] = s2;
    __syncthreads();
    if (t < 32) {
        s2 = (t < 8) ? r2[t] : 0.f;
#pragma unroll
        for (int o = 4; o > 0; o >>= 1) s2 += __shfl_xor_sync(0xffffffffu, s2, o);
        if (t == 0) r2[0] = s2;
    }
    __syncthreads();
    const float inv = 1.f / fmaxf(sqrtf(r2[0]), 1e-12f);

    __half2 hp0, hp1;
    hp0.x = __float2half(x.x * inv); hp0.y = __float2half(x.y * inv);
    hp1.x = __float2half(x.z * inv); hp1.y = __float2half(x.w * inv);
    uint2 hv;
    hv.x = *(uint32_t*)&hp0; hv.y = *(uint32_t*)&hp1;
    ((uint2*)hi)[(size_t)row * (DIM / 4) + t] = hv;
}

// ===========================================================================
__global__ void zero_kernel(float* __restrict__ p, int n) {
    const int i = blockIdx.x * blockDim.x + threadIdx.x;
    if (i < n) p[i] = 0.0f;
}

// ===========================================================================
extern "C" void kernel_launch(void* const* d_in, const int* in_sizes, int n_in,
                              void* d_out, int out_size) {
    const float* S     = (const float*)d_in[0];
    const float* W1    = (const float*)d_in[1];
    const float* b1    = (const float*)d_in[2];
    const float* gamma = (const float*)d_in[3];
    const float* beta  = (const float*)d_in[4];
    const float* W2    = (const float*)d_in[5];
    const float* b2    = (const float*)d_in[6];
    float* out = (float*)d_out;

    float *h, *enc;
    __nv_bfloat16 *hi, *lo, *wth, *wtl;
    cudaGetSymbolAddress((void**)&h, g_h);
    cudaGetSymbolAddress((void**)&enc, g_enc);
    cudaGetSymbolAddress((void**)&hi, g_hi);
    cudaGetSymbolAddress((void**)&lo, g_lo);
    cudaGetSymbolAddress((void**)&wth, g_wt_hi);
    cudaGetSymbolAddress((void**)&wtl, g_wt_lo);
    __half* eh = (__half*)h;  // h buffer dead after LN split -> reuse

    const int ENC_SMEM = 2 * 32768;    // 64 KB
    const int SIM_SMEM = 128 * 129 * 4;  // 66048 B (>= 3*16384 pipeline)
    cudaFuncSetAttribute(gemm_rect, cudaFuncAttributeMaxDynamicSharedMemorySize,
                         ENC_SMEM);
    cudaFuncSetAttribute(sim_tc_kernel, cudaFuncAttributeMaxDynamicSharedMemorySize,
                         SIM_SMEM);

    const int SPLIT_BLK = (NROWS * (DIM / 4)) / 256;

    // 1) split S (bf16); transpose+split W1
    split_kernel<<<SPLIT_BLK, 256>>>(S, hi, lo);
    transpose_split_kernel<<<dim3(32, 32), dim3(32, 8)>>>(W1, wth, wtl);
    // 2) h = S @ W1 + b1
    gemm_rect<<<dim3(DIM / 128, NROWS / 128), 256, ENC_SMEM>>>(
        hi, lo, wth, wtl, h, DIM, b1, DIM);
    // 3) LayerNorm + GELU + split (fused)
    ln_gelu_split_kernel<<<NROWS, 256>>>(h, gamma, beta, hi, lo);
    // 4) transpose+split W2
    transpose_split_kernel<<<dim3(32, 32), dim3(32, 8)>>>(W2, wth, wtl);
    // 5) enc = gelu(ln(h)) @ W2 + b2
    gemm_rect<<<dim3(DIM / 128, NROWS / 128), 256, ENC_SMEM>>>(
        hi, lo, wth, wtl, enc, DIM, b2, DIM);
    // 6) L2 normalize -> fp16 (h buffer reused)
    l2norm_f16_kernel<<<NROWS, 256>>>(enc, eh);
    // 7) dup init (if present)
    float* dup = nullptr;
    if (out_size >= NROWS * NROWS + NROWS) {
        dup = out + (size_t)NROWS * NROWS;
        zero_kernel<<<NROWS / 256, 256>>>(dup, NROWS);
    }
    // 8) sim lower-tri fp16 1-pass; smem-staged coalesced mirror + dup
    const int NT = NROWS / 128;
    sim_tc_kernel<<<NT * (NT + 1) / 2, 256, SIM_SMEM>>>(eh, out, dup);
}

// round 7
// speedup vs baseline: 8.3315x; 1.2477x over previous
#include <cuda_runtime.h>
#include <cuda_bf16.h>
#include <cuda_fp16.h>
#include <math.h>
#include <stdint.h>

#define NROWS 8192
#define DIM   1024
#define THR   0.85f

// Scratch (allocation-free: __device__ globals)
__device__ float g_h[(size_t)NROWS * DIM];              // 32 MB (h; later enc-fp16)
__device__ float g_enc[(size_t)NROWS * DIM];            // 32 MB
__device__ __nv_bfloat16 g_hi[(size_t)NROWS * DIM];     // 16 MB (act fp16 hi)
__device__ __nv_bfloat16 g_wt_hi[(size_t)DIM * DIM];    // 2 MB (Wt fp16 hi)
__device__ __nv_bfloat16 g_wt_lo[(size_t)DIM * DIM];    // 2 MB (Wt fp16 lo)

// ===========================================================================
// sm_80-generic PTX helpers (base sm_103 target: no tcgen05)
// ===========================================================================
__device__ __forceinline__ uint32_t smem_u32(const void* p) {
    uint32_t a;
    asm("{ .reg .u64 t; cvta.to.shared.u64 t, %1; cvt.u32.u64 %0, t; }"
        : "=r"(a) : "l"(p));
    return a;
}
__device__ __forceinline__ void cp16(uint32_t dst, const void* src) {
    asm volatile("cp.async.cg.shared.global [%0], [%1], 16;"
                 :: "r"(dst), "l"(src));
}
__device__ __forceinline__ void ldsm_x4(uint32_t* r, uint32_t addr) {
    asm volatile("ldmatrix.sync.aligned.m8n8.x4.shared.b16 {%0,%1,%2,%3}, [%4];"
                 : "=r"(r[0]), "=r"(r[1]), "=r"(r[2]), "=r"(r[3]) : "r"(addr));
}
__device__ __forceinline__ void mma_f16(float* c, const uint32_t* a,
                                        const uint32_t* b) {
    asm volatile("mma.sync.aligned.m16n8k16.row.col.f32.f16.f16.f32 "
                 "{%0,%1,%2,%3}, {%4,%5,%6,%7}, {%8,%9}, {%0,%1,%2,%3};"
                 : "+f"(c[0]), "+f"(c[1]), "+f"(c[2]), "+f"(c[3])
                 : "r"(a[0]), "r"(a[1]), "r"(a[2]), "r"(a[3]),
                   "r"(b[0]), "r"(b[1]));
}

// smem tile: 128 rows x 64B. 16B-chunk swizzle, conflict-free LDSM phases.
__device__ __forceinline__ uint32_t swz(uint32_t row, uint32_t chunk) {
    uint32_t c = chunk ^ (row & 3u) ^ ((row >> 2) & 1u);
    return row * 64u + c * 16u;
}

// ===========================================================================
// Encoder GEMM: fp16 2-pass (Ah*Bh + Ah*Bl), weights split, activations hi.
// 128x128 tile, 8 warps (2m x 4n), warp 64x32, BK=32, 3-stage cp.async
// (A, Bh, Bl = 24KB/stage). C[m,n] = sum_k A[m,k]*B[n,k] + bias[n].
// ===========================================================================
__global__ __launch_bounds__(256) void gemm_rect_f16(
    const __half* __restrict__ A,
    const __half* __restrict__ Bh, const __half* __restrict__ Bl,
    float* __restrict__ C, int ldc, const float* __restrict__ bias, int K) {
    extern __shared__ char sm[];
    const uint32_t sb = smem_u32(sm);

    const int rowBase = blockIdx.y * 128;
    const int colBase = blockIdx.x * 128;

    const int tid = threadIdx.x;
    const int wid = tid >> 5;
    const int lane = tid & 31;
    const int wm = (wid & 1) * 64;
    const int wn = (wid >> 1) * 32;

    const size_t rowB = (size_t)K * 2;
    const char* gA  = (const char*)A + (size_t)rowBase * rowB;
    const char* gBh = (const char*)Bh + (size_t)colBase * rowB;
    const char* gBl = (const char*)Bl + (size_t)colBase * rowB;

    auto load_stage = [&](int st, int kc) {
        const char* bases[3] = {gA, gBh, gBl};
#pragma unroll
        for (int t = 0; t < 3; t++) {
#pragma unroll
            for (int h = 0; h < 2; h++) {
                const int c = tid + h * 256;
                const uint32_t row = c >> 2, kch = c & 3;
                const uint32_t dst = sb + st * 24576u + t * 8192u + swz(row, kch);
                cp16(dst, bases[t] + (size_t)row * rowB + (size_t)kc * 64 + kch * 16);
            }
        }
    };

    float acc[4][4][4];
#pragma unroll
    for (int i = 0; i < 4; i++)
#pragma unroll
        for (int j = 0; j < 4; j++)
#pragma unroll
            for (int k = 0; k < 4; k++) acc[i][j][k] = 0.f;

    load_stage(0, 0);
    asm volatile("cp.async.commit_group;");
    load_stage(1, 1);
    asm volatile("cp.async.commit_group;");
    load_stage(2, 2);
    asm volatile("cp.async.commit_group;");

    const int kcN = K / 32;
    int st = 0;
    for (int kc = 0; kc < kcN; kc++) {
        asm volatile("cp.async.wait_group 2;");
        __syncthreads();
        const uint32_t uA  = sb + st * 24576u;
        const uint32_t uBh = uA + 8192u;
        const uint32_t uBl = uA + 16384u;

        uint32_t ah[4][4], bh[4][2], bl[4][2];
        const uint32_t arow0 = (uint32_t)(wm + (lane & 15));
        const uint32_t achb = (uint32_t)(lane >> 4);
        const uint32_t brow0 = (uint32_t)(wn + (lane & 7) + ((lane & 16) >> 1));
        const uint32_t bchb = (uint32_t)((lane >> 3) & 1);

#pragma unroll
        for (int ks = 0; ks < 2; ks++) {
#pragma unroll
            for (int mt = 0; mt < 4; mt++)
                ldsm_x4(ah[mt], uA + swz(arow0 + mt * 16, ks * 2u + achb));
#pragma unroll
            for (int p = 0; p < 2; p++) {
                uint32_t r[4];
                ldsm_x4(r, uBh + swz(brow0 + p * 16, ks * 2u + bchb));
                bh[p * 2][0] = r[0]; bh[p * 2][1] = r[1];
                bh[p * 2 + 1][0] = r[2]; bh[p * 2 + 1][1] = r[3];
                ldsm_x4(r, uBl + swz(brow0 + p * 16, ks * 2u + bchb));
                bl[p * 2][0] = r[0]; bl[p * 2][1] = r[1];
                bl[p * 2 + 1][0] = r[2]; bl[p * 2 + 1][1] = r[3];
            }
            if (ks == 1) {
                __syncthreads();
                if (kc + 3 < kcN) load_stage(st, kc + 3);
                asm volatile("cp.async.commit_group;");
            }
#pragma unroll
            for (int mt = 0; mt < 4; mt++)
#pragma unroll
                for (int nt = 0; nt < 4; nt++) {
                    mma_f16(acc[mt][nt], ah[mt], bh[nt]);
                    mma_f16(acc[mt][nt], ah[mt], bl[nt]);
                }
        }
        st = (st == 2) ? 0 : st + 1;
    }

    const int g = lane >> 2, tg = lane & 3;
#pragma unroll
    for (int mt = 0; mt < 4; mt++)
#pragma unroll
        for (int nt = 0; nt < 4; nt++) {
            const int r0 = rowBase + wm + mt * 16 + g;
            const int c0 = colBase + wn + nt * 8 + tg * 2;
            float2 v0, v1;
            v0.x = acc[mt][nt][0]; v0.y = acc[mt][nt][1];
            v1.x = acc[mt][nt][2]; v1.y = acc[mt][nt][3];
            const float bx = bias[c0], by = bias[c0 + 1];
            v0.x += bx; v0.y += by; v1.x += bx; v1.y += by;
            *(float2*)&C[(size_t)r0 * ldc + c0] = v0;
            *(float2*)&C[(size_t)(r0 + 8) * ldc + c0] = v1;
        }
}

// ===========================================================================
// Sim GEMM: fp16 1-pass, lower-tri 128x128 tiles, 3-stage pipeline. Epilogue
// stages fp32 tile in smem (stride 129), dual coalesced store + mirror + dup.
// (unchanged from round 6 — proven)
// ===========================================================================
__global__ __launch_bounds__(256) void sim_tc_kernel(
    const __half* __restrict__ E,
    float* __restrict__ out, float* __restrict__ dup) {
    extern __shared__ char sm[];
    const uint32_t sb = smem_u32(sm);

    const int b = blockIdx.x;
    int bi = (int)((sqrtf(8.f * b + 1.f) - 1.f) * 0.5f);
    while ((bi + 1) * (bi + 2) / 2 <= b) bi++;
    while (bi * (bi + 1) / 2 > b) bi--;
    const int bj = b - bi * (bi + 1) / 2;
    const int rowBase = bi * 128;
    const int colBase = bj * 128;
    const bool diag = (rowBase == colBase);

    const int tid = threadIdx.x;
    const int wid = tid >> 5;
    const int lane = tid & 31;
    const int wm = (wid & 1) * 64;
    const int wn = (wid >> 1) * 32;

    const char* gA = (const char*)E + (size_t)rowBase * 2048;
    const char* gB = (const char*)E + (size_t)colBase * 2048;

    auto load_stage = [&](int st, int kc) {
        const char* bases[2] = {gA, gB};
#pragma unroll
        for (int t = 0; t < 2; t++) {
#pragma unroll
            for (int h = 0; h < 2; h++) {
                const int c = tid + h * 256;
                const uint32_t row = c >> 2, kch = c & 3;
                const uint32_t dst = sb + st * 16384u + t * 8192u + swz(row, kch);
                cp16(dst, bases[t] + (size_t)row * 2048 + (size_t)kc * 64 + kch * 16);
            }
        }
    };

    float acc[4][4][4];
#pragma unroll
    for (int i = 0; i < 4; i++)
#pragma unroll
        for (int j = 0; j < 4; j++)
#pragma unroll
            for (int k = 0; k < 4; k++) acc[i][j][k] = 0.f;

    load_stage(0, 0);
    asm volatile("cp.async.commit_group;");
    load_stage(1, 1);
    asm volatile("cp.async.commit_group;");
    load_stage(2, 2);
    asm volatile("cp.async.commit_group;");

    int st = 0;
    for (int kc = 0; kc < 32; kc++) {
        asm volatile("cp.async.wait_group 2;");
        __syncthreads();
        const uint32_t uA = sb + st * 16384u;
        const uint32_t uB = uA + 8192u;

        uint32_t ah[4][4], bh[4][2];
        const uint32_t arow0 = (uint32_t)(wm + (lane & 15));
        const uint32_t achb = (uint32_t)(lane >> 4);
        const uint32_t brow0 = (uint32_t)(wn + (lane & 7) + ((lane & 16) >> 1));
        const uint32_t bchb = (uint32_t)((lane >> 3) & 1);

#pragma unroll
        for (int ks = 0; ks < 2; ks++) {
#pragma unroll
            for (int mt = 0; mt < 4; mt++)
                ldsm_x4(ah[mt], uA + swz(arow0 + mt * 16, ks * 2u + achb));
#pragma unroll
            for (int p = 0; p < 2; p++) {
                uint32_t r[4];
                ldsm_x4(r, uB + swz(brow0 + p * 16, ks * 2u + bchb));
                bh[p * 2][0] = r[0]; bh[p * 2][1] = r[1];
                bh[p * 2 + 1][0] = r[2]; bh[p * 2 + 1][1] = r[3];
            }
            if (ks == 1) {
                __syncthreads();
                if (kc + 3 < 32) load_stage(st, kc + 3);
                asm volatile("cp.async.commit_group;");
            }
#pragma unroll
            for (int mt = 0; mt < 4; mt++)
#pragma unroll
                for (int nt = 0; nt < 4; nt++)
                    mma_f16(acc[mt][nt], ah[mt], bh[nt]);
        }
        st = (st == 2) ? 0 : st + 1;
    }

    asm volatile("cp.async.wait_group 0;");
    __syncthreads();
    float* tile = (float*)sm;  // [128][129]

    const int g = lane >> 2, tg = lane & 3;
#pragma unroll
    for (int mt = 0; mt < 4; mt++)
#pragma unroll
        for (int nt = 0; nt < 4; nt++) {
            const int cl = wn + nt * 8 + tg * 2;
#pragma unroll
            for (int hf = 0; hf < 2; hf++) {
                const int rl = wm + mt * 16 + g + hf * 8;
                tile[rl * 129 + cl] = acc[mt][nt][hf * 2 + 0];
                tile[rl * 129 + cl + 1] = acc[mt][nt][hf * 2 + 1];
            }
        }
    __syncthreads();

    for (int it = tid; it < 16384; it += 256) {
        const int r = it >> 7, c = it & 127;
        const float v = tile[r * 129 + c];
        if (!diag || r >= c) {
            out[(size_t)(rowBase + r) * NROWS + colBase + c] = v;
            if (dup && v > THR && (!diag || r > c)) dup[rowBase + r] = 1.0f;
        }
    }
    for (int it = tid; it < 16384; it += 256) {
        const int c = it >> 7, r = it & 127;
        if (!diag || r > c)
            out[(size_t)(colBase + c) * NROWS + rowBase + r] = tile[r * 129 + c];
    }
}

// ===========================================================================
// Transpose + fp16 hi/lo split of weights: Wt[n,k] = split(W[k,n])
// ===========================================================================
__global__ __launch_bounds__(256) void transpose_split_f16_kernel(
    const float* __restrict__ W,
    __half* __restrict__ Wth, __half* __restrict__ Wtl) {
    __shared__ float t[32][33];
    const int n0 = blockIdx.x * 32, k0 = blockIdx.y * 32;
    const int x = threadIdx.x, ty = threadIdx.y;
#pragma unroll
    for (int yy = ty; yy < 32; yy += 8)
        t[yy][x] = W[(size_t)(k0 + yy) * DIM + n0 + x];
    __syncthreads();
#pragma unroll
    for (int yy = ty; yy < 32; yy += 8) {
        const float v = t[x][yy];
        const __half h = __float2half(v);
        const __half l = __float2half(v - __half2float(h));
        const size_t o = (size_t)(n0 + yy) * DIM + k0 + x;
        Wth[o] = h;
        Wtl[o] = l;
    }
}

// ===========================================================================
// Elementwise fp16 convert (hi only)
// ===========================================================================
__global__ __launch_bounds__(256) void split_f16_kernel(
    const float* __restrict__ e, __half* __restrict__ hi) {
    const size_t i = (size_t)blockIdx.x * blockDim.x + threadIdx.x;
    float4 x = ((const float4*)e)[i];
    __half2 hp0, hp1;
    hp0.x = __float2half(x.x); hp0.y = __float2half(x.y);
    hp1.x = __float2half(x.z); hp1.y = __float2half(x.w);
    uint2 hv;
    hv.x = *(uint32_t*)&hp0; hv.y = *(uint32_t*)&hp1;
    ((uint2*)hi)[i] = hv;
}

// ===========================================================================
// LayerNorm + exact GELU + fp16 (hi only) store
// ===========================================================================
__global__ __launch_bounds__(256) void ln_gelu_f16_kernel(
    const float* __restrict__ h, const float* __restrict__ gamma,
    const float* __restrict__ beta, __half* __restrict__ hi) {
    const int row = blockIdx.x;
    const float* p = h + (size_t)row * DIM;
    const int t = threadIdx.x;

    float4 x = *(const float4*)&p[t * 4];
    float s1 = x.x + x.y + x.z + x.w;
    float s2 = x.x * x.x + x.y * x.y + x.z * x.z + x.w * x.w;
#pragma unroll
    for (int o = 16; o > 0; o >>= 1) {
        s1 += __shfl_xor_sync(0xffffffffu, s1, o);
        s2 += __shfl_xor_sync(0xffffffffu, s2, o);
    }
    __shared__ float r1[8], r2[8];
    if ((t & 31) == 0) { r1[t >> 5] = s1; r2[t >> 5] = s2; }
    __syncthreads();
    if (t < 32) {
        s1 = (t < 8) ? r1[t] : 0.f;
        s2 = (t < 8) ? r2[t] : 0.f;
#pragma unroll
        for (int o = 4; o > 0; o >>= 1) {
            s1 += __shfl_xor_sync(0xffffffffu, s1, o);
            s2 += __shfl_xor_sync(0xffffffffu, s2, o);
        }
        if (t == 0) { r1[0] = s1; r2[0] = s2; }
    }
    __syncthreads();
    const float mu = r1[0] * (1.f / DIM);
    const float var = r2[0] * (1.f / DIM) - mu * mu;
    const float rstd = rsqrtf(var + 1e-5f);

    const float4 g = *(const float4*)&gamma[t * 4];
    const float4 bb = *(const float4*)&beta[t * 4];
    float y[4] = { (x.x - mu) * rstd * g.x + bb.x,
                   (x.y - mu) * rstd * g.y + bb.y,
                   (x.z - mu) * rstd * g.z + bb.z,
                   (x.w - mu) * rstd * g.w + bb.w };
    float v[4];
#pragma unroll
    for (int i = 0; i < 4; i++)
        v[i] = 0.5f * y[i] * (1.f + erff(y[i] * 0.70710678118654752f));

    __half2 hp0, hp1;
    hp0.x = __float2half(v[0]); hp0.y = __float2half(v[1]);
    hp1.x = __float2half(v[2]); hp1.y = __float2half(v[3]);
    uint2 hv;
    hv.x = *(uint32_t*)&hp0; hv.y = *(uint32_t*)&hp1;
    ((uint2*)hi)[(size_t)row * (DIM / 4) + t] = hv;
}

// ===========================================================================
// Row L2 normalize -> fp16
// ===========================================================================
__global__ __launch_bounds__(256) void l2norm_f16_kernel(
    const float* __restrict__ e, __half* __restrict__ hi) {
    const int row = blockIdx.x;
    const float* p = e + (size_t)row * DIM;
    const int t = threadIdx.x;

    float4 x = *(const float4*)&p[t * 4];
    float s2 = x.x * x.x + x.y * x.y + x.z * x.z + x.w * x.w;
#pragma unroll
    for (int o = 16; o > 0; o >>= 1) s2 += __shfl_xor_sync(0xffffffffu, s2, o);
    __shared__ float r2[8];
    if ((t & 31) == 0) r2[t >> 5] = s2;
    __syncthreads();
    if (t < 32) {
        s2 = (t < 8) ? r2[t] : 0.f;
#pragma unroll
        for (int o = 4; o > 0; o >>= 1) s2 += __shfl_xor_sync(0xffffffffu, s2, o);
        if (t == 0) r2[0] = s2;
    }
    __syncthreads();
    const float inv = 1.f / fmaxf(sqrtf(r2[0]), 1e-12f);

    __half2 hp0, hp1;
    hp0.x = __float2half(x.x * inv); hp0.y = __float2half(x.y * inv);
    hp1.x = __float2half(x.z * inv); hp1.y = __float2half(x.w * inv);
    uint2 hv;
    hv.x = *(uint32_t*)&hp0; hv.y = *(uint32_t*)&hp1;
    ((uint2*)hi)[(size_t)row * (DIM / 4) + t] = hv;
}

// ===========================================================================
__global__ void zero_kernel(float* __restrict__ p, int n) {
    const int i = blockIdx.x * blockDim.x + threadIdx.x;
    if (i < n) p[i] = 0.0f;
}

// ===========================================================================
extern "C" void kernel_launch(void* const* d_in, const int* in_sizes, int n_in,
                              void* d_out, int out_size) {
    const float* S     = (const float*)d_in[0];
    const float* W1    = (const float*)d_in[1];
    const float* b1    = (const float*)d_in[2];
    const float* gamma = (const float*)d_in[3];
    const float* beta  = (const float*)d_in[4];
    const float* W2    = (const float*)d_in[5];
    const float* b2    = (const float*)d_in[6];
    float* out = (float*)d_out;

    float *h, *enc;
    __nv_bfloat16 *hib, *wthb, *wtlb;
    cudaGetSymbolAddress((void**)&h, g_h);
    cudaGetSymbolAddress((void**)&enc, g_enc);
    cudaGetSymbolAddress((void**)&hib, g_hi);
    cudaGetSymbolAddress((void**)&wthb, g_wt_hi);
    cudaGetSymbolAddress((void**)&wtlb, g_wt_lo);
    __half* act = (__half*)hib;   // activation fp16 (S-hi, then gelu-hi)
    __half* wth = (__half*)wthb;
    __half* wtl = (__half*)wtlb;
    __half* eh  = (__half*)h;     // h dead after ln_gelu -> enc fp16

    const int ENC_SMEM = 3 * 24576;      // 72 KB
    const int SIM_SMEM = 128 * 129 * 4;  // 66048 B (>= 3*16384)
    cudaFuncSetAttribute(gemm_rect_f16, cudaFuncAttributeMaxDynamicSharedMemorySize,
                         ENC_SMEM);
    cudaFuncSetAttribute(sim_tc_kernel, cudaFuncAttributeMaxDynamicSharedMemorySize,
                         SIM_SMEM);

    const int SPLIT_BLK = (NROWS * (DIM / 4)) / 256;

    // 1) S -> fp16; W1 -> Wt fp16 hi/lo
    split_f16_kernel<<<SPLIT_BLK, 256>>>(S, act);
    transpose_split_f16_kernel<<<dim3(32, 32), dim3(32, 8)>>>(W1, wth, wtl);
    // 2) h = S @ W1 + b1  (fp16 2-pass)
    gemm_rect_f16<<<dim3(DIM / 128, NROWS / 128), 256, ENC_SMEM>>>(
        act, wth, wtl, h, DIM, b1, DIM);
    // 3) LayerNorm + GELU -> fp16 (act buffer reused; S dead)
    ln_gelu_f16_kernel<<<NROWS, 256>>>(h, gamma, beta, act);
    // 4) W2 -> Wt fp16 hi/lo
    transpose_split_f16_kernel<<<dim3(32, 32), dim3(32, 8)>>>(W2, wth, wtl);
    // 5) enc = gelu(ln(h)) @ W2 + b2  (fp16 2-pass)
    gemm_rect_f16<<<dim3(DIM / 128, NROWS / 128), 256, ENC_SMEM>>>(
        act, wth, wtl, enc, DIM, b2, DIM);
    // 6) L2 normalize -> fp16 (h buffer reused)
    l2norm_f16_kernel<<<NROWS, 256>>>(enc, eh);
    // 7) dup init (if present)
    float* dup = nullptr;
    if (out_size >= NROWS * NROWS + NROWS) {
        dup = out + (size_t)NROWS * NROWS;
        zero_kernel<<<NROWS / 256, 256>>>(dup, NROWS);
    }
    // 8) sim lower-tri fp16 1-pass; smem-staged coalesced mirror + dup
    const int NT = NROWS / 128;
    sim_tc_kernel<<<NT * (NT + 1) / 2, 256, SIM_SMEM>>>(eh, out, dup);
}

// round 8
// speedup vs baseline: 9.6295x; 1.1558x over previous
#include <cuda_runtime.h>
#include <cuda_bf16.h>
#include <cuda_fp16.h>
#include <math.h>
#include <stdint.h>

#define NROWS 8192
#define DIM   1024
#define THR   0.85f

// Scratch (allocation-free: __device__ globals)
__device__ float g_h[(size_t)NROWS * DIM];              // 32 MB (h; later enc-fp16)
__device__ float g_enc[(size_t)NROWS * DIM];            // 32 MB
__device__ __nv_bfloat16 g_hi[(size_t)NROWS * DIM];     // 16 MB (act fp16)
__device__ __nv_bfloat16 g_wt_hi[(size_t)DIM * DIM];    // 2 MB (Wt fp16)

// ===========================================================================
// sm_80-generic PTX helpers (base sm_103 target: no tcgen05)
// ===========================================================================
__device__ __forceinline__ uint32_t smem_u32(const void* p) {
    uint32_t a;
    asm("{ .reg .u64 t; cvta.to.shared.u64 t, %1; cvt.u32.u64 %0, t; }"
        : "=r"(a) : "l"(p));
    return a;
}
__device__ __forceinline__ void cp16(uint32_t dst, const void* src) {
    asm volatile("cp.async.cg.shared.global [%0], [%1], 16;"
                 :: "r"(dst), "l"(src));
}
__device__ __forceinline__ void ldsm_x4(uint32_t* r, uint32_t addr) {
    asm volatile("ldmatrix.sync.aligned.m8n8.x4.shared.b16 {%0,%1,%2,%3}, [%4];"
                 : "=r"(r[0]), "=r"(r[1]), "=r"(r[2]), "=r"(r[3]) : "r"(addr));
}
__device__ __forceinline__ void mma_f16(float* c, const uint32_t* a,
                                        const uint32_t* b) {
    asm volatile("mma.sync.aligned.m16n8k16.row.col.f32.f16.f16.f32 "
                 "{%0,%1,%2,%3}, {%4,%5,%6,%7}, {%8,%9}, {%0,%1,%2,%3};"
                 : "+f"(c[0]), "+f"(c[1]), "+f"(c[2]), "+f"(c[3])
                 : "r"(a[0]), "r"(a[1]), "r"(a[2]), "r"(a[3]),
                   "r"(b[0]), "r"(b[1]));
}

// smem tile: 128 rows x 64B. 16B-chunk swizzle, conflict-free LDSM phases.
__device__ __forceinline__ uint32_t swz(uint32_t row, uint32_t chunk) {
    uint32_t c = chunk ^ (row & 3u) ^ ((row >> 2) & 1u);
    return row * 64u + c * 16u;
}

// ===========================================================================
// Encoder GEMM: fp16 1-pass. C[m,n] = sum_k A[m,k]*B[n,k] + bias[n].
// 128x128 tile, 8 warps (2m x 4n), warp 64x32, BK=32, 3-stage cp.async
// (A, B = 16KB/stage).
// ===========================================================================
__global__ __launch_bounds__(256) void gemm_rect_1p(
    const __half* __restrict__ A, const __half* __restrict__ B,
    float* __restrict__ C, int ldc, const float* __restrict__ bias, int K) {
    extern __shared__ char sm[];
    const uint32_t sb = smem_u32(sm);

    const int rowBase = blockIdx.y * 128;
    const int colBase = blockIdx.x * 128;

    const int tid = threadIdx.x;
    const int wid = tid >> 5;
    const int lane = tid & 31;
    const int wm = (wid & 1) * 64;
    const int wn = (wid >> 1) * 32;

    const size_t rowB = (size_t)K * 2;
    const char* gA = (const char*)A + (size_t)rowBase * rowB;
    const char* gB = (const char*)B + (size_t)colBase * rowB;

    auto load_stage = [&](int st, int kc) {
        const char* bases[2] = {gA, gB};
#pragma unroll
        for (int t = 0; t < 2; t++) {
#pragma unroll
            for (int h = 0; h < 2; h++) {
                const int c = tid + h * 256;
                const uint32_t row = c >> 2, kch = c & 3;
                const uint32_t dst = sb + st * 16384u + t * 8192u + swz(row, kch);
                cp16(dst, bases[t] + (size_t)row * rowB + (size_t)kc * 64 + kch * 16);
            }
        }
    };

    float acc[4][4][4];
#pragma unroll
    for (int i = 0; i < 4; i++)
#pragma unroll
        for (int j = 0; j < 4; j++)
#pragma unroll
            for (int k = 0; k < 4; k++) acc[i][j][k] = 0.f;

    load_stage(0, 0);
    asm volatile("cp.async.commit_group;");
    load_stage(1, 1);
    asm volatile("cp.async.commit_group;");
    load_stage(2, 2);
    asm volatile("cp.async.commit_group;");

    const int kcN = K / 32;
    int st = 0;
    for (int kc = 0; kc < kcN; kc++) {
        asm volatile("cp.async.wait_group 2;");
        __syncthreads();
        const uint32_t uA = sb + st * 16384u;
        const uint32_t uB = uA + 8192u;

        uint32_t ah[4][4], bh[4][2];
        const uint32_t arow0 = (uint32_t)(wm + (lane & 15));
        const uint32_t achb = (uint32_t)(lane >> 4);
        const uint32_t brow0 = (uint32_t)(wn + (lane & 7) + ((lane & 16) >> 1));
        const uint32_t bchb = (uint32_t)((lane >> 3) & 1);

#pragma unroll
        for (int ks = 0; ks < 2; ks++) {
#pragma unroll
            for (int mt = 0; mt < 4; mt++)
                ldsm_x4(ah[mt], uA + swz(arow0 + mt * 16, ks * 2u + achb));
#pragma unroll
            for (int p = 0; p < 2; p++) {
                uint32_t r[4];
                ldsm_x4(r, uB + swz(brow0 + p * 16, ks * 2u + bchb));
                bh[p * 2][0] = r[0]; bh[p * 2][1] = r[1];
                bh[p * 2 + 1][0] = r[2]; bh[p * 2 + 1][1] = r[3];
            }
            if (ks == 1) {
                __syncthreads();
                if (kc + 3 < kcN) load_stage(st, kc + 3);
                asm volatile("cp.async.commit_group;");
            }
#pragma unroll
            for (int mt = 0; mt < 4; mt++)
#pragma unroll
                for (int nt = 0; nt < 4; nt++)
                    mma_f16(acc[mt][nt], ah[mt], bh[nt]);
        }
        st = (st == 2) ? 0 : st + 1;
    }

    const int g = lane >> 2, tg = lane & 3;
#pragma unroll
    for (int mt = 0; mt < 4; mt++)
#pragma unroll
        for (int nt = 0; nt < 4; nt++) {
            const int r0 = rowBase + wm + mt * 16 + g;
            const int c0 = colBase + wn + nt * 8 + tg * 2;
            float2 v0, v1;
            v0.x = acc[mt][nt][0]; v0.y = acc[mt][nt][1];
            v1.x = acc[mt][nt][2]; v1.y = acc[mt][nt][3];
            const float bx = bias[c0], by = bias[c0 + 1];
            v0.x += bx; v0.y += by; v1.x += bx; v1.y += by;
            *(float2*)&C[(size_t)r0 * ldc + c0] = v0;
            *(float2*)&C[(size_t)(r0 + 8) * ldc + c0] = v1;
        }
}

// ===========================================================================
// Sim GEMM: fp16 1-pass, lower-tri 128x128 tiles, 3-stage pipeline. Epilogue
// stages fp32 tile in smem (stride 129), dual coalesced store + mirror + dup.
// (proven)
// ===========================================================================
__global__ __launch_bounds__(256) void sim_tc_kernel(
    const __half* __restrict__ E,
    float* __restrict__ out, float* __restrict__ dup) {
    extern __shared__ char sm[];
    const uint32_t sb = smem_u32(sm);

    const int b = blockIdx.x;
    int bi = (int)((sqrtf(8.f * b + 1.f) - 1.f) * 0.5f);
    while ((bi + 1) * (bi + 2) / 2 <= b) bi++;
    while (bi * (bi + 1) / 2 > b) bi--;
    const int bj = b - bi * (bi + 1) / 2;
    const int rowBase = bi * 128;
    const int colBase = bj * 128;
    const bool diag = (rowBase == colBase);

    const int tid = threadIdx.x;
    const int wid = tid >> 5;
    const int lane = tid & 31;
    const int wm = (wid & 1) * 64;
    const int wn = (wid >> 1) * 32;

    const char* gA = (const char*)E + (size_t)rowBase * 2048;
    const char* gB = (const char*)E + (size_t)colBase * 2048;

    auto load_stage = [&](int st, int kc) {
        const char* bases[2] = {gA, gB};
#pragma unroll
        for (int t = 0; t < 2; t++) {
#pragma unroll
            for (int h = 0; h < 2; h++) {
                const int c = tid + h * 256;
                const uint32_t row = c >> 2, kch = c & 3;
                const uint32_t dst = sb + st * 16384u + t * 8192u + swz(row, kch);
                cp16(dst, bases[t] + (size_t)row * 2048 + (size_t)kc * 64 + kch * 16);
            }
        }
    };

    float acc[4][4][4];
#pragma unroll
    for (int i = 0; i < 4; i++)
#pragma unroll
        for (int j = 0; j < 4; j++)
#pragma unroll
            for (int k = 0; k < 4; k++) acc[i][j][k] = 0.f;

    load_stage(0, 0);
    asm volatile("cp.async.commit_group;");
    load_stage(1, 1);
    asm volatile("cp.async.commit_group;");
    load_stage(2, 2);
    asm volatile("cp.async.commit_group;");

    int st = 0;
    for (int kc = 0; kc < 32; kc++) {
        asm volatile("cp.async.wait_group 2;");
        __syncthreads();
        const uint32_t uA = sb + st * 16384u;
        const uint32_t uB = uA + 8192u;

        uint32_t ah[4][4], bh[4][2];
        const uint32_t arow0 = (uint32_t)(wm + (lane & 15));
        const uint32_t achb = (uint32_t)(lane >> 4);
        const uint32_t brow0 = (uint32_t)(wn + (lane & 7) + ((lane & 16) >> 1));
        const uint32_t bchb = (uint32_t)((lane >> 3) & 1);

#pragma unroll
        for (int ks = 0; ks < 2; ks++) {
#pragma unroll
            for (int mt = 0; mt < 4; mt++)
                ldsm_x4(ah[mt], uA + swz(arow0 + mt * 16, ks * 2u + achb));
#pragma unroll
            for (int p = 0; p < 2; p++) {
                uint32_t r[4];
                ldsm_x4(r, uB + swz(brow0 + p * 16, ks * 2u + bchb));
                bh[p * 2][0] = r[0]; bh[p * 2][1] = r[1];
                bh[p * 2 + 1][0] = r[2]; bh[p * 2 + 1][1] = r[3];
            }
            if (ks == 1) {
                __syncthreads();
                if (kc + 3 < 32) load_stage(st, kc + 3);
                asm volatile("cp.async.commit_group;");
            }
#pragma unroll
            for (int mt = 0; mt < 4; mt++)
#pragma unroll
                for (int nt = 0; nt < 4; nt++)
                    mma_f16(acc[mt][nt], ah[mt], bh[nt]);
        }
        st = (st == 2) ? 0 : st + 1;
    }

    asm volatile("cp.async.wait_group 0;");
    __syncthreads();
    float* tile = (float*)sm;  // [128][129]

    const int g = lane >> 2, tg = lane & 3;
#pragma unroll
    for (int mt = 0; mt < 4; mt++)
#pragma unroll
        for (int nt = 0; nt < 4; nt++) {
            const int cl = wn + nt * 8 + tg * 2;
#pragma unroll
            for (int hf = 0; hf < 2; hf++) {
                const int rl = wm + mt * 16 + g + hf * 8;
                tile[rl * 129 + cl] = acc[mt][nt][hf * 2 + 0];
                tile[rl * 129 + cl + 1] = acc[mt][nt][hf * 2 + 1];
            }
        }
    __syncthreads();

    for (int it = tid; it < 16384; it += 256) {
        const int r = it >> 7, c = it & 127;
        const float v = tile[r * 129 + c];
        if (!diag || r >= c) {
            out[(size_t)(rowBase + r) * NROWS + colBase + c] = v;
            if (dup && v > THR && (!diag || r > c)) dup[rowBase + r] = 1.0f;
        }
    }
    for (int it = tid; it < 16384; it += 256) {
        const int c = it >> 7, r = it & 127;
        if (!diag || r > c)
            out[(size_t)(colBase + c) * NROWS + rowBase + r] = tile[r * 129 + c];
    }
}

// ===========================================================================
// Transpose W -> Wt fp16 (hi only): Wt[n,k] = fp16(W[k,n])
// ===========================================================================
__global__ __launch_bounds__(256) void transpose_f16_kernel(
    const float* __restrict__ W, __half* __restrict__ Wt) {
    __shared__ float t[32][33];
    const int n0 = blockIdx.x * 32, k0 = blockIdx.y * 32;
    const int x = threadIdx.x, ty = threadIdx.y;
#pragma unroll
    for (int yy = ty; yy < 32; yy += 8)
        t[yy][x] = W[(size_t)(k0 + yy) * DIM + n0 + x];
    __syncthreads();
#pragma unroll
    for (int yy = ty; yy < 32; yy += 8)
        Wt[(size_t)(n0 + yy) * DIM + k0 + x] = __float2half(t[x][yy]);
}

// ===========================================================================
// Elementwise fp16 convert
// ===========================================================================
__global__ __launch_bounds__(256) void split_f16_kernel(
    const float* __restrict__ e, __half* __restrict__ hi) {
    const size_t i = (size_t)blockIdx.x * blockDim.x + threadIdx.x;
    float4 x = ((const float4*)e)[i];
    __half2 hp0, hp1;
    hp0.x = __float2half(x.x); hp0.y = __float2half(x.y);
    hp1.x = __float2half(x.z); hp1.y = __float2half(x.w);
    uint2 hv;
    hv.x = *(uint32_t*)&hp0; hv.y = *(uint32_t*)&hp1;
    ((uint2*)hi)[i] = hv;
}

// ===========================================================================
// LayerNorm + exact GELU -> fp16
// ===========================================================================
__global__ __launch_bounds__(256) void ln_gelu_f16_kernel(
    const float* __restrict__ h, const float* __restrict__ gamma,
    const float* __restrict__ beta, __half* __restrict__ hi) {
    const int row = blockIdx.x;
    const float* p = h + (size_t)row * DIM;
    const int t = threadIdx.x;

    float4 x = *(const float4*)&p[t * 4];
    float s1 = x.x + x.y + x.z + x.w;
    float s2 = x.x * x.x + x.y * x.y + x.z * x.z + x.w * x.w;
#pragma unroll
    for (int o = 16; o > 0; o >>= 1) {
        s1 += __shfl_xor_sync(0xffffffffu, s1, o);
        s2 += __shfl_xor_sync(0xffffffffu, s2, o);
    }
    __shared__ float r1[8], r2[8];
    if ((t & 31) == 0) { r1[t >> 5] = s1; r2[t >> 5] = s2; }
    __syncthreads();
    if (t < 32) {
        s1 = (t < 8) ? r1[t] : 0.f;
        s2 = (t < 8) ? r2[t] : 0.f;
#pragma unroll
        for (int o = 4; o > 0; o >>= 1) {
            s1 += __shfl_xor_sync(0xffffffffu, s1, o);
            s2 += __shfl_xor_sync(0xffffffffu, s2, o);
        }
        if (t == 0) { r1[0] = s1; r2[0] = s2; }
    }
    __syncthreads();
    const float mu = r1[0] * (1.f / DIM);
    const float var = r2[0] * (1.f / DIM) - mu * mu;
    const float rstd = rsqrtf(var + 1e-5f);

    const float4 g = *(const float4*)&gamma[t * 4];
    const float4 bb = *(const float4*)&beta[t * 4];
    float y[4] = { (x.x - mu) * rstd * g.x + bb.x,
                   (x.y - mu) * rstd * g.y + bb.y,
                   (x.z - mu) * rstd * g.z + bb.z,
                   (x.w - mu) * rstd * g.w + bb.w };
    float v[4];
#pragma unroll
    for (int i = 0; i < 4; i++)
        v[i] = 0.5f * y[i] * (1.f + erff(y[i] * 0.70710678118654752f));

    __half2 hp0, hp1;
    hp0.x = __float2half(v[0]); hp0.y = __float2half(v[1]);
    hp1.x = __float2half(v[2]); hp1.y = __float2half(v[3]);
    uint2 hv;
    hv.x = *(uint32_t*)&hp0; hv.y = *(uint32_t*)&hp1;
    ((uint2*)hi)[(size_t)row * (DIM / 4) + t] = hv;
}

// ===========================================================================
// Row L2 normalize -> fp16
// ===========================================================================
__global__ __launch_bounds__(256) void l2norm_f16_kernel(
    const float* __restrict__ e, __half* __restrict__ hi) {
    const int row = blockIdx.x;
    const float* p = e + (size_t)row * DIM;
    const int t = threadIdx.x;

    float4 x = *(const float4*)&p[t * 4];
    float s2 = x.x * x.x + x.y * x.y + x.z * x.z + x.w * x.w;
#pragma unroll
    for (int o = 16; o > 0; o >>= 1) s2 += __shfl_xor_sync(0xffffffffu, s2, o);
    __shared__ float r2[8];
    if ((t & 31) == 0) r2[t >> 5] = s2;
    __syncthreads();
    if (t < 32) {
        s2 = (t < 8) ? r2[t] : 0.f;
#pragma unroll
        for (int o = 4; o > 0; o >>= 1) s2 += __shfl_xor_sync(0xffffffffu, s2, o);
        if (t == 0) r2[0] = s2;
    }
    __syncthreads();
    const float inv = 1.f / fmaxf(sqrtf(r2[0]), 1e-12f);

    __half2 hp0, hp1;
    hp0.x = __float2half(x.x * inv); hp0.y = __float2half(x.y * inv);
    hp1.x = __float2half(x.z * inv); hp1.y = __float2half(x.w * inv);
    uint2 hv;
    hv.x = *(uint32_t*)&hp0; hv.y = *(uint32_t*)&hp1;
    ((uint2*)hi)[(size_t)row * (DIM / 4) + t] = hv;
}

// ===========================================================================
__global__ void zero_kernel(float* __restrict__ p, int n) {
    const int i = blockIdx.x * blockDim.x + threadIdx.x;
    if (i < n) p[i] = 0.0f;
}

// ===========================================================================
extern "C" void kernel_launch(void* const* d_in, const int* in_sizes, int n_in,
                              void* d_out, int out_size) {
    const float* S     = (const float*)d_in[0];
    const float* W1    = (const float*)d_in[1];
    const float* b1    = (const float*)d_in[2];
    const float* gamma = (const float*)d_in[3];
    const float* beta  = (const float*)d_in[4];
    const float* W2    = (const float*)d_in[5];
    const float* b2    = (const float*)d_in[6];
    float* out = (float*)d_out;

    float *h, *enc;
    __nv_bfloat16 *hib, *wthb;
    cudaGetSymbolAddress((void**)&h, g_h);
    cudaGetSymbolAddress((void**)&enc, g_enc);
    cudaGetSymbolAddress((void**)&hib, g_hi);
    cudaGetSymbolAddress((void**)&wthb, g_wt_hi);
    __half* act = (__half*)hib;   // activations fp16 (S, then gelu(ln(h)))
    __half* wt  = (__half*)wthb;  // transposed weight fp16
    __half* eh  = (__half*)h;     // h dead after ln_gelu -> enc fp16

    const int GEMM_SMEM = 3 * 16384;     // 48 KB
    const int SIM_SMEM = 128 * 129 * 4;  // 66048 B (>= 3*16384)
    cudaFuncSetAttribute(gemm_rect_1p, cudaFuncAttributeMaxDynamicSharedMemorySize,
                         GEMM_SMEM);
    cudaFuncSetAttribute(sim_tc_kernel, cudaFuncAttributeMaxDynamicSharedMemorySize,
                         SIM_SMEM);

    const int SPLIT_BLK = (NROWS * (DIM / 4)) / 256;

    // 1) S -> fp16; W1 -> Wt fp16
    split_f16_kernel<<<SPLIT_BLK, 256>>>(S, act);
    transpose_f16_kernel<<<dim3(32, 32), dim3(32, 8)>>>(W1, wt);
    // 2) h = S @ W1 + b1  (fp16 1-pass)
    gemm_rect_1p<<<dim3(DIM / 128, NROWS / 128), 256, GEMM_SMEM>>>(
        act, wt, h, DIM, b1, DIM);
    // 3) LayerNorm + GELU -> fp16 (act reused; S dead)
    ln_gelu_f16_kernel<<<NROWS, 256>>>(h, gamma, beta, act);
    // 4) W2 -> Wt fp16
    transpose_f16_kernel<<<dim3(32, 32), dim3(32, 8)>>>(W2, wt);
    // 5) enc = gelu(ln(h)) @ W2 + b2  (fp16 1-pass)
    gemm_rect_1p<<<dim3(DIM / 128, NROWS / 128), 256, GEMM_SMEM>>>(
        act, wt, enc, DIM, b2, DIM);
    // 6) L2 normalize -> fp16 (h buffer reused)
    l2norm_f16_kernel<<<NROWS, 256>>>(enc, eh);
    // 7) dup init (if present)
    float* dup = nullptr;
    if (out_size >= NROWS * NROWS + NROWS) {
        dup = out + (size_t)NROWS * NROWS;
        zero_kernel<<<NROWS / 256, 256>>>(dup, NROWS);
    }
    // 8) sim lower-tri fp16 1-pass; smem-staged coalesced mirror + dup
    const int NT = NROWS / 128;
    sim_tc_kernel<<<NT * (NT + 1) / 2, 256, SIM_SMEM>>>(eh, out, dup);
}

// round 9
// speedup vs baseline: 10.4149x; 1.0816x over previous
#include <cuda_runtime.h>
#include <cuda_bf16.h>
#include <cuda_fp16.h>
#include <math.h>
#include <stdint.h>

#define NROWS 8192
#define DIM   1024
#define THR   0.85f

// Scratch (allocation-free: __device__ globals)
__device__ float g_h[(size_t)NROWS * DIM];              // 32 MB (h; later enc-fp16)
__device__ float g_enc[(size_t)NROWS * DIM];            // 32 MB
__device__ __nv_bfloat16 g_hi[(size_t)NROWS * DIM];     // 16 MB (act fp16)
__device__ __nv_bfloat16 g_wt_hi[(size_t)DIM * DIM];    // 2 MB (Wt fp16)

// ===========================================================================
// sm_80-generic PTX helpers (base sm_103 target: no tcgen05)
// ===========================================================================
__device__ __forceinline__ uint32_t smem_u32(const void* p) {
    uint32_t a;
    asm("{ .reg .u64 t; cvta.to.shared.u64 t, %1; cvt.u32.u64 %0, t; }"
        : "=r"(a) : "l"(p));
    return a;
}
__device__ __forceinline__ void cp16(uint32_t dst, const void* src) {
    asm volatile("cp.async.cg.shared.global [%0], [%1], 16;"
                 :: "r"(dst), "l"(src));
}
__device__ __forceinline__ void ldsm_x4(uint32_t* r, uint32_t addr) {
    asm volatile("ldmatrix.sync.aligned.m8n8.x4.shared.b16 {%0,%1,%2,%3}, [%4];"
                 : "=r"(r[0]), "=r"(r[1]), "=r"(r[2]), "=r"(r[3]) : "r"(addr));
}
__device__ __forceinline__ void mma_f16(float* c, const uint32_t* a,
                                        const uint32_t* b) {
    asm volatile("mma.sync.aligned.m16n8k16.row.col.f32.f16.f16.f32 "
                 "{%0,%1,%2,%3}, {%4,%5,%6,%7}, {%8,%9}, {%0,%1,%2,%3};"
                 : "+f"(c[0]), "+f"(c[1]), "+f"(c[2]), "+f"(c[3])
                 : "r"(a[0]), "r"(a[1]), "r"(a[2]), "r"(a[3]),
                   "r"(b[0]), "r"(b[1]));
}

// smem tile: 128 rows x 64B. 16B-chunk swizzle, conflict-free LDSM phases.
__device__ __forceinline__ uint32_t swz(uint32_t row, uint32_t chunk) {
    uint32_t c = chunk ^ (row & 3u) ^ ((row >> 2) & 1u);
    return row * 64u + c * 16u;
}

// ===========================================================================
// Encoder GEMM: fp16 1-pass. 128x128 tile, 8 warps (2m x 4n), warp 64x32,
// BK=32, 3-stage cp.async. (proven)
// ===========================================================================
__global__ __launch_bounds__(256) void gemm_rect_1p(
    const __half* __restrict__ A, const __half* __restrict__ B,
    float* __restrict__ C, int ldc, const float* __restrict__ bias, int K) {
    extern __shared__ char sm[];
    const uint32_t sb = smem_u32(sm);

    const int rowBase = blockIdx.y * 128;
    const int colBase = blockIdx.x * 128;

    const int tid = threadIdx.x;
    const int wid = tid >> 5;
    const int lane = tid & 31;
    const int wm = (wid & 1) * 64;
    const int wn = (wid >> 1) * 32;

    const size_t rowB = (size_t)K * 2;
    const char* gA = (const char*)A + (size_t)rowBase * rowB;
    const char* gB = (const char*)B + (size_t)colBase * rowB;

    auto load_stage = [&](int st, int kc) {
        const char* bases[2] = {gA, gB};
#pragma unroll
        for (int t = 0; t < 2; t++) {
#pragma unroll
            for (int h = 0; h < 2; h++) {
                const int c = tid + h * 256;
                const uint32_t row = c >> 2, kch = c & 3;
                const uint32_t dst = sb + st * 16384u + t * 8192u + swz(row, kch);
                cp16(dst, bases[t] + (size_t)row * rowB + (size_t)kc * 64 + kch * 16);
            }
        }
    };

    float acc[4][4][4];
#pragma unroll
    for (int i = 0; i < 4; i++)
#pragma unroll
        for (int j = 0; j < 4; j++)
#pragma unroll
            for (int k = 0; k < 4; k++) acc[i][j][k] = 0.f;

    load_stage(0, 0);
    asm volatile("cp.async.commit_group;");
    load_stage(1, 1);
    asm volatile("cp.async.commit_group;");
    load_stage(2, 2);
    asm volatile("cp.async.commit_group;");

    const int kcN = K / 32;
    int st = 0;
    for (int kc = 0; kc < kcN; kc++) {
        asm volatile("cp.async.wait_group 2;");
        __syncthreads();
        const uint32_t uA = sb + st * 16384u;
        const uint32_t uB = uA + 8192u;

        uint32_t ah[4][4], bh[4][2];
        const uint32_t arow0 = (uint32_t)(wm + (lane & 15));
        const uint32_t achb = (uint32_t)(lane >> 4);
        const uint32_t brow0 = (uint32_t)(wn + (lane & 7) + ((lane & 16) >> 1));
        const uint32_t bchb = (uint32_t)((lane >> 3) & 1);

#pragma unroll
        for (int ks = 0; ks < 2; ks++) {
#pragma unroll
            for (int mt = 0; mt < 4; mt++)
                ldsm_x4(ah[mt], uA + swz(arow0 + mt * 16, ks * 2u + achb));
#pragma unroll
            for (int p = 0; p < 2; p++) {
                uint32_t r[4];
                ldsm_x4(r, uB + swz(brow0 + p * 16, ks * 2u + bchb));
                bh[p * 2][0] = r[0]; bh[p * 2][1] = r[1];
                bh[p * 2 + 1][0] = r[2]; bh[p * 2 + 1][1] = r[3];
            }
            if (ks == 1) {
                __syncthreads();
                if (kc + 3 < kcN) load_stage(st, kc + 3);
                asm volatile("cp.async.commit_group;");
            }
#pragma unroll
            for (int mt = 0; mt < 4; mt++)
#pragma unroll
                for (int nt = 0; nt < 4; nt++)
                    mma_f16(acc[mt][nt], ah[mt], bh[nt]);
        }
        st = (st == 2) ? 0 : st + 1;
    }

    const int g = lane >> 2, tg = lane & 3;
#pragma unroll
    for (int mt = 0; mt < 4; mt++)
#pragma unroll
        for (int nt = 0; nt < 4; nt++) {
            const int r0 = rowBase + wm + mt * 16 + g;
            const int c0 = colBase + wn + nt * 8 + tg * 2;
            float2 v0, v1;
            v0.x = acc[mt][nt][0]; v0.y = acc[mt][nt][1];
            v1.x = acc[mt][nt][2]; v1.y = acc[mt][nt][3];
            const float bx = bias[c0], by = bias[c0 + 1];
            v0.x += bx; v0.y += by; v1.x += bx; v1.y += by;
            *(float2*)&C[(size_t)r0 * ldc + c0] = v0;
            *(float2*)&C[(size_t)(r0 + 8) * ldc + c0] = v1;
        }
}

// ===========================================================================
// Sim GEMM: fp16 1-pass, lower-tri 128x128 tiles. 4 warps (128 thr), warp
// tile 64x64 (acc 128 regs), 4-stage cp.async. Epilogue: direct coalesced
// fragment store (+dup flag) for out[r][c]; smem-staged (stride 129)
// transposed store for the mirror out[c][r].
// ===========================================================================
__global__ __launch_bounds__(128, 2) void sim_tc_kernel(
    const __half* __restrict__ E,
    float* __restrict__ out, float* __restrict__ dup) {
    extern __shared__ char sm[];
    const uint32_t sb = smem_u32(sm);

    const int b = blockIdx.x;
    int bi = (int)((sqrtf(8.f * b + 1.f) - 1.f) * 0.5f);
    while ((bi + 1) * (bi + 2) / 2 <= b) bi++;
    while (bi * (bi + 1) / 2 > b) bi--;
    const int bj = b - bi * (bi + 1) / 2;
    const int rowBase = bi * 128;
    const int colBase = bj * 128;
    const bool diag = (rowBase == colBase);

    const int tid = threadIdx.x;
    const int wid = tid >> 5;
    const int lane = tid & 31;
    const int wm = (wid & 1) * 64;   // warp m offset (2 warps)
    const int wn = (wid >> 1) * 64;  // warp n offset (2 warps)

    const char* gA = (const char*)E + (size_t)rowBase * 2048;
    const char* gB = (const char*)E + (size_t)colBase * 2048;

    auto load_stage = [&](int st, int kc) {
        const char* bases[2] = {gA, gB};
#pragma unroll
        for (int t = 0; t < 2; t++) {
#pragma unroll
            for (int h = 0; h < 4; h++) {
                const int c = tid + h * 128;
                const uint32_t row = c >> 2, kch = c & 3;
                const uint32_t dst = sb + st * 16384u + t * 8192u + swz(row, kch);
                cp16(dst, bases[t] + (size_t)row * 2048 + (size_t)kc * 64 + kch * 16);
            }
        }
    };

    float acc[4][8][4];
#pragma unroll
    for (int i = 0; i < 4; i++)
#pragma unroll
        for (int j = 0; j < 8; j++)
#pragma unroll
            for (int k = 0; k < 4; k++) acc[i][j][k] = 0.f;

    load_stage(0, 0);
    asm volatile("cp.async.commit_group;");
    load_stage(1, 1);
    asm volatile("cp.async.commit_group;");
    load_stage(2, 2);
    asm volatile("cp.async.commit_group;");
    load_stage(3, 3);
    asm volatile("cp.async.commit_group;");

    int st = 0;
    for (int kc = 0; kc < 32; kc++) {
        asm volatile("cp.async.wait_group 3;");
        __syncthreads();
        const uint32_t uA = sb + st * 16384u;
        const uint32_t uB = uA + 8192u;

        uint32_t ah[4][4], bh[8][2];
        const uint32_t arow0 = (uint32_t)(wm + (lane & 15));
        const uint32_t achb = (uint32_t)(lane >> 4);
        const uint32_t brow0 = (uint32_t)(wn + (lane & 7) + ((lane & 16) >> 1));
        const uint32_t bchb = (uint32_t)((lane >> 3) & 1);

#pragma unroll
        for (int ks = 0; ks < 2; ks++) {
#pragma unroll
            for (int mt = 0; mt < 4; mt++)
                ldsm_x4(ah[mt], uA + swz(arow0 + mt * 16, ks * 2u + achb));
#pragma unroll
            for (int p = 0; p < 4; p++) {
                uint32_t r[4];
                ldsm_x4(r, uB + swz(brow0 + p * 16, ks * 2u + bchb));
                bh[p * 2][0] = r[0]; bh[p * 2][1] = r[1];
                bh[p * 2 + 1][0] = r[2]; bh[p * 2 + 1][1] = r[3];
            }
            if (ks == 1) {
                __syncthreads();
                if (kc + 4 < 32) load_stage(st, kc + 4);
                asm volatile("cp.async.commit_group;");
            }
#pragma unroll
            for (int mt = 0; mt < 4; mt++)
#pragma unroll
                for (int nt = 0; nt < 8; nt++)
                    mma_f16(acc[mt][nt], ah[mt], bh[nt]);
        }
        st = (st + 1) & 3;
    }

    // ---- epilogue part 1: direct coalesced stores of out[r][c] + dup ----
    const int g = lane >> 2, tg = lane & 3;
#pragma unroll
    for (int mt = 0; mt < 4; mt++)
#pragma unroll
        for (int nt = 0; nt < 8; nt++) {
            const int c0 = colBase + wn + nt * 8 + tg * 2;
#pragma unroll
            for (int hf = 0; hf < 2; hf++) {
                const int r = rowBase + wm + mt * 16 + g + hf * 8;
                const float vx = acc[mt][nt][hf * 2 + 0];
                const float vy = acc[mt][nt][hf * 2 + 1];
                if (!diag) {
                    float2 v; v.x = vx; v.y = vy;
                    *(float2*)&out[(size_t)r * NROWS + c0] = v;
                    if (dup) {
                        if (vx > THR) dup[r] = 1.0f;
                        if (vy > THR) dup[r] = 1.0f;
                    }
                } else {
                    if (r >= c0) {
                        out[(size_t)r * NROWS + c0] = vx;
                        if (dup && r > c0 && vx > THR) dup[r] = 1.0f;
                    }
                    if (r >= c0 + 1) {
                        out[(size_t)r * NROWS + c0 + 1] = vy;
                        if (dup && r > c0 + 1 && vy > THR) dup[r] = 1.0f;
                    }
                }
            }
        }

    // ---- epilogue part 2: smem-staged transposed mirror ----
    asm volatile("cp.async.wait_group 0;");
    __syncthreads();
    float* tile = (float*)sm;  // [128][129]
#pragma unroll
    for (int mt = 0; mt < 4; mt++)
#pragma unroll
        for (int nt = 0; nt < 8; nt++) {
            const int cl = wn + nt * 8 + tg * 2;
#pragma unroll
            for (int hf = 0; hf < 2; hf++) {
                const int rl = wm + mt * 16 + g + hf * 8;
                tile[rl * 129 + cl] = acc[mt][nt][hf * 2 + 0];
                tile[rl * 129 + cl + 1] = acc[mt][nt][hf * 2 + 1];
            }
        }
    __syncthreads();
    for (int it = tid; it < 16384; it += 128) {
        const int c = it >> 7, r = it & 127;
        if (!diag || r > c)
            out[(size_t)(colBase + c) * NROWS + rowBase + r] = tile[r * 129 + c];
    }
}

// ===========================================================================
// Transpose W -> Wt fp16: Wt[n,k] = fp16(W[k,n])
// ===========================================================================
__global__ __launch_bounds__(256) void transpose_f16_kernel(
    const float* __restrict__ W, __half* __restrict__ Wt) {
    __shared__ float t[32][33];
    const int n0 = blockIdx.x * 32, k0 = blockIdx.y * 32;
    const int x = threadIdx.x, ty = threadIdx.y;
#pragma unroll
    for (int yy = ty; yy < 32; yy += 8)
        t[yy][x] = W[(size_t)(k0 + yy) * DIM + n0 + x];
    __syncthreads();
#pragma unroll
    for (int yy = ty; yy < 32; yy += 8)
        Wt[(size_t)(n0 + yy) * DIM + k0 + x] = __float2half(t[x][yy]);
}

// ===========================================================================
// Elementwise fp16 convert
// ===========================================================================
__global__ __launch_bounds__(256) void split_f16_kernel(
    const float* __restrict__ e, __half* __restrict__ hi) {
    const size_t i = (size_t)blockIdx.x * blockDim.x + threadIdx.x;
    float4 x = ((const float4*)e)[i];
    __half2 hp0, hp1;
    hp0.x = __float2half(x.x); hp0.y = __float2half(x.y);
    hp1.x = __float2half(x.z); hp1.y = __float2half(x.w);
    uint2 hv;
    hv.x = *(uint32_t*)&hp0; hv.y = *(uint32_t*)&hp1;
    ((uint2*)hi)[i] = hv;
}

// ===========================================================================
// LayerNorm + exact GELU -> fp16
// ===========================================================================
__global__ __launch_bounds__(256) void ln_gelu_f16_kernel(
    const float* __restrict__ h, const float* __restrict__ gamma,
    const float* __restrict__ beta, __half* __restrict__ hi) {
    const int row = blockIdx.x;
    const float* p = h + (size_t)row * DIM;
    const int t = threadIdx.x;

    float4 x = *(const float4*)&p[t * 4];
    float s1 = x.x + x.y + x.z + x.w;
    float s2 = x.x * x.x + x.y * x.y + x.z * x.z + x.w * x.w;
#pragma unroll
    for (int o = 16; o > 0; o >>= 1) {
        s1 += __shfl_xor_sync(0xffffffffu, s1, o);
        s2 += __shfl_xor_sync(0xffffffffu, s2, o);
    }
    __shared__ float r1[8], r2[8];
    if ((t & 31) == 0) { r1[t >> 5] = s1; r2[t >> 5] = s2; }
    __syncthreads();
    if (t < 32) {
        s1 = (t < 8) ? r1[t] : 0.f;
        s2 = (t < 8) ? r2[t] : 0.f;
#pragma unroll
        for (int o = 4; o > 0; o >>= 1) {
            s1 += __shfl_xor_sync(0xffffffffu, s1, o);
            s2 += __shfl_xor_sync(0xffffffffu, s2, o);
        }
        if (t == 0) { r1[0] = s1; r2[0] = s2; }
    }
    __syncthreads();
    const float mu = r1[0] * (1.f / DIM);
    const float var = r2[0] * (1.f / DIM) - mu * mu;
    const float rstd = rsqrtf(var + 1e-5f);

    const float4 g = *(const float4*)&gamma[t * 4];
    const float4 bb = *(const float4*)&beta[t * 4];
    float y[4] = { (x.x - mu) * rstd * g.x + bb.x,
                   (x.y - mu) * rstd * g.y + bb.y,
                   (x.z - mu) * rstd * g.z + bb.z,
                   (x.w - mu) * rstd * g.w + bb.w };
    float v[4];
#pragma unroll
    for (int i = 0; i < 4; i++)
        v[i] = 0.5f * y[i] * (1.f + erff(y[i] * 0.70710678118654752f));

    __half2 hp0, hp1;
    hp0.x = __float2half(v[0]); hp0.y = __float2half(v[1]);
    hp1.x = __float2half(v[2]); hp1.y = __float2half(v[3]);
    uint2 hv;
    hv.x = *(uint32_t*)&hp0; hv.y = *(uint32_t*)&hp1;
    ((uint2*)hi)[(size_t)row * (DIM / 4) + t] = hv;
}

// ===========================================================================
// Row L2 normalize -> fp16; also zeroes dup[row] (runs before sim)
// ===========================================================================
__global__ __launch_bounds__(256) void l2norm_f16_kernel(
    const float* __restrict__ e, __half* __restrict__ hi,
    float* __restrict__ dup) {
    const int row = blockIdx.x;
    const float* p = e + (size_t)row * DIM;
    const int t = threadIdx.x;

    float4 x = *(const float4*)&p[t * 4];
    float s2 = x.x * x.x + x.y * x.y + x.z * x.z + x.w * x.w;
#pragma unroll
    for (int o = 16; o > 0; o >>= 1) s2 += __shfl_xor_sync(0xffffffffu, s2, o);
    __shared__ float r2[8];
    if ((t & 31) == 0) r2[t >> 5] = s2;
    __syncthreads();
    if (t < 32) {
        s2 = (t < 8) ? r2[t] : 0.f;
#pragma unroll
        for (int o = 4; o > 0; o >>= 1) s2 += __shfl_xor_sync(0xffffffffu, s2, o);
        if (t == 0) r2[0] = s2;
    }
    __syncthreads();
    const float inv = 1.f / fmaxf(sqrtf(r2[0]), 1e-12f);

    __half2 hp0, hp1;
    hp0.x = __float2half(x.x * inv); hp0.y = __float2half(x.y * inv);
    hp1.x = __float2half(x.z * inv); hp1.y = __float2half(x.w * inv);
    uint2 hv;
    hv.x = *(uint32_t*)&hp0; hv.y = *(uint32_t*)&hp1;
    ((uint2*)hi)[(size_t)row * (DIM / 4) + t] = hv;
    if (dup && t == 0) dup[row] = 0.0f;
}

// ===========================================================================
extern "C" void kernel_launch(void* const* d_in, const int* in_sizes, int n_in,
                              void* d_out, int out_size) {
    const float* S     = (const float*)d_in[0];
    const float* W1    = (const float*)d_in[1];
    const float* b1    = (const float*)d_in[2];
    const float* gamma = (const float*)d_in[3];
    const float* beta  = (const float*)d_in[4];
    const float* W2    = (const float*)d_in[5];
    const float* b2    = (const float*)d_in[6];
    float* out = (float*)d_out;

    float *h, *enc;
    __nv_bfloat16 *hib, *wthb;
    cudaGetSymbolAddress((void**)&h, g_h);
    cudaGetSymbolAddress((void**)&enc, g_enc);
    cudaGetSymbolAddress((void**)&hib, g_hi);
    cudaGetSymbolAddress((void**)&wthb, g_wt_hi);
    __half* act = (__half*)hib;   // activations fp16 (S, then gelu(ln(h)))
    __half* wt  = (__half*)wthb;  // transposed weight fp16
    __half* eh  = (__half*)h;     // h dead after ln_gelu -> enc fp16

    const int GEMM_SMEM = 3 * 16384;     // 48 KB
    const int SIM_SMEM = 128 * 129 * 4;  // 66048 B (>= 4*16384 pipeline)
    cudaFuncSetAttribute(gemm_rect_1p, cudaFuncAttributeMaxDynamicSharedMemorySize,
                         GEMM_SMEM);
    cudaFuncSetAttribute(sim_tc_kernel, cudaFuncAttributeMaxDynamicSharedMemorySize,
                         SIM_SMEM);

    const int SPLIT_BLK = (NROWS * (DIM / 4)) / 256;

    float* dup = nullptr;
    if (out_size >= NROWS * NROWS + NROWS) dup = out + (size_t)NROWS * NROWS;

    // 1) S -> fp16; W1 -> Wt fp16
    split_f16_kernel<<<SPLIT_BLK, 256>>>(S, act);
    transpose_f16_kernel<<<dim3(32, 32), dim3(32, 8)>>>(W1, wt);
    // 2) h = S @ W1 + b1  (fp16 1-pass)
    gemm_rect_1p<<<dim3(DIM / 128, NROWS / 128), 256, GEMM_SMEM>>>(
        act, wt, h, DIM, b1, DIM);
    // 3) LayerNorm + GELU -> fp16 (act reused; S dead)
    ln_gelu_f16_kernel<<<NROWS, 256>>>(h, gamma, beta, act);
    // 4) W2 -> Wt fp16
    transpose_f16_kernel<<<dim3(32, 32), dim3(32, 8)>>>(W2, wt);
    // 5) enc = gelu(ln(h)) @ W2 + b2  (fp16 1-pass)
    gemm_rect_1p<<<dim3(DIM / 128, NROWS / 128), 256, GEMM_SMEM>>>(
        act, wt, enc, DIM, b2, DIM);
    // 6) L2 normalize -> fp16 (+ zero dup; h buffer reused)
    l2norm_f16_kernel<<<NROWS, 256>>>(enc, eh, dup);
    // 7) sim lower-tri fp16 1-pass; direct store + staged mirror + dup
    const int NT = NROWS / 128;
    sim_tc_kernel<<<NT * (NT + 1) / 2, 128, SIM_SMEM>>>(eh, out, dup);
}

// round 10
// speedup vs baseline: 10.8557x; 1.0423x over previous
#include <cuda_runtime.h>
#include <cuda_bf16.h>
#include <cuda_fp16.h>
#include <math.h>
#include <stdint.h>

#define NROWS 8192
#define DIM   1024
#define THR   0.85f

// Scratch (allocation-free: __device__ globals)
__device__ float g_h[(size_t)NROWS * DIM];              // 32 MB: h-fp16 | enc-fp16
__device__ float g_enc[(size_t)NROWS * DIM];            // 32 MB (enc fp32)
__device__ __nv_bfloat16 g_hi[(size_t)NROWS * DIM];     // 16 MB (act fp16)
__device__ __nv_bfloat16 g_wt_hi[(size_t)DIM * DIM];    // 2 MB (Wt fp16)

// ===========================================================================
// sm_80-generic PTX helpers (base sm_103 target: no tcgen05)
// ===========================================================================
__device__ __forceinline__ uint32_t smem_u32(const void* p) {
    uint32_t a;
    asm("{ .reg .u64 t; cvta.to.shared.u64 t, %1; cvt.u32.u64 %0, t; }"
        : "=r"(a) : "l"(p));
    return a;
}
__device__ __forceinline__ void cp16(uint32_t dst, const void* src) {
    asm volatile("cp.async.cg.shared.global [%0], [%1], 16;"
                 :: "r"(dst), "l"(src));
}
__device__ __forceinline__ void ldsm_x4(uint32_t* r, uint32_t addr) {
    asm volatile("ldmatrix.sync.aligned.m8n8.x4.shared.b16 {%0,%1,%2,%3}, [%4];"
                 : "=r"(r[0]), "=r"(r[1]), "=r"(r[2]), "=r"(r[3]) : "r"(addr));
}
__device__ __forceinline__ void mma_f16(float* c, const uint32_t* a,
                                        const uint32_t* b) {
    asm volatile("mma.sync.aligned.m16n8k16.row.col.f32.f16.f16.f32 "
                 "{%0,%1,%2,%3}, {%4,%5,%6,%7}, {%8,%9}, {%0,%1,%2,%3};"
                 : "+f"(c[0]), "+f"(c[1]), "+f"(c[2]), "+f"(c[3])
                 : "r"(a[0]), "r"(a[1]), "r"(a[2]), "r"(a[3]),
                   "r"(b[0]), "r"(b[1]));
}

// smem tile: 128 rows x 64B. 16B-chunk swizzle, conflict-free LDSM phases.
__device__ __forceinline__ uint32_t swz(uint32_t row, uint32_t chunk) {
    uint32_t c = chunk ^ (row & 3u) ^ ((row >> 2) & 1u);
    return row * 64u + c * 16u;
}

// ===========================================================================
// Encoder GEMM: fp16 1-pass, 128x128 tile, 4 warps (64x64 warp tile),
// 4-stage cp.async, SINGLE barrier per k-chunk (prefetch distance 3 writes a
// stage whose readers all passed the top barrier). OutT = __half or float.
// ===========================================================================
template <typename OutT>
__global__ __launch_bounds__(128, 2) void gemm_enc(
    const __half* __restrict__ A, const __half* __restrict__ B,
    OutT* __restrict__ C, int ldc, const float* __restrict__ bias) {
    extern __shared__ char sm[];
    const uint32_t sb = smem_u32(sm);

    const int rowBase = blockIdx.y * 128;
    const int colBase = blockIdx.x * 128;

    const int tid = threadIdx.x;
    const int wid = tid >> 5;
    const int lane = tid & 31;
    const int wm = (wid & 1) * 64;
    const int wn = (wid >> 1) * 64;

    const char* gA = (const char*)A + (size_t)rowBase * 2048;
    const char* gB = (const char*)B + (size_t)colBase * 2048;

    auto load_stage = [&](int st, int kc) {
        const char* bases[2] = {gA, gB};
#pragma unroll
        for (int t = 0; t < 2; t++) {
#pragma unroll
            for (int h = 0; h < 4; h++) {
                const int c = tid + h * 128;
                const uint32_t row = c >> 2, kch = c & 3;
                const uint32_t dst = sb + st * 16384u + t * 8192u + swz(row, kch);
                cp16(dst, bases[t] + (size_t)row * 2048 + (size_t)kc * 64 + kch * 16);
            }
        }
    };

    float acc[4][8][4];
#pragma unroll
    for (int i = 0; i < 4; i++)
#pragma unroll
        for (int j = 0; j < 8; j++)
#pragma unroll
            for (int k = 0; k < 4; k++) acc[i][j][k] = 0.f;

    load_stage(0, 0);
    asm volatile("cp.async.commit_group;");
    load_stage(1, 1);
    asm volatile("cp.async.commit_group;");
    load_stage(2, 2);
    asm volatile("cp.async.commit_group;");

    int st = 0;
    for (int kc = 0; kc < 32; kc++) {
        asm volatile("cp.async.wait_group 2;");
        __syncthreads();   // single barrier per kc
        const uint32_t uA = sb + st * 16384u;
        const uint32_t uB = uA + 8192u;

        uint32_t ah[4][4], bh[8][2];
        const uint32_t arow0 = (uint32_t)(wm + (lane & 15));
        const uint32_t achb = (uint32_t)(lane >> 4);
        const uint32_t brow0 = (uint32_t)(wn + (lane & 7) + ((lane & 16) >> 1));
        const uint32_t bchb = (uint32_t)((lane >> 3) & 1);

#pragma unroll
        for (int ks = 0; ks < 2; ks++) {
#pragma unroll
            for (int mt = 0; mt < 4; mt++)
                ldsm_x4(ah[mt], uA + swz(arow0 + mt * 16, ks * 2u + achb));
#pragma unroll
            for (int p = 0; p < 4; p++) {
                uint32_t r[4];
                ldsm_x4(r, uB + swz(brow0 + p * 16, ks * 2u + bchb));
                bh[p * 2][0] = r[0]; bh[p * 2][1] = r[1];
                bh[p * 2 + 1][0] = r[2]; bh[p * 2 + 1][1] = r[3];
            }
            if (ks == 1) {
                // prefetch into stage (st+3)&3: its readers finished at the
                // top barrier of THIS iteration -> no second barrier needed
                if (kc + 3 < 32) load_stage((st + 3) & 3, kc + 3);
                asm volatile("cp.async.commit_group;");
            }
#pragma unroll
            for (int mt = 0; mt < 4; mt++)
#pragma unroll
                for (int nt = 0; nt < 8; nt++)
                    mma_f16(acc[mt][nt], ah[mt], bh[nt]);
        }
        st = (st + 1) & 3;
    }

    const int g = lane >> 2, tg = lane & 3;
#pragma unroll
    for (int mt = 0; mt < 4; mt++)
#pragma unroll
        for (int nt = 0; nt < 8; nt++) {
            const int c0 = colBase + wn + nt * 8 + tg * 2;
            const float bx = bias[c0], by = bias[c0 + 1];
#pragma unroll
            for (int hf = 0; hf < 2; hf++) {
                const int r = rowBase + wm + mt * 16 + g + hf * 8;
                const float vx = acc[mt][nt][hf * 2 + 0] + bx;
                const float vy = acc[mt][nt][hf * 2 + 1] + by;
                if (sizeof(OutT) == 2) {
                    __half2 hv;
                    hv.x = __float2half(vx); hv.y = __float2half(vy);
                    *(__half2*)&C[(size_t)r * ldc + c0] = hv;
                } else {
                    float2 v; v.x = vx; v.y = vy;
                    *(float2*)&C[(size_t)r * ldc + c0] = v;
                }
            }
        }
}

// ===========================================================================
// Sim GEMM: fp16 1-pass, lower-tri 128x128 tiles, 4 warps (64x64 warp tile),
// 4-stage cp.async, single barrier per kc. Epilogue: direct coalesced
// fragment store (+dup) for out[r][c]; smem-staged transposed mirror.
// ===========================================================================
__global__ __launch_bounds__(128, 2) void sim_tc_kernel(
    const __half* __restrict__ E,
    float* __restrict__ out, float* __restrict__ dup) {
    extern __shared__ char sm[];
    const uint32_t sb = smem_u32(sm);

    const int b = blockIdx.x;
    int bi = (int)((sqrtf(8.f * b + 1.f) - 1.f) * 0.5f);
    while ((bi + 1) * (bi + 2) / 2 <= b) bi++;
    while (bi * (bi + 1) / 2 > b) bi--;
    const int bj = b - bi * (bi + 1) / 2;
    const int rowBase = bi * 128;
    const int colBase = bj * 128;
    const bool diag = (rowBase == colBase);

    const int tid = threadIdx.x;
    const int wid = tid >> 5;
    const int lane = tid & 31;
    const int wm = (wid & 1) * 64;
    const int wn = (wid >> 1) * 64;

    const char* gA = (const char*)E + (size_t)rowBase * 2048;
    const char* gB = (const char*)E + (size_t)colBase * 2048;

    auto load_stage = [&](int st, int kc) {
        const char* bases[2] = {gA, gB};
#pragma unroll
        for (int t = 0; t < 2; t++) {
#pragma unroll
            for (int h = 0; h < 4; h++) {
                const int c = tid + h * 128;
                const uint32_t row = c >> 2, kch = c & 3;
                const uint32_t dst = sb + st * 16384u + t * 8192u + swz(row, kch);
                cp16(dst, bases[t] + (size_t)row * 2048 + (size_t)kc * 64 + kch * 16);
            }
        }
    };

    float acc[4][8][4];
#pragma unroll
    for (int i = 0; i < 4; i++)
#pragma unroll
        for (int j = 0; j < 8; j++)
#pragma unroll
            for (int k = 0; k < 4; k++) acc[i][j][k] = 0.f;

    load_stage(0, 0);
    asm volatile("cp.async.commit_group;");
    load_stage(1, 1);
    asm volatile("cp.async.commit_group;");
    load_stage(2, 2);
    asm volatile("cp.async.commit_group;");

    int st = 0;
    for (int kc = 0; kc < 32; kc++) {
        asm volatile("cp.async.wait_group 2;");
        __syncthreads();   // single barrier per kc
        const uint32_t uA = sb + st * 16384u;
        const uint32_t uB = uA + 8192u;

        uint32_t ah[4][4], bh[8][2];
        const uint32_t arow0 = (uint32_t)(wm + (lane & 15));
        const uint32_t achb = (uint32_t)(lane >> 4);
        const uint32_t brow0 = (uint32_t)(wn + (lane & 7) + ((lane & 16) >> 1));
        const uint32_t bchb = (uint32_t)((lane >> 3) & 1);

#pragma unroll
        for (int ks = 0; ks < 2; ks++) {
#pragma unroll
            for (int mt = 0; mt < 4; mt++)
                ldsm_x4(ah[mt], uA + swz(arow0 + mt * 16, ks * 2u + achb));
#pragma unroll
            for (int p = 0; p < 4; p++) {
                uint32_t r[4];
                ldsm_x4(r, uB + swz(brow0 + p * 16, ks * 2u + bchb));
                bh[p * 2][0] = r[0]; bh[p * 2][1] = r[1];
                bh[p * 2 + 1][0] = r[2]; bh[p * 2 + 1][1] = r[3];
            }
            if (ks == 1) {
                if (kc + 3 < 32) load_stage((st + 3) & 3, kc + 3);
                asm volatile("cp.async.commit_group;");
            }
#pragma unroll
            for (int mt = 0; mt < 4; mt++)
#pragma unroll
                for (int nt = 0; nt < 8; nt++)
                    mma_f16(acc[mt][nt], ah[mt], bh[nt]);
        }
        st = (st + 1) & 3;
    }

    // ---- epilogue part 1: direct coalesced stores of out[r][c] + dup ----
    const int g = lane >> 2, tg = lane & 3;
#pragma unroll
    for (int mt = 0; mt < 4; mt++)
#pragma unroll
        for (int nt = 0; nt < 8; nt++) {
            const int c0 = colBase + wn + nt * 8 + tg * 2;
#pragma unroll
            for (int hf = 0; hf < 2; hf++) {
                const int r = rowBase + wm + mt * 16 + g + hf * 8;
                const float vx = acc[mt][nt][hf * 2 + 0];
                const float vy = acc[mt][nt][hf * 2 + 1];
                if (!diag) {
                    float2 v; v.x = vx; v.y = vy;
                    *(float2*)&out[(size_t)r * NROWS + c0] = v;
                    if (dup) {
                        if (vx > THR) dup[r] = 1.0f;
                        if (vy > THR) dup[r] = 1.0f;
                    }
                } else {
                    if (r >= c0) {
                        out[(size_t)r * NROWS + c0] = vx;
                        if (dup && r > c0 && vx > THR) dup[r] = 1.0f;
                    }
                    if (r >= c0 + 1) {
                        out[(size_t)r * NROWS + c0 + 1] = vy;
                        if (dup && r > c0 + 1 && vy > THR) dup[r] = 1.0f;
                    }
                }
            }
        }

    // ---- epilogue part 2: smem-staged transposed mirror ----
    asm volatile("cp.async.wait_group 0;");
    __syncthreads();
    float* tile = (float*)sm;  // [128][129]
#pragma unroll
    for (int mt = 0; mt < 4; mt++)
#pragma unroll
        for (int nt = 0; nt < 8; nt++) {
            const int cl = wn + nt * 8 + tg * 2;
#pragma unroll
            for (int hf = 0; hf < 2; hf++) {
                const int rl = wm + mt * 16 + g + hf * 8;
                tile[rl * 129 + cl] = acc[mt][nt][hf * 2 + 0];
                tile[rl * 129 + cl + 1] = acc[mt][nt][hf * 2 + 1];
            }
        }
    __syncthreads();
    for (int it = tid; it < 16384; it += 128) {
        const int c = it >> 7, r = it & 127;
        if (!diag || r > c)
            out[(size_t)(colBase + c) * NROWS + rowBase + r] = tile[r * 129 + c];
    }
}

// ===========================================================================
// Transpose W -> Wt fp16: Wt[n,k] = fp16(W[k,n])
// ===========================================================================
__global__ __launch_bounds__(256) void transpose_f16_kernel(
    const float* __restrict__ W, __half* __restrict__ Wt) {
    __shared__ float t[32][33];
    const int n0 = blockIdx.x * 32, k0 = blockIdx.y * 32;
    const int x = threadIdx.x, ty = threadIdx.y;
#pragma unroll
    for (int yy = ty; yy < 32; yy += 8)
        t[yy][x] = W[(size_t)(k0 + yy) * DIM + n0 + x];
    __syncthreads();
#pragma unroll
    for (int yy = ty; yy < 32; yy += 8)
        Wt[(size_t)(n0 + yy) * DIM + k0 + x] = __float2half(t[x][yy]);
}

// ===========================================================================
// Elementwise fp16 convert (S)
// ===========================================================================
__global__ __launch_bounds__(256) void split_f16_kernel(
    const float* __restrict__ e, __half* __restrict__ hi) {
    const size_t i = (size_t)blockIdx.x * blockDim.x + threadIdx.x;
    float4 x = ((const float4*)e)[i];
    __half2 hp0, hp1;
    hp0.x = __float2half(x.x); hp0.y = __float2half(x.y);
    hp1.x = __float2half(x.z); hp1.y = __float2half(x.w);
    uint2 hv;
    hv.x = *(uint32_t*)&hp0; hv.y = *(uint32_t*)&hp1;
    ((uint2*)hi)[i] = hv;
}

// ===========================================================================
// LayerNorm + exact GELU: fp16 in (h), fp16 out
// ===========================================================================
__global__ __launch_bounds__(256) void ln_gelu_h_kernel(
    const __half* __restrict__ h, const float* __restrict__ gamma,
    const float* __restrict__ beta, __half* __restrict__ hi) {
    const int row = blockIdx.x;
    const int t = threadIdx.x;

    uint2 raw = ((const uint2*)(h + (size_t)row * DIM))[t];
    __half2 p0 = *(__half2*)&raw.x;
    __half2 p1 = *(__half2*)&raw.y;
    float x0 = __half2float(p0.x), x1 = __half2float(p0.y);
    float x2 = __half2float(p1.x), x3 = __half2float(p1.y);

    float s1 = x0 + x1 + x2 + x3;
    float s2 = x0 * x0 + x1 * x1 + x2 * x2 + x3 * x3;
#pragma unroll
    for (int o = 16; o > 0; o >>= 1) {
        s1 += __shfl_xor_sync(0xffffffffu, s1, o);
        s2 += __shfl_xor_sync(0xffffffffu, s2, o);
    }
    __shared__ float r1[8], r2[8];
    if ((t & 31) == 0) { r1[t >> 5] = s1; r2[t >> 5] = s2; }
    __syncthreads();
    if (t < 32) {
        s1 = (t < 8) ? r1[t] : 0.f;
        s2 = (t < 8) ? r2[t] : 0.f;
#pragma unroll
        for (int o = 4; o > 0; o >>= 1) {
            s1 += __shfl_xor_sync(0xffffffffu, s1, o);
            s2 += __shfl_xor_sync(0xffffffffu, s2, o);
        }
        if (t == 0) { r1[0] = s1; r2[0] = s2; }
    }
    __syncthreads();
    const float mu = r1[0] * (1.f / DIM);
    const float var = r2[0] * (1.f / DIM) - mu * mu;
    const float rstd = rsqrtf(var + 1e-5f);

    const float4 g = *(const float4*)&gamma[t * 4];
    const float4 bb = *(const float4*)&beta[t * 4];
    float y[4] = { (x0 - mu) * rstd * g.x + bb.x,
                   (x1 - mu) * rstd * g.y + bb.y,
                   (x2 - mu) * rstd * g.z + bb.z,
                   (x3 - mu) * rstd * g.w + bb.w };
    float v[4];
#pragma unroll
    for (int i = 0; i < 4; i++)
        v[i] = 0.5f * y[i] * (1.f + erff(y[i] * 0.70710678118654752f));

    __half2 hp0, hp1;
    hp0.x = __float2half(v[0]); hp0.y = __float2half(v[1]);
    hp1.x = __float2half(v[2]); hp1.y = __float2half(v[3]);
    uint2 hv;
    hv.x = *(uint32_t*)&hp0; hv.y = *(uint32_t*)&hp1;
    ((uint2*)hi)[(size_t)row * (DIM / 4) + t] = hv;
}

// ===========================================================================
// Row L2 normalize -> fp16; also zeroes dup[row]
// ===========================================================================
__global__ __launch_bounds__(256) void l2norm_f16_kernel(
    const float* __restrict__ e, __half* __restrict__ hi,
    float* __restrict__ dup) {
    const int row = blockIdx.x;
    const float* p = e + (size_t)row * DIM;
    const int t = threadIdx.x;

    float4 x = *(const float4*)&p[t * 4];
    float s2 = x.x * x.x + x.y * x.y + x.z * x.z + x.w * x.w;
#pragma unroll
    for (int o = 16; o > 0; o >>= 1) s2 += __shfl_xor_sync(0xffffffffu, s2, o);
    __shared__ float r2[8];
    if ((t & 31) == 0) r2[t >> 5] = s2;
    __syncthreads();
    if (t < 32) {
        s2 = (t < 8) ? r2[t] : 0.f;
#pragma unroll
        for (int o = 4; o > 0; o >>= 1) s2 += __shfl_xor_sync(0xffffffffu, s2, o);
        if (t == 0) r2[0] = s2;
    }
    __syncthreads();
    const float inv = 1.f / fmaxf(sqrtf(r2[0]), 1e-12f);

    __half2 hp0, hp1;
    hp0.x = __float2half(x.x * inv); hp0.y = __float2half(x.y * inv);
    hp1.x = __float2half(x.z * inv); hp1.y = __float2half(x.w * inv);
    uint2 hv;
    hv.x = *(uint32_t*)&hp0; hv.y = *(uint32_t*)&hp1;
    ((uint2*)hi)[(size_t)row * (DIM / 4) + t] = hv;
    if (dup && t == 0) dup[row] = 0.0f;
}

// ===========================================================================
extern "C" void kernel_launch(void* const* d_in, const int* in_sizes, int n_in,
                              void* d_out, int out_size) {
    const float* S     = (const float*)d_in[0];
    const float* W1    = (const float*)d_in[1];
    const float* b1    = (const float*)d_in[2];
    const float* gamma = (const float*)d_in[3];
    const float* beta  = (const float*)d_in[4];
    const float* W2    = (const float*)d_in[5];
    const float* b2    = (const float*)d_in[6];
    float* out = (float*)d_out;

    float *hbuf, *enc;
    __nv_bfloat16 *hib, *wthb;
    cudaGetSymbolAddress((void**)&hbuf, g_h);
    cudaGetSymbolAddress((void**)&enc, g_enc);
    cudaGetSymbolAddress((void**)&hib, g_hi);
    cudaGetSymbolAddress((void**)&wthb, g_wt_hi);
    __half* act = (__half*)hib;                      // S fp16, then gelu fp16
    __half* wt  = (__half*)wthb;                     // transposed weight fp16
    __half* hh  = (__half*)hbuf;                     // h fp16 (front 16 MB)
    __half* eh  = hh + (size_t)NROWS * DIM;          // enc fp16 (back 16 MB)

    const int GEMM_SMEM = 4 * 16384;     // 64 KB
    const int SIM_SMEM = 128 * 129 * 4;  // 66048 B (>= 4*16384 pipeline)
    cudaFuncSetAttribute(gemm_enc<__half>,
                         cudaFuncAttributeMaxDynamicSharedMemorySize, GEMM_SMEM);
    cudaFuncSetAttribute(gemm_enc<float>,
                         cudaFuncAttributeMaxDynamicSharedMemorySize, GEMM_SMEM);
    cudaFuncSetAttribute(sim_tc_kernel,
                         cudaFuncAttributeMaxDynamicSharedMemorySize, SIM_SMEM);

    const int SPLIT_BLK = (NROWS * (DIM / 4)) / 256;

    float* dup = nullptr;
    if (out_size >= NROWS * NROWS + NROWS) dup = out + (size_t)NROWS * NROWS;

    // 1) S -> fp16; W1 -> Wt fp16
    split_f16_kernel<<<SPLIT_BLK, 256>>>(S, act);
    transpose_f16_kernel<<<dim3(32, 32), dim3(32, 8)>>>(W1, wt);
    // 2) h = S @ W1 + b1  (fp16 1-pass, fp16 output)
    gemm_enc<__half><<<dim3(DIM / 128, NROWS / 128), 128, GEMM_SMEM>>>(
        act, wt, hh, DIM, b1);
    // 3) LayerNorm + GELU (fp16 in/out; act reused, S dead)
    ln_gelu_h_kernel<<<NROWS, 256>>>(hh, gamma, beta, act);
    // 4) W2 -> Wt fp16
    transpose_f16_kernel<<<dim3(32, 32), dim3(32, 8)>>>(W2, wt);
    // 5) enc = gelu(ln(h)) @ W2 + b2  (fp16 1-pass, fp32 output)
    gemm_enc<float><<<dim3(DIM / 128, NROWS / 128), 128, GEMM_SMEM>>>(
        act, wt, enc, DIM, b2);
    // 6) L2 normalize -> fp16 (+ zero dup)
    l2norm_f16_kernel<<<NROWS, 256>>>(enc, eh, dup);
    // 7) sim lower-tri fp16 1-pass; direct store + staged mirror + dup
    const int NT = NROWS / 128;
    sim_tc_kernel<<<NT * (NT + 1) / 2, 128, SIM_SMEM>>>(eh, out, dup);
}

// round 11
// speedup vs baseline: 10.9899x; 1.0124x over previous
#include <cuda_runtime.h>
#include <cuda_bf16.h>
#include <cuda_fp16.h>
#include <math.h>
#include <stdint.h>

#define NROWS 8192
#define DIM   1024
#define THR   0.85f

// Scratch (allocation-free: __device__ globals)
__device__ float g_h[(size_t)NROWS * DIM];              // 32 MB: h-fp16 | enc-fp16
__device__ __nv_bfloat16 g_hi[(size_t)NROWS * DIM];     // 16 MB (act fp16)
__device__ __nv_bfloat16 g_wt[(size_t)2 * DIM * DIM];   // 4 MB (Wt1, Wt2 fp16)

// ===========================================================================
// sm_80-generic PTX helpers (base sm_103 target: no tcgen05)
// ===========================================================================
__device__ __forceinline__ uint32_t smem_u32(const void* p) {
    uint32_t a;
    asm("{ .reg .u64 t; cvta.to.shared.u64 t, %1; cvt.u32.u64 %0, t; }"
        : "=r"(a) : "l"(p));
    return a;
}
__device__ __forceinline__ void cp16(uint32_t dst, const void* src) {
    asm volatile("cp.async.cg.shared.global [%0], [%1], 16;"
                 :: "r"(dst), "l"(src));
}
__device__ __forceinline__ void ldsm_x4(uint32_t* r, uint32_t addr) {
    asm volatile("ldmatrix.sync.aligned.m8n8.x4.shared.b16 {%0,%1,%2,%3}, [%4];"
                 : "=r"(r[0]), "=r"(r[1]), "=r"(r[2]), "=r"(r[3]) : "r"(addr));
}
__device__ __forceinline__ void mma_f16(float* c, const uint32_t* a,
                                        const uint32_t* b) {
    asm volatile("mma.sync.aligned.m16n8k16.row.col.f32.f16.f16.f32 "
                 "{%0,%1,%2,%3}, {%4,%5,%6,%7}, {%8,%9}, {%0,%1,%2,%3};"
                 : "+f"(c[0]), "+f"(c[1]), "+f"(c[2]), "+f"(c[3])
                 : "r"(a[0]), "r"(a[1]), "r"(a[2]), "r"(a[3]),
                   "r"(b[0]), "r"(b[1]));
}

// smem tile: 128 rows x 64B. 16B-chunk swizzle, conflict-free LDSM phases.
__device__ __forceinline__ uint32_t swz(uint32_t row, uint32_t chunk) {
    uint32_t c = chunk ^ (row & 3u) ^ ((row >> 2) & 1u);
    return row * 64u + c * 16u;
}

// ===========================================================================
// Encoder GEMM: fp16 1-pass, 128x128 tile, 4 warps (64x64 warp tile),
// 4-stage cp.async, single barrier per k-chunk. OutT = __half or float.
// ===========================================================================
template <typename OutT>
__global__ __launch_bounds__(128, 2) void gemm_enc(
    const __half* __restrict__ A, const __half* __restrict__ B,
    OutT* __restrict__ C, int ldc, const float* __restrict__ bias) {
    extern __shared__ char sm[];
    const uint32_t sb = smem_u32(sm);

    const int rowBase = blockIdx.y * 128;
    const int colBase = blockIdx.x * 128;

    const int tid = threadIdx.x;
    const int wid = tid >> 5;
    const int lane = tid & 31;
    const int wm = (wid & 1) * 64;
    const int wn = (wid >> 1) * 64;

    const char* gA = (const char*)A + (size_t)rowBase * 2048;
    const char* gB = (const char*)B + (size_t)colBase * 2048;

    auto load_stage = [&](int st, int kc) {
        const char* bases[2] = {gA, gB};
#pragma unroll
        for (int t = 0; t < 2; t++) {
#pragma unroll
            for (int h = 0; h < 4; h++) {
                const int c = tid + h * 128;
                const uint32_t row = c >> 2, kch = c & 3;
                const uint32_t dst = sb + st * 16384u + t * 8192u + swz(row, kch);
                cp16(dst, bases[t] + (size_t)row * 2048 + (size_t)kc * 64 + kch * 16);
            }
        }
    };

    float acc[4][8][4];
#pragma unroll
    for (int i = 0; i < 4; i++)
#pragma unroll
        for (int j = 0; j < 8; j++)
#pragma unroll
            for (int k = 0; k < 4; k++) acc[i][j][k] = 0.f;

    load_stage(0, 0);
    asm volatile("cp.async.commit_group;");
    load_stage(1, 1);
    asm volatile("cp.async.commit_group;");
    load_stage(2, 2);
    asm volatile("cp.async.commit_group;");

    int st = 0;
    for (int kc = 0; kc < 32; kc++) {
        asm volatile("cp.async.wait_group 2;");
        __syncthreads();
        const uint32_t uA = sb + st * 16384u;
        const uint32_t uB = uA + 8192u;

        uint32_t ah[4][4], bh[8][2];
        const uint32_t arow0 = (uint32_t)(wm + (lane & 15));
        const uint32_t achb = (uint32_t)(lane >> 4);
        const uint32_t brow0 = (uint32_t)(wn + (lane & 7) + ((lane & 16) >> 1));
        const uint32_t bchb = (uint32_t)((lane >> 3) & 1);

#pragma unroll
        for (int ks = 0; ks < 2; ks++) {
#pragma unroll
            for (int mt = 0; mt < 4; mt++)
                ldsm_x4(ah[mt], uA + swz(arow0 + mt * 16, ks * 2u + achb));
#pragma unroll
            for (int p = 0; p < 4; p++) {
                uint32_t r[4];
                ldsm_x4(r, uB + swz(brow0 + p * 16, ks * 2u + bchb));
                bh[p * 2][0] = r[0]; bh[p * 2][1] = r[1];
                bh[p * 2 + 1][0] = r[2]; bh[p * 2 + 1][1] = r[3];
            }
            if (ks == 1) {
                if (kc + 3 < 32) load_stage((st + 3) & 3, kc + 3);
                asm volatile("cp.async.commit_group;");
            }
#pragma unroll
            for (int mt = 0; mt < 4; mt++)
#pragma unroll
                for (int nt = 0; nt < 8; nt++)
                    mma_f16(acc[mt][nt], ah[mt], bh[nt]);
        }
        st = (st + 1) & 3;
    }

    const int g = lane >> 2, tg = lane & 3;
#pragma unroll
    for (int mt = 0; mt < 4; mt++)
#pragma unroll
        for (int nt = 0; nt < 8; nt++) {
            const int c0 = colBase + wn + nt * 8 + tg * 2;
            const float bx = bias[c0], by = bias[c0 + 1];
#pragma unroll
            for (int hf = 0; hf < 2; hf++) {
                const int r = rowBase + wm + mt * 16 + g + hf * 8;
                const float vx = acc[mt][nt][hf * 2 + 0] + bx;
                const float vy = acc[mt][nt][hf * 2 + 1] + by;
                if (sizeof(OutT) == 2) {
                    __half2 hv;
                    hv.x = __float2half(vx); hv.y = __float2half(vy);
                    *(__half2*)&C[(size_t)r * ldc + c0] = hv;
                } else {
                    float2 v; v.x = vx; v.y = vy;
                    *(float2*)&C[(size_t)r * ldc + c0] = v;
                }
            }
        }
}

// ===========================================================================
// Sim GEMM: fp16 1-pass, lower-tri 128x128 tiles, 4 warps (64x64 warp tile),
// 4-stage cp.async, single barrier per kc. Epilogue: direct coalesced
// fragment store (+dup) for out[r][c]; smem-staged transposed mirror.
// ===========================================================================
__global__ __launch_bounds__(128, 2) void sim_tc_kernel(
    const __half* __restrict__ E,
    float* __restrict__ out, float* __restrict__ dup) {
    extern __shared__ char sm[];
    const uint32_t sb = smem_u32(sm);

    const int b = blockIdx.x;
    int bi = (int)((sqrtf(8.f * b + 1.f) - 1.f) * 0.5f);
    while ((bi + 1) * (bi + 2) / 2 <= b) bi++;
    while (bi * (bi + 1) / 2 > b) bi--;
    const int bj = b - bi * (bi + 1) / 2;
    const int rowBase = bi * 128;
    const int colBase = bj * 128;
    const bool diag = (rowBase == colBase);

    const int tid = threadIdx.x;
    const int wid = tid >> 5;
    const int lane = tid & 31;
    const int wm = (wid & 1) * 64;
    const int wn = (wid >> 1) * 64;

    const char* gA = (const char*)E + (size_t)rowBase * 2048;
    const char* gB = (const char*)E + (size_t)colBase * 2048;

    auto load_stage = [&](int st, int kc) {
        const char* bases[2] = {gA, gB};
#pragma unroll
        for (int t = 0; t < 2; t++) {
#pragma unroll
            for (int h = 0; h < 4; h++) {
                const int c = tid + h * 128;
                const uint32_t row = c >> 2, kch = c & 3;
                const uint32_t dst = sb + st * 16384u + t * 8192u + swz(row, kch);
                cp16(dst, bases[t] + (size_t)row * 2048 + (size_t)kc * 64 + kch * 16);
            }
        }
    };

    float acc[4][8][4];
#pragma unroll
    for (int i = 0; i < 4; i++)
#pragma unroll
        for (int j = 0; j < 8; j++)
#pragma unroll
            for (int k = 0; k < 4; k++) acc[i][j][k] = 0.f;

    load_stage(0, 0);
    asm volatile("cp.async.commit_group;");
    load_stage(1, 1);
    asm volatile("cp.async.commit_group;");
    load_stage(2, 2);
    asm volatile("cp.async.commit_group;");

    int st = 0;
    for (int kc = 0; kc < 32; kc++) {
        asm volatile("cp.async.wait_group 2;");
        __syncthreads();
        const uint32_t uA = sb + st * 16384u;
        const uint32_t uB = uA + 8192u;

        uint32_t ah[4][4], bh[8][2];
        const uint32_t arow0 = (uint32_t)(wm + (lane & 15));
        const uint32_t achb = (uint32_t)(lane >> 4);
        const uint32_t brow0 = (uint32_t)(wn + (lane & 7) + ((lane & 16) >> 1));
        const uint32_t bchb = (uint32_t)((lane >> 3) & 1);

#pragma unroll
        for (int ks = 0; ks < 2; ks++) {
#pragma unroll
            for (int mt = 0; mt < 4; mt++)
                ldsm_x4(ah[mt], uA + swz(arow0 + mt * 16, ks * 2u + achb));
#pragma unroll
            for (int p = 0; p < 4; p++) {
                uint32_t r[4];
                ldsm_x4(r, uB + swz(brow0 + p * 16, ks * 2u + bchb));
                bh[p * 2][0] = r[0]; bh[p * 2][1] = r[1];
                bh[p * 2 + 1][0] = r[2]; bh[p * 2 + 1][1] = r[3];
            }
            if (ks == 1) {
                if (kc + 3 < 32) load_stage((st + 3) & 3, kc + 3);
                asm volatile("cp.async.commit_group;");
            }
#pragma unroll
            for (int mt = 0; mt < 4; mt++)
#pragma unroll
                for (int nt = 0; nt < 8; nt++)
                    mma_f16(acc[mt][nt], ah[mt], bh[nt]);
        }
        st = (st + 1) & 3;
    }

    // ---- epilogue part 1: direct coalesced stores of out[r][c] + dup ----
    const int g = lane >> 2, tg = lane & 3;
#pragma unroll
    for (int mt = 0; mt < 4; mt++)
#pragma unroll
        for (int nt = 0; nt < 8; nt++) {
            const int c0 = colBase + wn + nt * 8 + tg * 2;
#pragma unroll
            for (int hf = 0; hf < 2; hf++) {
                const int r = rowBase + wm + mt * 16 + g + hf * 8;
                const float vx = acc[mt][nt][hf * 2 + 0];
                const float vy = acc[mt][nt][hf * 2 + 1];
                if (!diag) {
                    float2 v; v.x = vx; v.y = vy;
                    *(float2*)&out[(size_t)r * NROWS + c0] = v;
                    if (dup) {
                        if (vx > THR) dup[r] = 1.0f;
                        if (vy > THR) dup[r] = 1.0f;
                    }
                } else {
                    if (r >= c0) {
                        out[(size_t)r * NROWS + c0] = vx;
                        if (dup && r > c0 && vx > THR) dup[r] = 1.0f;
                    }
                    if (r >= c0 + 1) {
                        out[(size_t)r * NROWS + c0 + 1] = vy;
                        if (dup && r > c0 + 1 && vy > THR) dup[r] = 1.0f;
                    }
                }
            }
        }

    // ---- epilogue part 2: smem-staged transposed mirror ----
    asm volatile("cp.async.wait_group 0;");
    __syncthreads();
    float* tile = (float*)sm;  // [128][129]
#pragma unroll
    for (int mt = 0; mt < 4; mt++)
#pragma unroll
        for (int nt = 0; nt < 8; nt++) {
            const int cl = wn + nt * 8 + tg * 2;
#pragma unroll
            for (int hf = 0; hf < 2; hf++) {
                const int rl = wm + mt * 16 + g + hf * 8;
                tile[rl * 129 + cl] = acc[mt][nt][hf * 2 + 0];
                tile[rl * 129 + cl + 1] = acc[mt][nt][hf * 2 + 1];
            }
        }
    __syncthreads();
    for (int it = tid; it < 16384; it += 128) {
        const int c = it >> 7, r = it & 127;
        if (!diag || r > c)
            out[(size_t)(colBase + c) * NROWS + rowBase + r] = tile[r * 129 + c];
    }
}

// ===========================================================================
// prep: split S -> fp16 (blocks 0..8191) and transpose+convert W1/W2
// (blocks 8192..10239). One launch instead of three.
// ===========================================================================
__global__ __launch_bounds__(256) void prep_kernel(
    const float* __restrict__ S, const float* __restrict__ W1,
    const float* __restrict__ W2, __half* __restrict__ act,
    __half* __restrict__ wt1, __half* __restrict__ wt2) {
    const int b = blockIdx.x;
    const int tid = threadIdx.x;
    if (b < 8192) {
        // split S: 8192 blocks x 256 thr x 4 elems
        const size_t i = (size_t)b * 256 + tid;
        float4 x = ((const float4*)S)[i];
        __half2 hp0, hp1;
        hp0.x = __float2half(x.x); hp0.y = __float2half(x.y);
        hp1.x = __float2half(x.z); hp1.y = __float2half(x.w);
        uint2 hv;
        hv.x = *(uint32_t*)&hp0; hv.y = *(uint32_t*)&hp1;
        ((uint2*)act)[i] = hv;
    } else {
        // transpose: 2 x 1024 blocks of 32x32 tiles
        const int b2 = b - 8192;
        const float* W = (b2 < 1024) ? W1 : W2;
        __half* Wt = (b2 < 1024) ? wt1 : wt2;
        const int b3 = b2 & 1023;
        const int n0 = (b3 & 31) * 32, k0 = (b3 >> 5) * 32;
        __shared__ float t[32][33];
        const int x = tid & 31, ty = tid >> 5;  // ty 0..7
#pragma unroll
        for (int yy = ty; yy < 32; yy += 8)
            t[yy][x] = W[(size_t)(k0 + yy) * DIM + n0 + x];
        __syncthreads();
#pragma unroll
        for (int yy = ty; yy < 32; yy += 8)
            Wt[(size_t)(n0 + yy) * DIM + k0 + x] = __float2half(t[x][yy]);
    }
}

// ===========================================================================
// LayerNorm + exact GELU: fp16 in (h), fp16 out
// ===========================================================================
__global__ __launch_bounds__(256) void ln_gelu_h_kernel(
    const __half* __restrict__ h, const float* __restrict__ gamma,
    const float* __restrict__ beta, __half* __restrict__ hi) {
    const int row = blockIdx.x;
    const int t = threadIdx.x;

    uint2 raw = ((const uint2*)(h + (size_t)row * DIM))[t];
    __half2 p0 = *(__half2*)&raw.x;
    __half2 p1 = *(__half2*)&raw.y;
    float x0 = __half2float(p0.x), x1 = __half2float(p0.y);
    float x2 = __half2float(p1.x), x3 = __half2float(p1.y);

    float s1 = x0 + x1 + x2 + x3;
    float s2 = x0 * x0 + x1 * x1 + x2 * x2 + x3 * x3;
#pragma unroll
    for (int o = 16; o > 0; o >>= 1) {
        s1 += __shfl_xor_sync(0xffffffffu, s1, o);
        s2 += __shfl_xor_sync(0xffffffffu, s2, o);
    }
    __shared__ float r1[8], r2[8];
    if ((t & 31) == 0) { r1[t >> 5] = s1; r2[t >> 5] = s2; }
    __syncthreads();
    if (t < 32) {
        s1 = (t < 8) ? r1[t] : 0.f;
        s2 = (t < 8) ? r2[t] : 0.f;
#pragma unroll
        for (int o = 4; o > 0; o >>= 1) {
            s1 += __shfl_xor_sync(0xffffffffu, s1, o);
            s2 += __shfl_xor_sync(0xffffffffu, s2, o);
        }
        if (t == 0) { r1[0] = s1; r2[0] = s2; }
    }
    __syncthreads();
    const float mu = r1[0] * (1.f / DIM);
    const float var = r2[0] * (1.f / DIM) - mu * mu;
    const float rstd = rsqrtf(var + 1e-5f);

    const float4 g = *(const float4*)&gamma[t * 4];
    const float4 bb = *(const float4*)&beta[t * 4];
    float y[4] = { (x0 - mu) * rstd * g.x + bb.x,
                   (x1 - mu) * rstd * g.y + bb.y,
                   (x2 - mu) * rstd * g.z + bb.z,
                   (x3 - mu) * rstd * g.w + bb.w };
    float v[4];
#pragma unroll
    for (int i = 0; i < 4; i++)
        v[i] = 0.5f * y[i] * (1.f + erff(y[i] * 0.70710678118654752f));

    __half2 hp0, hp1;
    hp0.x = __float2half(v[0]); hp0.y = __float2half(v[1]);
    hp1.x = __float2half(v[2]); hp1.y = __float2half(v[3]);
    uint2 hv;
    hv.x = *(uint32_t*)&hp0; hv.y = *(uint32_t*)&hp1;
    ((uint2*)hi)[(size_t)row * (DIM / 4) + t] = hv;
}

// ===========================================================================
// Row L2 normalize IN PLACE on fp16 enc; also zeroes dup[row]
// ===========================================================================
__global__ __launch_bounds__(256) void l2norm_f16_inplace_kernel(
    __half* __restrict__ e, float* __restrict__ dup) {
    const int row = blockIdx.x;
    const int t = threadIdx.x;

    uint2 raw = ((uint2*)(e + (size_t)row * DIM))[t];
    __half2 p0 = *(__half2*)&raw.x;
    __half2 p1 = *(__half2*)&raw.y;
    float x0 = __half2float(p0.x), x1 = __half2float(p0.y);
    float x2 = __half2float(p1.x), x3 = __half2float(p1.y);

    float s2 = x0 * x0 + x1 * x1 + x2 * x2 + x3 * x3;
#pragma unroll
    for (int o = 16; o > 0; o >>= 1) s2 += __shfl_xor_sync(0xffffffffu, s2, o);
    __shared__ float r2[8];
    if ((t & 31) == 0) r2[t >> 5] = s2;
    __syncthreads();
    if (t < 32) {
        s2 = (t < 8) ? r2[t] : 0.f;
#pragma unroll
        for (int o = 4; o > 0; o >>= 1) s2 += __shfl_xor_sync(0xffffffffu, s2, o);
        if (t == 0) r2[0] = s2;
    }
    __syncthreads();
    const float inv = 1.f / fmaxf(sqrtf(r2[0]), 1e-12f);

    __half2 hp0, hp1;
    hp0.x = __float2half(x0 * inv); hp0.y = __float2half(x1 * inv);
    hp1.x = __float2half(x2 * inv); hp1.y = __float2half(x3 * inv);
    uint2 hv;
    hv.x = *(uint32_t*)&hp0; hv.y = *(uint32_t*)&hp1;
    ((uint2*)(e + (size_t)row * DIM))[t] = hv;
    if (dup && t == 0) dup[row] = 0.0f;
}

// ===========================================================================
extern "C" void kernel_launch(void* const* d_in, const int* in_sizes, int n_in,
                              void* d_out, int out_size) {
    const float* S     = (const float*)d_in[0];
    const float* W1    = (const float*)d_in[1];
    const float* b1    = (const float*)d_in[2];
    const float* gamma = (const float*)d_in[3];
    const float* beta  = (const float*)d_in[4];
    const float* W2    = (const float*)d_in[5];
    const float* b2    = (const float*)d_in[6];
    float* out = (float*)d_out;

    float* hbuf;
    __nv_bfloat16 *hib, *wtb;
    cudaGetSymbolAddress((void**)&hbuf, g_h);
    cudaGetSymbolAddress((void**)&hib, g_hi);
    cudaGetSymbolAddress((void**)&wtb, g_wt);
    __half* act = (__half*)hib;                      // S fp16, then gelu fp16
    __half* wt1 = (__half*)wtb;                      // Wt1 fp16
    __half* wt2 = wt1 + (size_t)DIM * DIM;           // Wt2 fp16
    __half* hh  = (__half*)hbuf;                     // h fp16 (front 16 MB)
    __half* eh  = hh + (size_t)NROWS * DIM;          // enc fp16 (back 16 MB)

    const int GEMM_SMEM = 4 * 16384;     // 64 KB
    const int SIM_SMEM = 128 * 129 * 4;  // 66048 B (>= 4*16384 pipeline)
    cudaFuncSetAttribute(gemm_enc<__half>,
                         cudaFuncAttributeMaxDynamicSharedMemorySize, GEMM_SMEM);
    cudaFuncSetAttribute(sim_tc_kernel,
                         cudaFuncAttributeMaxDynamicSharedMemorySize, SIM_SMEM);

    float* dup = nullptr;
    if (out_size >= NROWS * NROWS + NROWS) dup = out + (size_t)NROWS * NROWS;

    // 1) prep: S -> fp16; W1, W2 -> Wt fp16 (single launch)
    prep_kernel<<<8192 + 2048, 256>>>(S, W1, W2, act, wt1, wt2);
    // 2) h = S @ W1 + b1  (fp16 1-pass, fp16 output)
    gemm_enc<__half><<<dim3(DIM / 128, NROWS / 128), 128, GEMM_SMEM>>>(
        act, wt1, hh, DIM, b1);
    // 3) LayerNorm + GELU (fp16 in/out; act reused, S dead)
    ln_gelu_h_kernel<<<NROWS, 256>>>(hh, gamma, beta, act);
    // 4) enc = gelu(ln(h)) @ W2 + b2  (fp16 1-pass, fp16 output)
    gemm_enc<__half><<<dim3(DIM / 128, NROWS / 128), 128, GEMM_SMEM>>>(
        act, wt2, eh, DIM, b2);
    // 5) L2 normalize in place on fp16 enc (+ zero dup)
    l2norm_f16_inplace_kernel<<<NROWS, 256>>>(eh, dup);
    // 6) sim lower-tri fp16 1-pass; direct store + staged mirror + dup
    const int NT = NROWS / 128;
    sim_tc_kernel<<<NT * (NT + 1) / 2, 128, SIM_SMEM>>>(eh, out, dup);
}

// round 12
// speedup vs baseline: 11.5571x; 1.0516x over previous
#include <cuda_runtime.h>
#include <cuda_bf16.h>
#include <cuda_fp16.h>
#include <math.h>
#include <stdint.h>

#define NROWS 8192
#define DIM   1024
#define THR   0.85f

// Scratch (allocation-free: __device__ globals)
__device__ float g_h[(size_t)NROWS * DIM];              // 32 MB: h-fp16 | enc-fp16
__device__ __nv_bfloat16 g_hi[(size_t)NROWS * DIM];     // 16 MB (act fp16)
__device__ __nv_bfloat16 g_wt[(size_t)2 * DIM * DIM];   // 4 MB (Wt1, Wt2 fp16)

// ===========================================================================
// sm_80-generic PTX helpers (base sm_103 target: no tcgen05)
// ===========================================================================
__device__ __forceinline__ uint32_t smem_u32(const void* p) {
    uint32_t a;
    asm("{ .reg .u64 t; cvta.to.shared.u64 t, %1; cvt.u32.u64 %0, t; }"
        : "=r"(a) : "l"(p));
    return a;
}
__device__ __forceinline__ void cp16(uint32_t dst, const void* src) {
    asm volatile("cp.async.cg.shared.global [%0], [%1], 16;"
                 :: "r"(dst), "l"(src));
}
__device__ __forceinline__ void ldsm_x4(uint32_t* r, uint32_t addr) {
    asm volatile("ldmatrix.sync.aligned.m8n8.x4.shared.b16 {%0,%1,%2,%3}, [%4];"
                 : "=r"(r[0]), "=r"(r[1]), "=r"(r[2]), "=r"(r[3]) : "r"(addr));
}
__device__ __forceinline__ void mma_f16(float* c, const uint32_t* a,
                                        const uint32_t* b) {
    asm volatile("mma.sync.aligned.m16n8k16.row.col.f32.f16.f16.f32 "
                 "{%0,%1,%2,%3}, {%4,%5,%6,%7}, {%8,%9}, {%0,%1,%2,%3};"
                 : "+f"(c[0]), "+f"(c[1]), "+f"(c[2]), "+f"(c[3])
                 : "r"(a[0]), "r"(a[1]), "r"(a[2]), "r"(a[3]),
                   "r"(b[0]), "r"(b[1]));
}

// smem tile: 128 rows x 64B. 16B-chunk swizzle, conflict-free LDSM phases.
__device__ __forceinline__ uint32_t swz(uint32_t row, uint32_t chunk) {
    uint32_t c = chunk ^ (row & 3u) ^ ((row >> 2) & 1u);
    return row * 64u + c * 16u;
}

// Load one phase of fragments (A 64 rows, B 64 cols) from a stage.
#define LOAD_FRAGS(A, B, uA_, uB_, ksoff)                                   \
    do {                                                                    \
        _Pragma("unroll")                                                   \
        for (int mt = 0; mt < 4; mt++)                                      \
            ldsm_x4((A)[mt], (uA_) + swz(arow0 + mt * 16, (ksoff) + achb)); \
        _Pragma("unroll")                                                   \
        for (int p = 0; p < 4; p++) {                                       \
            uint32_t r_[4];                                                 \
            ldsm_x4(r_, (uB_) + swz(brow0 + p * 16, (ksoff) + bchb));       \
            (B)[p * 2][0] = r_[0]; (B)[p * 2][1] = r_[1];                   \
            (B)[p * 2 + 1][0] = r_[2]; (B)[p * 2 + 1][1] = r_[3];           \
        }                                                                   \
    } while (0)

#define MMA_ALL(A, B)                                                       \
    do {                                                                    \
        _Pragma("unroll")                                                   \
        for (int mt = 0; mt < 4; mt++)                                      \
            _Pragma("unroll")                                               \
            for (int nt = 0; nt < 8; nt++)                                  \
                mma_f16(acc[mt][nt], (A)[mt], (B)[nt]);                     \
    } while (0)

// ===========================================================================
// Encoder GEMM: fp16 1-pass, 128x128 tile, 4 warps (64x64 warp tile),
// 4-stage cp.async, register-double-buffered fragments (LDSM hidden behind
// MMA; wait_group 1 so stage st+1 is readable for the early frag load).
// ===========================================================================
template <typename OutT>
__global__ __launch_bounds__(128, 2) void gemm_enc(
    const __half* __restrict__ A, const __half* __restrict__ B,
    OutT* __restrict__ C, int ldc, const float* __restrict__ bias) {
    extern __shared__ char sm[];
    const uint32_t sb = smem_u32(sm);

    const int rowBase = blockIdx.y * 128;
    const int colBase = blockIdx.x * 128;

    const int tid = threadIdx.x;
    const int wid = tid >> 5;
    const int lane = tid & 31;
    const int wm = (wid & 1) * 64;
    const int wn = (wid >> 1) * 64;

    const char* gA = (const char*)A + (size_t)rowBase * 2048;
    const char* gB = (const char*)B + (size_t)colBase * 2048;

    auto load_stage = [&](int st_, int kc_) {
        const char* bases[2] = {gA, gB};
#pragma unroll
        for (int t = 0; t < 2; t++) {
#pragma unroll
            for (int h = 0; h < 4; h++) {
                const int c = tid + h * 128;
                const uint32_t row = c >> 2, kch = c & 3;
                const uint32_t dst = sb + st_ * 16384u + t * 8192u + swz(row, kch);
                cp16(dst, bases[t] + (size_t)row * 2048 + (size_t)kc_ * 64 + kch * 16);
            }
        }
    };

    float acc[4][8][4];
#pragma unroll
    for (int i = 0; i < 4; i++)
#pragma unroll
        for (int j = 0; j < 8; j++)
#pragma unroll
            for (int k = 0; k < 4; k++) acc[i][j][k] = 0.f;

    load_stage(0, 0);
    asm volatile("cp.async.commit_group;");
    load_stage(1, 1);
    asm volatile("cp.async.commit_group;");
    load_stage(2, 2);
    asm volatile("cp.async.commit_group;");

    const uint32_t arow0 = (uint32_t)(wm + (lane & 15));
    const uint32_t achb = (uint32_t)(lane >> 4);
    const uint32_t brow0 = (uint32_t)(wn + (lane & 7) + ((lane & 16) >> 1));
    const uint32_t bchb = (uint32_t)((lane >> 3) & 1);

    uint32_t a0[4][4], b0[8][2], a1[4][4], b1[8][2];

    asm volatile("cp.async.wait_group 1;");  // stages 0,1 complete
    __syncthreads();
    LOAD_FRAGS(a0, b0, sb, sb + 8192u, 0u);

    int st = 0;
    for (int kc = 0; kc < 32; kc++) {
        const uint32_t uA = sb + st * 16384u;
        const uint32_t uB = uA + 8192u;
        LOAD_FRAGS(a1, b1, uA, uB, 2u);
        MMA_ALL(a0, b0);
        if (kc + 1 < 32) {
            const uint32_t uA2 = sb + ((st + 1) & 3) * 16384u;
            LOAD_FRAGS(a0, b0, uA2, uA2 + 8192u, 0u);
        }
        if (kc + 3 < 32) load_stage((st + 3) & 3, kc + 3);
        asm volatile("cp.async.commit_group;");
        MMA_ALL(a1, b1);
        asm volatile("cp.async.wait_group 1;");
        __syncthreads();
        st = (st + 1) & 3;
    }

    const int g = lane >> 2, tg = lane & 3;
#pragma unroll
    for (int mt = 0; mt < 4; mt++)
#pragma unroll
        for (int nt = 0; nt < 8; nt++) {
            const int c0 = colBase + wn + nt * 8 + tg * 2;
            const float bx = bias[c0], by = bias[c0 + 1];
#pragma unroll
            for (int hf = 0; hf < 2; hf++) {
                const int r = rowBase + wm + mt * 16 + g + hf * 8;
                const float vx = acc[mt][nt][hf * 2 + 0] + bx;
                const float vy = acc[mt][nt][hf * 2 + 1] + by;
                if (sizeof(OutT) == 2) {
                    __half2 hv;
                    hv.x = __float2half(vx); hv.y = __float2half(vy);
                    *(__half2*)&C[(size_t)r * ldc + c0] = hv;
                } else {
                    float2 v; v.x = vx; v.y = vy;
                    *(float2*)&C[(size_t)r * ldc + c0] = v;
                }
            }
        }
}

// ===========================================================================
// Sim GEMM: fp16 1-pass, lower-tri 128x128 tiles, same pipelined mainloop.
// Epilogue: direct coalesced fragment store (+dup); smem-staged mirror.
// ===========================================================================
__global__ __launch_bounds__(128, 2) void sim_tc_kernel(
    const __half* __restrict__ E,
    float* __restrict__ out, float* __restrict__ dup) {
    extern __shared__ char sm[];
    const uint32_t sb = smem_u32(sm);

    const int b = blockIdx.x;
    int bi = (int)((sqrtf(8.f * b + 1.f) - 1.f) * 0.5f);
    while ((bi + 1) * (bi + 2) / 2 <= b) bi++;
    while (bi * (bi + 1) / 2 > b) bi--;
    const int bj = b - bi * (bi + 1) / 2;
    const int rowBase = bi * 128;
    const int colBase = bj * 128;
    const bool diag = (rowBase == colBase);

    const int tid = threadIdx.x;
    const int wid = tid >> 5;
    const int lane = tid & 31;
    const int wm = (wid & 1) * 64;
    const int wn = (wid >> 1) * 64;

    const char* gA = (const char*)E + (size_t)rowBase * 2048;
    const char* gB = (const char*)E + (size_t)colBase * 2048;

    auto load_stage = [&](int st_, int kc_) {
        const char* bases[2] = {gA, gB};
#pragma unroll
        for (int t = 0; t < 2; t++) {
#pragma unroll
            for (int h = 0; h < 4; h++) {
                const int c = tid + h * 128;
                const uint32_t row = c >> 2, kch = c & 3;
                const uint32_t dst = sb + st_ * 16384u + t * 8192u + swz(row, kch);
                cp16(dst, bases[t] + (size_t)row * 2048 + (size_t)kc_ * 64 + kch * 16);
            }
        }
    };

    float acc[4][8][4];
#pragma unroll
    for (int i = 0; i < 4; i++)
#pragma unroll
        for (int j = 0; j < 8; j++)
#pragma unroll
            for (int k = 0; k < 4; k++) acc[i][j][k] = 0.f;

    load_stage(0, 0);
    asm volatile("cp.async.commit_group;");
    load_stage(1, 1);
    asm volatile("cp.async.commit_group;");
    load_stage(2, 2);
    asm volatile("cp.async.commit_group;");

    const uint32_t arow0 = (uint32_t)(wm + (lane & 15));
    const uint32_t achb = (uint32_t)(lane >> 4);
    const uint32_t brow0 = (uint32_t)(wn + (lane & 7) + ((lane & 16) >> 1));
    const uint32_t bchb = (uint32_t)((lane >> 3) & 1);

    uint32_t a0[4][4], b0[8][2], a1[4][4], b1[8][2];

    asm volatile("cp.async.wait_group 1;");
    __syncthreads();
    LOAD_FRAGS(a0, b0, sb, sb + 8192u, 0u);

    int st = 0;
    for (int kc = 0; kc < 32; kc++) {
        const uint32_t uA = sb + st * 16384u;
        const uint32_t uB = uA + 8192u;
        LOAD_FRAGS(a1, b1, uA, uB, 2u);
        MMA_ALL(a0, b0);
        if (kc + 1 < 32) {
            const uint32_t uA2 = sb + ((st + 1) & 3) * 16384u;
            LOAD_FRAGS(a0, b0, uA2, uA2 + 8192u, 0u);
        }
        if (kc + 3 < 32) load_stage((st + 3) & 3, kc + 3);
        asm volatile("cp.async.commit_group;");
        MMA_ALL(a1, b1);
        asm volatile("cp.async.wait_group 1;");
        __syncthreads();
        st = (st + 1) & 3;
    }

    // ---- epilogue part 1: direct coalesced stores of out[r][c] + dup ----
    const int g = lane >> 2, tg = lane & 3;
#pragma unroll
    for (int mt = 0; mt < 4; mt++)
#pragma unroll
        for (int nt = 0; nt < 8; nt++) {
            const int c0 = colBase + wn + nt * 8 + tg * 2;
#pragma unroll
            for (int hf = 0; hf < 2; hf++) {
                const int r = rowBase + wm + mt * 16 + g + hf * 8;
                const float vx = acc[mt][nt][hf * 2 + 0];
                const float vy = acc[mt][nt][hf * 2 + 1];
                if (!diag) {
                    float2 v; v.x = vx; v.y = vy;
                    *(float2*)&out[(size_t)r * NROWS + c0] = v;
                    if (dup) {
                        if (vx > THR) dup[r] = 1.0f;
                        if (vy > THR) dup[r] = 1.0f;
                    }
                } else {
                    if (r >= c0) {
                        out[(size_t)r * NROWS + c0] = vx;
                        if (dup && r > c0 && vx > THR) dup[r] = 1.0f;
                    }
                    if (r >= c0 + 1) {
                        out[(size_t)r * NROWS + c0 + 1] = vy;
                        if (dup && r > c0 + 1 && vy > THR) dup[r] = 1.0f;
                    }
                }
            }
        }

    // ---- epilogue part 2: smem-staged transposed mirror ----
    asm volatile("cp.async.wait_group 0;");
    __syncthreads();
    float* tile = (float*)sm;  // [128][129]
#pragma unroll
    for (int mt = 0; mt < 4; mt++)
#pragma unroll
        for (int nt = 0; nt < 8; nt++) {
            const int cl = wn + nt * 8 + tg * 2;
#pragma unroll
            for (int hf = 0; hf < 2; hf++) {
                const int rl = wm + mt * 16 + g + hf * 8;
                tile[rl * 129 + cl] = acc[mt][nt][hf * 2 + 0];
                tile[rl * 129 + cl + 1] = acc[mt][nt][hf * 2 + 1];
            }
        }
    __syncthreads();
    for (int it = tid; it < 16384; it += 128) {
        const int c = it >> 7, r = it & 127;
        if (!diag || r > c)
            out[(size_t)(colBase + c) * NROWS + rowBase + r] = tile[r * 129 + c];
    }
}

// ===========================================================================
// prep: split S -> fp16 (blocks 0..8191) and transpose+convert W1/W2
// ===========================================================================
__global__ __launch_bounds__(256) void prep_kernel(
    const float* __restrict__ S, const float* __restrict__ W1,
    const float* __restrict__ W2, __half* __restrict__ act,
    __half* __restrict__ wt1, __half* __restrict__ wt2) {
    const int b = blockIdx.x;
    const int tid = threadIdx.x;
    if (b < 8192) {
        const size_t i = (size_t)b * 256 + tid;
        float4 x = ((const float4*)S)[i];
        __half2 hp0, hp1;
        hp0.x = __float2half(x.x); hp0.y = __float2half(x.y);
        hp1.x = __float2half(x.z); hp1.y = __float2half(x.w);
        uint2 hv;
        hv.x = *(uint32_t*)&hp0; hv.y = *(uint32_t*)&hp1;
        ((uint2*)act)[i] = hv;
    } else {
        const int b2 = b - 8192;
        const float* W = (b2 < 1024) ? W1 : W2;
        __half* Wt = (b2 < 1024) ? wt1 : wt2;
        const int b3 = b2 & 1023;
        const int n0 = (b3 & 31) * 32, k0 = (b3 >> 5) * 32;
        __shared__ float t[32][33];
        const int x = tid & 31, ty = tid >> 5;
#pragma unroll
        for (int yy = ty; yy < 32; yy += 8)
            t[yy][x] = W[(size_t)(k0 + yy) * DIM + n0 + x];
        __syncthreads();
#pragma unroll
        for (int yy = ty; yy < 32; yy += 8)
            Wt[(size_t)(n0 + yy) * DIM + k0 + x] = __float2half(t[x][yy]);
    }
}

// ===========================================================================
// LayerNorm + exact GELU: fp16 in (h), fp16 out
// ===========================================================================
__global__ __launch_bounds__(256) void ln_gelu_h_kernel(
    const __half* __restrict__ h, const float* __restrict__ gamma,
    const float* __restrict__ beta, __half* __restrict__ hi) {
    const int row = blockIdx.x;
    const int t = threadIdx.x;

    uint2 raw = ((const uint2*)(h + (size_t)row * DIM))[t];
    __half2 p0 = *(__half2*)&raw.x;
    __half2 p1 = *(__half2*)&raw.y;
    float x0 = __half2float(p0.x), x1 = __half2float(p0.y);
    float x2 = __half2float(p1.x), x3 = __half2float(p1.y);

    float s1 = x0 + x1 + x2 + x3;
    float s2 = x0 * x0 + x1 * x1 + x2 * x2 + x3 * x3;
#pragma unroll
    for (int o = 16; o > 0; o >>= 1) {
        s1 += __shfl_xor_sync(0xffffffffu, s1, o);
        s2 += __shfl_xor_sync(0xffffffffu, s2, o);
    }
    __shared__ float r1[8], r2[8];
    if ((t & 31) == 0) { r1[t >> 5] = s1; r2[t >> 5] = s2; }
    __syncthreads();
    if (t < 32) {
        s1 = (t < 8) ? r1[t] : 0.f;
        s2 = (t < 8) ? r2[t] : 0.f;
#pragma unroll
        for (int o = 4; o > 0; o >>= 1) {
            s1 += __shfl_xor_sync(0xffffffffu, s1, o);
            s2 += __shfl_xor_sync(0xffffffffu, s2, o);
        }
        if (t == 0) { r1[0] = s1; r2[0] = s2; }
    }
    __syncthreads();
    const float mu = r1[0] * (1.f / DIM);
    const float var = r2[0] * (1.f / DIM) - mu * mu;
    const float rstd = rsqrtf(var + 1e-5f);

    const float4 g = *(const float4*)&gamma[t * 4];
    const float4 bb = *(const float4*)&beta[t * 4];
    float y[4] = { (x0 - mu) * rstd * g.x + bb.x,
                   (x1 - mu) * rstd * g.y + bb.y,
                   (x2 - mu) * rstd * g.z + bb.z,
                   (x3 - mu) * rstd * g.w + bb.w };
    float v[4];
#pragma unroll
    for (int i = 0; i < 4; i++)
        v[i] = 0.5f * y[i] * (1.f + erff(y[i] * 0.70710678118654752f));

    __half2 hp0, hp1;
    hp0.x = __float2half(v[0]); hp0.y = __float2half(v[1]);
    hp1.x = __float2half(v[2]); hp1.y = __float2half(v[3]);
    uint2 hv;
    hv.x = *(uint32_t*)&hp0; hv.y = *(uint32_t*)&hp1;
    ((uint2*)hi)[(size_t)row * (DIM / 4) + t] = hv;
}

// ===========================================================================
// Row L2 normalize IN PLACE on fp16 enc; also zeroes dup[row]
// ===========================================================================
__global__ __launch_bounds__(256) void l2norm_f16_inplace_kernel(
    __half* __restrict__ e, float* __restrict__ dup) {
    const int row = blockIdx.x;
    const int t = threadIdx.x;

    uint2 raw = ((uint2*)(e + (size_t)row * DIM))[t];
    __half2 p0 = *(__half2*)&raw.x;
    __half2 p1 = *(__half2*)&raw.y;
    float x0 = __half2float(p0.x), x1 = __half2float(p0.y);
    float x2 = __half2float(p1.x), x3 = __half2float(p1.y);

    float s2 = x0 * x0 + x1 * x1 + x2 * x2 + x3 * x3;
#pragma unroll
    for (int o = 16; o > 0; o >>= 1) s2 += __shfl_xor_sync(0xffffffffu, s2, o);
    __shared__ float r2[8];
    if ((t & 31) == 0) r2[t >> 5] = s2;
    __syncthreads();
    if (t < 32) {
        s2 = (t < 8) ? r2[t] : 0.f;
#pragma unroll
        for (int o = 4; o > 0; o >>= 1) s2 += __shfl_xor_sync(0xffffffffu, s2, o);
        if (t == 0) r2[0] = s2;
    }
    __syncthreads();
    const float inv = 1.f / fmaxf(sqrtf(r2[0]), 1e-12f);

    __half2 hp0, hp1;
    hp0.x = __float2half(x0 * inv); hp0.y = __float2half(x1 * inv);
    hp1.x = __float2half(x2 * inv); hp1.y = __float2half(x3 * inv);
    uint2 hv;
    hv.x = *(uint32_t*)&hp0; hv.y = *(uint32_t*)&hp1;
    ((uint2*)(e + (size_t)row * DIM))[t] = hv;
    if (dup && t == 0) dup[row] = 0.0f;
}

// ===========================================================================
extern "C" void kernel_launch(void* const* d_in, const int* in_sizes, int n_in,
                              void* d_out, int out_size) {
    const float* S     = (const float*)d_in[0];
    const float* W1    = (const float*)d_in[1];
    const float* b1    = (const float*)d_in[2];
    const float* gamma = (const float*)d_in[3];
    const float* beta  = (const float*)d_in[4];
    const float* W2    = (const float*)d_in[5];
    const float* b2    = (const float*)d_in[6];
    float* out = (float*)d_out;

    float* hbuf;
    __nv_bfloat16 *hib, *wtb;
    cudaGetSymbolAddress((void**)&hbuf, g_h);
    cudaGetSymbolAddress((void**)&hib, g_hi);
    cudaGetSymbolAddress((void**)&wtb, g_wt);
    __half* act = (__half*)hib;
    __half* wt1 = (__half*)wtb;
    __half* wt2 = wt1 + (size_t)DIM * DIM;
    __half* hh  = (__half*)hbuf;
    __half* eh  = hh + (size_t)NROWS * DIM;

    const int GEMM_SMEM = 4 * 16384;     // 64 KB
    const int SIM_SMEM = 128 * 129 * 4;  // 66048 B (>= 4*16384 pipeline)
    cudaFuncSetAttribute(gemm_enc<__half>,
                         cudaFuncAttributeMaxDynamicSharedMemorySize, GEMM_SMEM);
    cudaFuncSetAttribute(sim_tc_kernel,
                         cudaFuncAttributeMaxDynamicSharedMemorySize, SIM_SMEM);

    float* dup = nullptr;
    if (out_size >= NROWS * NROWS + NROWS) dup = out + (size_t)NROWS * NROWS;

    // 1) prep: S -> fp16; W1, W2 -> Wt fp16 (single launch)
    prep_kernel<<<8192 + 2048, 256>>>(S, W1, W2, act, wt1, wt2);
    // 2) h = S @ W1 + b1  (fp16 1-pass, fp16 output)
    gemm_enc<__half><<<dim3(DIM / 128, NROWS / 128), 128, GEMM_SMEM>>>(
        act, wt1, hh, DIM, b1);
    // 3) LayerNorm + GELU (fp16 in/out)
    ln_gelu_h_kernel<<<NROWS, 256>>>(hh, gamma, beta, act);
    // 4) enc = gelu(ln(h)) @ W2 + b2  (fp16 1-pass, fp16 output)
    gemm_enc<__half><<<dim3(DIM / 128, NROWS / 128), 128, GEMM_SMEM>>>(
        act, wt2, eh, DIM, b2);
    // 5) L2 normalize in place on fp16 enc (+ zero dup)
    l2norm_f16_inplace_kernel<<<NROWS, 256>>>(eh, dup);
    // 6) sim lower-tri fp16 1-pass; direct store + staged mirror + dup
    const int NT = NROWS / 128;
    sim_tc_kernel<<<NT * (NT + 1) / 2, 128, SIM_SMEM>>>(eh, out, dup);
}